// round 1
// baseline (speedup 1.0000x reference)
#include <cuda_runtime.h>
#include <cuda_bf16.h>
#include <cfloat>
#include <cstdint>

// Problem constants
#define Bsz 4
#define Ssz 1024
#define Dm  1024
#define NT  4096        // B*S tokens
#define NN  256         // n_neurons
#define NB  32          // n_basis
#define RK  512         // rank
#define NH  16          // heads
#define DH  32          // head dim
#define TOPK 8

// ---------------- scratch (device globals; no allocation allowed) ----------
__device__ float g_scores[NT * NN];          // 4 MB
__device__ float g_trQ[NT * NB];
__device__ float g_trK[NT * NB];
__device__ float g_trV[NT * NB];
__device__ float g_trO[NT * NB];
__device__ float g_Q[NT * RK];               // 8 MB each
__device__ float g_Km[NT * RK];
__device__ float g_V[NT * RK];
__device__ float g_ctx[NT * RK];

// ---------------- 1) router GEMM: scores = x @ W_router --------------------
// C[4096,256] = A[4096,1024] * B[1024,256]
__global__ void router_gemm(const float* __restrict__ A, const float* __restrict__ Bw,
                            float* __restrict__ C) {
    __shared__ float As[64][16];
    __shared__ float Bs[16][65];
    const int tid = threadIdx.x;
    const int tx = tid & 15, ty = tid >> 4;
    const int m0 = blockIdx.y * 64, n0 = blockIdx.x * 64;
    float acc[4][4] = {};
    for (int k0 = 0; k0 < Dm; k0 += 16) {
        #pragma unroll
        for (int p = 0; p < 4; p++) {
            int e = tid + p * 256;
            As[e >> 4][e & 15] = A[(size_t)(m0 + (e >> 4)) * Dm + k0 + (e & 15)];
        }
        #pragma unroll
        for (int p = 0; p < 4; p++) {
            int e = tid + p * 256;
            Bs[e >> 6][e & 63] = Bw[(size_t)(k0 + (e >> 6)) * NN + n0 + (e & 63)];
        }
        __syncthreads();
        #pragma unroll
        for (int kk = 0; kk < 16; kk++) {
            float a[4], b[4];
            #pragma unroll
            for (int i = 0; i < 4; i++) a[i] = As[ty * 4 + i][kk];
            #pragma unroll
            for (int j = 0; j < 4; j++) b[j] = Bs[kk][tx * 4 + j];
            #pragma unroll
            for (int i = 0; i < 4; i++)
                #pragma unroll
                for (int j = 0; j < 4; j++) acc[i][j] += a[i] * b[j];
        }
        __syncthreads();
    }
    #pragma unroll
    for (int i = 0; i < 4; i++)
        #pragma unroll
        for (int j = 0; j < 4; j++)
            C[(size_t)(m0 + ty * 4 + i) * NN + n0 + tx * 4 + j] = acc[i][j];
}

// ---------------- 2) routing: top-8 -> softmax -> recipe mix -> softmax ----
// one warp per token
__global__ void route_kernel(const float* __restrict__ scores,
                             const float* __restrict__ rQ, const float* __restrict__ rK,
                             const float* __restrict__ rV, const float* __restrict__ rO,
                             float* __restrict__ tQ, float* __restrict__ tK,
                             float* __restrict__ tV, float* __restrict__ tO) {
    const int t = blockIdx.x;
    const int lane = threadIdx.x;
    const float* s = scores + (size_t)t * NN;
    float v[8];
    #pragma unroll
    for (int i = 0; i < 8; i++) v[i] = s[i * 32 + lane];

    float top_v[TOPK];
    int   top_i[TOPK];
    for (int it = 0; it < TOPK; it++) {
        float lm = -FLT_MAX; int li = 0;
        #pragma unroll
        for (int i = 0; i < 8; i++) if (v[i] > lm) { lm = v[i]; li = i; }
        int gi = li * 32 + lane;
        #pragma unroll
        for (int off = 16; off > 0; off >>= 1) {
            float ov = __shfl_xor_sync(0xffffffffu, lm, off);
            int   oi = __shfl_xor_sync(0xffffffffu, gi, off);
            if (ov > lm || (ov == lm && oi < gi)) { lm = ov; gi = oi; }
        }
        top_v[it] = lm; top_i[it] = gi;
        if (lane == (gi & 31)) v[gi >> 5] = -FLT_MAX;
    }
    // softmax over top-8 scores (top_v[0] is max)
    float w[TOPK];
    float ssum = 0.f;
    #pragma unroll
    for (int k = 0; k < TOPK; k++) { w[k] = expf(top_v[k] - top_v[0]); ssum += w[k]; }
    float inv = 1.f / ssum;
    #pragma unroll
    for (int k = 0; k < TOPK; k++) w[k] *= inv;

    // lane == basis index n (NB == 32)
    const float* recs[4] = { rQ, rK, rV, rO };
    float* outs[4] = { tQ, tK, tV, tO };
    for (int rr = 0; rr < 4; rr++) {
        const float* R = recs[rr];
        float a = 0.f;
        #pragma unroll
        for (int k = 0; k < TOPK; k++) a += w[k] * R[top_i[k] * NB + lane];
        float mx = a;
        #pragma unroll
        for (int off = 16; off > 0; off >>= 1) mx = fmaxf(mx, __shfl_xor_sync(0xffffffffu, mx, off));
        float e = expf(a - mx);
        float sm = e;
        #pragma unroll
        for (int off = 16; off > 0; off >>= 1) sm += __shfl_xor_sync(0xffffffffu, sm, off);
        outs[rr][(size_t)t * NB + lane] = e / sm;
    }
}

// ---------------- 3) Q,K fused projection -----------------------------------
// Q/K[t,r] = sum_n tr[t,n] * (x[t,:] @ basis_qk[n])[r]
__global__ void qk_gemm(const float* __restrict__ X, const float* __restrict__ basis,
                        const float* __restrict__ trQ, const float* __restrict__ trK,
                        float* __restrict__ Qo, float* __restrict__ Ko) {
    __shared__ float As[64][16];
    __shared__ float Bs[16][65];
    __shared__ float wQ[64], wK[64];
    const int tid = threadIdx.x;
    const int tx = tid & 15, ty = tid >> 4;
    const int m0 = blockIdx.y * 64, r0 = blockIdx.x * 64;
    float accQ[4][4] = {}, accK[4][4] = {};
    for (int n = 0; n < NB; n++) {
        __syncthreads();
        if (tid < 64) {
            wQ[tid] = trQ[(size_t)(m0 + tid) * NB + n];
            wK[tid] = trK[(size_t)(m0 + tid) * NB + n];
        }
        float acc[4][4] = {};
        const float* Bn = basis + (size_t)n * Dm * RK;
        for (int k0 = 0; k0 < Dm; k0 += 16) {
            #pragma unroll
            for (int p = 0; p < 4; p++) {
                int e = tid + p * 256;
                As[e >> 4][e & 15] = X[(size_t)(m0 + (e >> 4)) * Dm + k0 + (e & 15)];
            }
            #pragma unroll
            for (int p = 0; p < 4; p++) {
                int e = tid + p * 256;
                Bs[e >> 6][e & 63] = Bn[(size_t)(k0 + (e >> 6)) * RK + r0 + (e & 63)];
            }
            __syncthreads();
            #pragma unroll
            for (int kk = 0; kk < 16; kk++) {
                float a[4], b[4];
                #pragma unroll
                for (int i = 0; i < 4; i++) a[i] = As[ty * 4 + i][kk];
                #pragma unroll
                for (int j = 0; j < 4; j++) b[j] = Bs[kk][tx * 4 + j];
                #pragma unroll
                for (int i = 0; i < 4; i++)
                    #pragma unroll
                    for (int j = 0; j < 4; j++) acc[i][j] += a[i] * b[j];
            }
            __syncthreads();
        }
        #pragma unroll
        for (int i = 0; i < 4; i++) {
            float wq = wQ[ty * 4 + i], wk = wK[ty * 4 + i];
            #pragma unroll
            for (int j = 0; j < 4; j++) {
                accQ[i][j] += wq * acc[i][j];
                accK[i][j] += wk * acc[i][j];
            }
        }
    }
    #pragma unroll
    for (int i = 0; i < 4; i++)
        #pragma unroll
        for (int j = 0; j < 4; j++) {
            size_t off = (size_t)(m0 + ty * 4 + i) * RK + r0 + tx * 4 + j;
            Qo[off] = accQ[i][j];
            Ko[off] = accK[i][j];
        }
}

// ---------------- 4) V projection (single accumulator) ----------------------
__global__ void v_gemm(const float* __restrict__ X, const float* __restrict__ basis,
                       const float* __restrict__ trV, float* __restrict__ Vo) {
    __shared__ float As[64][16];
    __shared__ float Bs[16][65];
    __shared__ float wV[64];
    const int tid = threadIdx.x;
    const int tx = tid & 15, ty = tid >> 4;
    const int m0 = blockIdx.y * 64, r0 = blockIdx.x * 64;
    float accV[4][4] = {};
    for (int n = 0; n < NB; n++) {
        __syncthreads();
        if (tid < 64) wV[tid] = trV[(size_t)(m0 + tid) * NB + n];
        float acc[4][4] = {};
        const float* Bn = basis + (size_t)n * Dm * RK;
        for (int k0 = 0; k0 < Dm; k0 += 16) {
            #pragma unroll
            for (int p = 0; p < 4; p++) {
                int e = tid + p * 256;
                As[e >> 4][e & 15] = X[(size_t)(m0 + (e >> 4)) * Dm + k0 + (e & 15)];
            }
            #pragma unroll
            for (int p = 0; p < 4; p++) {
                int e = tid + p * 256;
                Bs[e >> 6][e & 63] = Bn[(size_t)(k0 + (e >> 6)) * RK + r0 + (e & 63)];
            }
            __syncthreads();
            #pragma unroll
            for (int kk = 0; kk < 16; kk++) {
                float a[4], b[4];
                #pragma unroll
                for (int i = 0; i < 4; i++) a[i] = As[ty * 4 + i][kk];
                #pragma unroll
                for (int j = 0; j < 4; j++) b[j] = Bs[kk][tx * 4 + j];
                #pragma unroll
                for (int i = 0; i < 4; i++)
                    #pragma unroll
                    for (int j = 0; j < 4; j++) acc[i][j] += a[i] * b[j];
            }
            __syncthreads();
        }
        #pragma unroll
        for (int i = 0; i < 4; i++) {
            float wv = wV[ty * 4 + i];
            #pragma unroll
            for (int j = 0; j < 4; j++) accV[i][j] += wv * acc[i][j];
        }
    }
    #pragma unroll
    for (int i = 0; i < 4; i++)
        #pragma unroll
        for (int j = 0; j < 4; j++)
            Vo[(size_t)(m0 + ty * 4 + i) * RK + r0 + tx * 4 + j] = accV[i][j];
}

// ---------------- 5) causal attention (warp per query row) ------------------
__global__ void attn_kernel(const float* __restrict__ Q, const float* __restrict__ Km,
                            const float* __restrict__ V, float* __restrict__ ctx) {
    __shared__ float Ks[64][32];
    __shared__ float Vs[64][32];
    const int bh = blockIdx.x;
    const int b = bh >> 4, h = bh & 15;
    const int warp = threadIdx.x >> 5, lane = threadIdx.x & 31;
    const int q = blockIdx.y * 8 + warp;
    const size_t tq = (size_t)b * Ssz + q;
    const float scale = 0.17677669529663688f;  // 1/sqrt(32)
    float qd = Q[tq * RK + h * DH + lane] * scale;
    float m = -FLT_MAX, l = 0.f, acc = 0.f;
    const int qmax = blockIdx.y * 8 + 7;
    for (int k0 = 0; k0 <= qmax; k0 += 64) {
        __syncthreads();
        #pragma unroll
        for (int p = 0; p < 8; p++) {
            int e = threadIdx.x + p * 256;
            int r = e >> 5, c = e & 31;
            size_t tk = ((size_t)b * Ssz + k0 + r) * RK + h * DH + c;
            Ks[r][c] = Km[tk];
            Vs[r][c] = V[tk];
        }
        __syncthreads();
        int kend = q - k0; if (kend > 63) kend = 63;
        for (int kk = 0; kk <= kend; kk++) {
            float sv = qd * Ks[kk][lane];
            #pragma unroll
            for (int off = 16; off > 0; off >>= 1) sv += __shfl_xor_sync(0xffffffffu, sv, off);
            float mn = fmaxf(m, sv);
            float p = __expf(sv - mn);
            float cr = __expf(m - mn);
            l = l * cr + p;
            acc = acc * cr + p * Vs[kk][lane];
            m = mn;
        }
    }
    ctx[tq * RK + h * DH + lane] = acc / l;
}

// ---------------- 6) O projection: out[t,d] = sum_n trO * (ctx @ Bvo_n^T) ---
__global__ void o_gemm(const float* __restrict__ Cx, const float* __restrict__ basisvo,
                       const float* __restrict__ trO, float* __restrict__ Out) {
    __shared__ float As[64][16];   // ctx tile: 64 tok x 16 r
    __shared__ float Bs[16][65];   // Bs[kk][jj] = Bvo[n][d0+jj][k0+kk]
    __shared__ float wO[64];
    const int tid = threadIdx.x;
    const int tx = tid & 15, ty = tid >> 4;
    const int m0 = blockIdx.y * 64, d0 = blockIdx.x * 64;
    float accO[4][4] = {};
    for (int n = 0; n < NB; n++) {
        __syncthreads();
        if (tid < 64) wO[tid] = trO[(size_t)(m0 + tid) * NB + n];
        float acc[4][4] = {};
        const float* Bn = basisvo + (size_t)n * Dm * RK;
        for (int k0 = 0; k0 < RK; k0 += 16) {
            #pragma unroll
            for (int p = 0; p < 4; p++) {
                int e = tid + p * 256;
                As[e >> 4][e & 15] = Cx[(size_t)(m0 + (e >> 4)) * RK + k0 + (e & 15)];
            }
            #pragma unroll
            for (int p = 0; p < 4; p++) {
                int e = tid + p * 256;
                int jj = e >> 4, kk = e & 15;
                Bs[kk][jj] = Bn[(size_t)(d0 + jj) * RK + k0 + kk];
            }
            __syncthreads();
            #pragma unroll
            for (int kk = 0; kk < 16; kk++) {
                float a[4], b[4];
                #pragma unroll
                for (int i = 0; i < 4; i++) a[i] = As[ty * 4 + i][kk];
                #pragma unroll
                for (int j = 0; j < 4; j++) b[j] = Bs[kk][tx * 4 + j];
                #pragma unroll
                for (int i = 0; i < 4; i++)
                    #pragma unroll
                    for (int j = 0; j < 4; j++) acc[i][j] += a[i] * b[j];
            }
            __syncthreads();
        }
        #pragma unroll
        for (int i = 0; i < 4; i++) {
            float wo = wO[ty * 4 + i];
            #pragma unroll
            for (int j = 0; j < 4; j++) accO[i][j] += wo * acc[i][j];
        }
    }
    #pragma unroll
    for (int i = 0; i < 4; i++)
        #pragma unroll
        for (int j = 0; j < 4; j++)
            Out[(size_t)(m0 + ty * 4 + i) * Dm + d0 + tx * 4 + j] = accO[i][j];
}

// ---------------- launch ----------------------------------------------------
extern "C" void kernel_launch(void* const* d_in, const int* in_sizes, int n_in,
                              void* d_out, int out_size) {
    const float* x        = (const float*)d_in[0];  // [4,1024,1024]
    const float* W_router = (const float*)d_in[1];  // [1024,256]
    const float* recipe_Q = (const float*)d_in[2];  // [256,32]
    const float* recipe_K = (const float*)d_in[3];
    const float* recipe_V = (const float*)d_in[4];
    const float* recipe_O = (const float*)d_in[5];
    const float* basis_qk = (const float*)d_in[6];  // [32,1024,512]
    const float* basis_vo = (const float*)d_in[7];  // [32,1024,512]
    // d_in[8] = causal mask, applied analytically
    float* out = (float*)d_out;                     // [4,1024,1024]

    float *scores, *tQ, *tK, *tV, *tO, *Qp, *Kp, *Vp, *ctx;
    cudaGetSymbolAddress((void**)&scores, g_scores);
    cudaGetSymbolAddress((void**)&tQ, g_trQ);
    cudaGetSymbolAddress((void**)&tK, g_trK);
    cudaGetSymbolAddress((void**)&tV, g_trV);
    cudaGetSymbolAddress((void**)&tO, g_trO);
    cudaGetSymbolAddress((void**)&Qp, g_Q);
    cudaGetSymbolAddress((void**)&Kp, g_Km);
    cudaGetSymbolAddress((void**)&Vp, g_V);
    cudaGetSymbolAddress((void**)&ctx, g_ctx);

    router_gemm<<<dim3(NN / 64, NT / 64), 256>>>(x, W_router, scores);
    route_kernel<<<NT, 32>>>(scores, recipe_Q, recipe_K, recipe_V, recipe_O, tQ, tK, tV, tO);
    qk_gemm<<<dim3(RK / 64, NT / 64), 256>>>(x, basis_qk, tQ, tK, Qp, Kp);
    v_gemm<<<dim3(RK / 64, NT / 64), 256>>>(x, basis_vo, tV, Vp);
    attn_kernel<<<dim3(Bsz * NH, Ssz / 8), 256>>>(Qp, Kp, Vp, ctx);
    o_gemm<<<dim3(Dm / 64, NT / 64), 256>>>(ctx, basis_vo, tO, out);
}

// round 2
// speedup vs baseline: 2.0186x; 2.0186x over previous
#include <cuda_runtime.h>
#include <cuda_bf16.h>
#include <cfloat>
#include <cstdint>

// Problem constants
#define Bsz 4
#define Ssz 1024
#define Dm  1024
#define NT  4096        // B*S tokens
#define NN  256         // n_neurons
#define NB  32          // n_basis
#define RK  512         // rank
#define NH  16          // heads
#define DH  32          // head dim
#define TOPK 8

// MMA tiling
#define BM 128
#define BN 64
#define BK 16
#define AROW (BM + 8)   // 136: 136 mod 32 = 8 -> conflict-free frag loads
#define BROW (BN + 8)   // 72

// ---------------- scratch (device globals; no allocation allowed) ----------
__device__ float g_scores[NT * NN];
__device__ float g_trQ[NT * NB];
__device__ float g_trK[NT * NB];
__device__ float g_trV[NT * NB];
__device__ float g_trO[NT * NB];
__device__ float g_Q[NT * RK];
__device__ float g_Km[NT * RK];
__device__ float g_V[NT * RK];
__device__ float g_ctx[NT * RK];

// ---------------- tf32 helpers ---------------------------------------------
__device__ __forceinline__ unsigned f2tf32(float x) {
    unsigned r;
    asm("cvt.rna.tf32.f32 %0, %1;" : "=r"(r) : "f"(x));
    return r;
}

__device__ __forceinline__ void mma_tf32(float* c, const unsigned* a, const unsigned* b) {
    asm volatile("mma.sync.aligned.m16n8k8.row.col.f32.tf32.tf32.f32 "
        "{%0,%1,%2,%3}, {%4,%5,%6,%7}, {%8,%9}, {%0,%1,%2,%3};"
        : "+f"(c[0]), "+f"(c[1]), "+f"(c[2]), "+f"(c[3])
        : "r"(a[0]), "r"(a[1]), "r"(a[2]), "r"(a[3]), "r"(b[0]), "r"(b[1]));
}

// ---------------- 1) router GEMM (fp32 SIMT: protects top-k selection) ------
__global__ void router_gemm(const float* __restrict__ A, const float* __restrict__ Bw,
                            float* __restrict__ C) {
    __shared__ float As[64][16];
    __shared__ float Bs[16][65];
    const int tid = threadIdx.x;
    const int tx = tid & 15, ty = tid >> 4;
    const int m0 = blockIdx.y * 64, n0 = blockIdx.x * 64;
    float acc[4][4] = {};
    for (int k0 = 0; k0 < Dm; k0 += 16) {
        #pragma unroll
        for (int p = 0; p < 4; p++) {
            int e = tid + p * 256;
            As[e >> 4][e & 15] = A[(size_t)(m0 + (e >> 4)) * Dm + k0 + (e & 15)];
        }
        #pragma unroll
        for (int p = 0; p < 4; p++) {
            int e = tid + p * 256;
            Bs[e >> 6][e & 63] = Bw[(size_t)(k0 + (e >> 6)) * NN + n0 + (e & 63)];
        }
        __syncthreads();
        #pragma unroll
        for (int kk = 0; kk < 16; kk++) {
            float a[4], b[4];
            #pragma unroll
            for (int i = 0; i < 4; i++) a[i] = As[ty * 4 + i][kk];
            #pragma unroll
            for (int j = 0; j < 4; j++) b[j] = Bs[kk][tx * 4 + j];
            #pragma unroll
            for (int i = 0; i < 4; i++)
                #pragma unroll
                for (int j = 0; j < 4; j++) acc[i][j] += a[i] * b[j];
        }
        __syncthreads();
    }
    #pragma unroll
    for (int i = 0; i < 4; i++)
        #pragma unroll
        for (int j = 0; j < 4; j++)
            C[(size_t)(m0 + ty * 4 + i) * NN + n0 + tx * 4 + j] = acc[i][j];
}

// ---------------- 2) routing: top-8 -> softmax -> recipe mix -> softmax ----
__global__ void route_kernel(const float* __restrict__ scores,
                             const float* __restrict__ rQ, const float* __restrict__ rK,
                             const float* __restrict__ rV, const float* __restrict__ rO,
                             float* __restrict__ tQ, float* __restrict__ tK,
                             float* __restrict__ tV, float* __restrict__ tO) {
    const int t = blockIdx.x;
    const int lane = threadIdx.x;
    const float* s = scores + (size_t)t * NN;
    float v[8];
    #pragma unroll
    for (int i = 0; i < 8; i++) v[i] = s[i * 32 + lane];

    float top_v[TOPK];
    int   top_i[TOPK];
    for (int it = 0; it < TOPK; it++) {
        float lm = -FLT_MAX; int li = 0;
        #pragma unroll
        for (int i = 0; i < 8; i++) if (v[i] > lm) { lm = v[i]; li = i; }
        int gi = li * 32 + lane;
        #pragma unroll
        for (int off = 16; off > 0; off >>= 1) {
            float ov = __shfl_xor_sync(0xffffffffu, lm, off);
            int   oi = __shfl_xor_sync(0xffffffffu, gi, off);
            if (ov > lm || (ov == lm && oi < gi)) { lm = ov; gi = oi; }
        }
        top_v[it] = lm; top_i[it] = gi;
        if (lane == (gi & 31)) v[gi >> 5] = -FLT_MAX;
    }
    float w[TOPK];
    float ssum = 0.f;
    #pragma unroll
    for (int k = 0; k < TOPK; k++) { w[k] = expf(top_v[k] - top_v[0]); ssum += w[k]; }
    float inv = 1.f / ssum;
    #pragma unroll
    for (int k = 0; k < TOPK; k++) w[k] *= inv;

    const float* recs[4] = { rQ, rK, rV, rO };
    float* outs[4] = { tQ, tK, tV, tO };
    for (int rr = 0; rr < 4; rr++) {
        const float* R = recs[rr];
        float a = 0.f;
        #pragma unroll
        for (int k = 0; k < TOPK; k++) a += w[k] * R[top_i[k] * NB + lane];
        float mx = a;
        #pragma unroll
        for (int off = 16; off > 0; off >>= 1) mx = fmaxf(mx, __shfl_xor_sync(0xffffffffu, mx, off));
        float e = expf(a - mx);
        float sm = e;
        #pragma unroll
        for (int off = 16; off > 0; off >>= 1) sm += __shfl_xor_sync(0xffffffffu, sm, off);
        outs[rr][(size_t)t * NB + lane] = e / sm;
    }
}

// ---------------- 3) Q,K fused projection via mma.sync tf32 -----------------
// Virtual GEMM: A'[t, n*1024+d] = w[t,n]*x[t,d], B'[n*1024+d, r] = basis[n][d][r]
__global__ __launch_bounds__(256) void qk_mma(
        const float* __restrict__ X, const float* __restrict__ basis,
        const float* __restrict__ trQ, const float* __restrict__ trK,
        float* __restrict__ Qo, float* __restrict__ Ko) {
    __shared__ unsigned AsQ[BK][AROW];
    __shared__ unsigned AsK[BK][AROW];
    __shared__ unsigned Bs[BK][BROW];
    const int tid = threadIdx.x;
    const int m0 = blockIdx.y * BM, r0 = blockIdx.x * BN;
    const int w = tid >> 5, lane = tid & 31;
    const int wm = (w >> 1) * 32, wn = (w & 1) * 32;
    const int g = lane >> 2, tg = lane & 3;
    float accQ[2][4][4] = {};
    float accK[2][4][4] = {};
    const int NS = NB * (Dm / BK);   // 2048 stages

    float4 ax[2]; float wq[2], wk[2]; float4 bx;

    auto gload = [&](int s) {
        int n = s >> 6;
        int k0 = (s & 63) << 4;
        #pragma unroll
        for (int p = 0; p < 2; p++) {
            int idx = tid + p * 256;
            int m = idx >> 2, kq = (idx & 3) << 2;
            ax[p] = *(const float4*)(X + (size_t)(m0 + m) * Dm + k0 + kq);
            wq[p] = trQ[(size_t)(m0 + m) * NB + n];
            wk[p] = trK[(size_t)(m0 + m) * NB + n];
        }
        int kr = tid >> 4, c4 = (tid & 15) << 2;
        bx = *(const float4*)(basis + (size_t)n * Dm * RK + (size_t)(k0 + kr) * RK + r0 + c4);
    };
    auto sstore = [&]() {
        #pragma unroll
        for (int p = 0; p < 2; p++) {
            int idx = tid + p * 256;
            int m = idx >> 2, kq = (idx & 3) << 2;
            float v[4] = { ax[p].x, ax[p].y, ax[p].z, ax[p].w };
            #pragma unroll
            for (int i = 0; i < 4; i++) {
                AsQ[kq + i][m] = f2tf32(wq[p] * v[i]);
                AsK[kq + i][m] = f2tf32(wk[p] * v[i]);
            }
        }
        int kr = tid >> 4, c4 = (tid & 15) << 2;
        float v[4] = { bx.x, bx.y, bx.z, bx.w };
        #pragma unroll
        for (int i = 0; i < 4; i++) Bs[kr][c4 + i] = f2tf32(v[i]);
    };

    gload(0); sstore(); __syncthreads();
    for (int s = 0; s < NS; s++) {
        bool more = (s + 1 < NS);
        if (more) gload(s + 1);
        #pragma unroll
        for (int ks = 0; ks < BK; ks += 8) {
            unsigned aQ[2][4], aK[2][4], bb[4][2];
            int kk = ks + tg;
            #pragma unroll
            for (int f = 0; f < 2; f++) {
                int r = wm + f * 16 + g;
                aQ[f][0] = AsQ[kk][r];     aQ[f][1] = AsQ[kk][r + 8];
                aQ[f][2] = AsQ[kk + 4][r]; aQ[f][3] = AsQ[kk + 4][r + 8];
                aK[f][0] = AsK[kk][r];     aK[f][1] = AsK[kk][r + 8];
                aK[f][2] = AsK[kk + 4][r]; aK[f][3] = AsK[kk + 4][r + 8];
            }
            #pragma unroll
            for (int j = 0; j < 4; j++) {
                int c = wn + j * 8 + g;
                bb[j][0] = Bs[kk][c];
                bb[j][1] = Bs[kk + 4][c];
            }
            #pragma unroll
            for (int f = 0; f < 2; f++)
                #pragma unroll
                for (int j = 0; j < 4; j++) {
                    mma_tf32(accQ[f][j], aQ[f], bb[j]);
                    mma_tf32(accK[f][j], aK[f], bb[j]);
                }
        }
        __syncthreads();
        if (more) { sstore(); __syncthreads(); }
    }
    #pragma unroll
    for (int f = 0; f < 2; f++)
        #pragma unroll
        for (int j = 0; j < 4; j++) {
            int row = m0 + wm + f * 16 + g;
            int col = r0 + wn + j * 8 + tg * 2;
            *(float2*)(Qo + (size_t)row * RK + col)       = make_float2(accQ[f][j][0], accQ[f][j][1]);
            *(float2*)(Qo + (size_t)(row + 8) * RK + col) = make_float2(accQ[f][j][2], accQ[f][j][3]);
            *(float2*)(Ko + (size_t)row * RK + col)       = make_float2(accK[f][j][0], accK[f][j][1]);
            *(float2*)(Ko + (size_t)(row + 8) * RK + col) = make_float2(accK[f][j][2], accK[f][j][3]);
        }
}

// ---------------- 4) V projection via mma.sync tf32 -------------------------
__global__ __launch_bounds__(256) void v_mma(
        const float* __restrict__ X, const float* __restrict__ basis,
        const float* __restrict__ trV, float* __restrict__ Vo) {
    __shared__ unsigned As[BK][AROW];
    __shared__ unsigned Bs[BK][BROW];
    const int tid = threadIdx.x;
    const int m0 = blockIdx.y * BM, r0 = blockIdx.x * BN;
    const int w = tid >> 5, lane = tid & 31;
    const int wm = (w >> 1) * 32, wn = (w & 1) * 32;
    const int g = lane >> 2, tg = lane & 3;
    float acc[2][4][4] = {};
    const int NS = NB * (Dm / BK);

    float4 ax[2]; float wv[2]; float4 bx;

    auto gload = [&](int s) {
        int n = s >> 6;
        int k0 = (s & 63) << 4;
        #pragma unroll
        for (int p = 0; p < 2; p++) {
            int idx = tid + p * 256;
            int m = idx >> 2, kq = (idx & 3) << 2;
            ax[p] = *(const float4*)(X + (size_t)(m0 + m) * Dm + k0 + kq);
            wv[p] = trV[(size_t)(m0 + m) * NB + n];
        }
        int kr = tid >> 4, c4 = (tid & 15) << 2;
        bx = *(const float4*)(basis + (size_t)n * Dm * RK + (size_t)(k0 + kr) * RK + r0 + c4);
    };
    auto sstore = [&]() {
        #pragma unroll
        for (int p = 0; p < 2; p++) {
            int idx = tid + p * 256;
            int m = idx >> 2, kq = (idx & 3) << 2;
            float v[4] = { ax[p].x, ax[p].y, ax[p].z, ax[p].w };
            #pragma unroll
            for (int i = 0; i < 4; i++) As[kq + i][m] = f2tf32(wv[p] * v[i]);
        }
        int kr = tid >> 4, c4 = (tid & 15) << 2;
        float v[4] = { bx.x, bx.y, bx.z, bx.w };
        #pragma unroll
        for (int i = 0; i < 4; i++) Bs[kr][c4 + i] = f2tf32(v[i]);
    };

    gload(0); sstore(); __syncthreads();
    for (int s = 0; s < NS; s++) {
        bool more = (s + 1 < NS);
        if (more) gload(s + 1);
        #pragma unroll
        for (int ks = 0; ks < BK; ks += 8) {
            unsigned aa[2][4], bb[4][2];
            int kk = ks + tg;
            #pragma unroll
            for (int f = 0; f < 2; f++) {
                int r = wm + f * 16 + g;
                aa[f][0] = As[kk][r];     aa[f][1] = As[kk][r + 8];
                aa[f][2] = As[kk + 4][r]; aa[f][3] = As[kk + 4][r + 8];
            }
            #pragma unroll
            for (int j = 0; j < 4; j++) {
                int c = wn + j * 8 + g;
                bb[j][0] = Bs[kk][c];
                bb[j][1] = Bs[kk + 4][c];
            }
            #pragma unroll
            for (int f = 0; f < 2; f++)
                #pragma unroll
                for (int j = 0; j < 4; j++) mma_tf32(acc[f][j], aa[f], bb[j]);
        }
        __syncthreads();
        if (more) { sstore(); __syncthreads(); }
    }
    #pragma unroll
    for (int f = 0; f < 2; f++)
        #pragma unroll
        for (int j = 0; j < 4; j++) {
            int row = m0 + wm + f * 16 + g;
            int col = r0 + wn + j * 8 + tg * 2;
            *(float2*)(Vo + (size_t)row * RK + col)       = make_float2(acc[f][j][0], acc[f][j][1]);
            *(float2*)(Vo + (size_t)(row + 8) * RK + col) = make_float2(acc[f][j][2], acc[f][j][3]);
        }
}

// ---------------- 5) causal attention (warp per query row) ------------------
__global__ void attn_kernel(const float* __restrict__ Q, const float* __restrict__ Km,
                            const float* __restrict__ V, float* __restrict__ ctx) {
    __shared__ float Ks[64][32];
    __shared__ float Vs[64][32];
    const int bh = blockIdx.x;
    const int b = bh >> 4, h = bh & 15;
    const int warp = threadIdx.x >> 5, lane = threadIdx.x & 31;
    const int q = blockIdx.y * 8 + warp;
    const size_t tq = (size_t)b * Ssz + q;
    const float scale = 0.17677669529663688f;  // 1/sqrt(32)
    float qd = Q[tq * RK + h * DH + lane] * scale;
    float m = -FLT_MAX, l = 0.f, acc = 0.f;
    const int qmax = blockIdx.y * 8 + 7;
    for (int k0 = 0; k0 <= qmax; k0 += 64) {
        __syncthreads();
        #pragma unroll
        for (int p = 0; p < 8; p++) {
            int e = threadIdx.x + p * 256;
            int r = e >> 5, c = e & 31;
            size_t tk = ((size_t)b * Ssz + k0 + r) * RK + h * DH + c;
            Ks[r][c] = Km[tk];
            Vs[r][c] = V[tk];
        }
        __syncthreads();
        int kend = q - k0; if (kend > 63) kend = 63;
        for (int kk = 0; kk <= kend; kk++) {
            float sv = qd * Ks[kk][lane];
            #pragma unroll
            for (int off = 16; off > 0; off >>= 1) sv += __shfl_xor_sync(0xffffffffu, sv, off);
            float mn = fmaxf(m, sv);
            float p = __expf(sv - mn);
            float cr = __expf(m - mn);
            l = l * cr + p;
            acc = acc * cr + p * Vs[kk][lane];
            m = mn;
        }
    }
    ctx[tq * RK + h * DH + lane] = acc / l;
}

// ---------------- 6) O projection via mma.sync tf32 -------------------------
// out[t,d] = sum_n sum_r (trO[t,n]*ctx[t,r]) * basis_vo[n][d][r]
// Virtual GEMM K = 32*512; B'[k=(n,r)][d] = basis_vo[n][d][r] (transposed staging)
__global__ __launch_bounds__(256) void o_mma(
        const float* __restrict__ Cx, const float* __restrict__ basisvo,
        const float* __restrict__ trO, float* __restrict__ Out) {
    __shared__ unsigned As[BK][AROW];
    __shared__ unsigned Bs[BK][BROW];
    const int tid = threadIdx.x;
    const int m0 = blockIdx.y * BM, d0 = blockIdx.x * BN;
    const int w = tid >> 5, lane = tid & 31;
    const int wm = (w >> 1) * 32, wn = (w & 1) * 32;
    const int g = lane >> 2, tg = lane & 3;
    float acc[2][4][4] = {};
    const int NS = NB * (RK / BK);   // 1024 stages

    float4 ax[2]; float wo[2]; float4 bx;

    auto gload = [&](int s) {
        int n = s >> 5;
        int k0 = (s & 31) << 4;
        #pragma unroll
        for (int p = 0; p < 2; p++) {
            int idx = tid + p * 256;
            int m = idx >> 2, kq = (idx & 3) << 2;
            ax[p] = *(const float4*)(Cx + (size_t)(m0 + m) * RK + k0 + kq);
            wo[p] = trO[(size_t)(m0 + m) * NB + n];
        }
        int d = tid >> 2, k4 = (tid & 3) << 2;
        bx = *(const float4*)(basisvo + (size_t)n * Dm * RK + (size_t)(d0 + d) * RK + k0 + k4);
    };
    auto sstore = [&]() {
        #pragma unroll
        for (int p = 0; p < 2; p++) {
            int idx = tid + p * 256;
            int m = idx >> 2, kq = (idx & 3) << 2;
            float v[4] = { ax[p].x, ax[p].y, ax[p].z, ax[p].w };
            #pragma unroll
            for (int i = 0; i < 4; i++) As[kq + i][m] = f2tf32(wo[p] * v[i]);
        }
        int d = tid >> 2, k4 = (tid & 3) << 2;
        float v[4] = { bx.x, bx.y, bx.z, bx.w };
        #pragma unroll
        for (int i = 0; i < 4; i++) Bs[k4 + i][d] = f2tf32(v[i]);
    };

    gload(0); sstore(); __syncthreads();
    for (int s = 0; s < NS; s++) {
        bool more = (s + 1 < NS);
        if (more) gload(s + 1);
        #pragma unroll
        for (int ks = 0; ks < BK; ks += 8) {
            unsigned aa[2][4], bb[4][2];
            int kk = ks + tg;
            #pragma unroll
            for (int f = 0; f < 2; f++) {
                int r = wm + f * 16 + g;
                aa[f][0] = As[kk][r];     aa[f][1] = As[kk][r + 8];
                aa[f][2] = As[kk + 4][r]; aa[f][3] = As[kk + 4][r + 8];
            }
            #pragma unroll
            for (int j = 0; j < 4; j++) {
                int c = wn + j * 8 + g;
                bb[j][0] = Bs[kk][c];
                bb[j][1] = Bs[kk + 4][c];
            }
            #pragma unroll
            for (int f = 0; f < 2; f++)
                #pragma unroll
                for (int j = 0; j < 4; j++) mma_tf32(acc[f][j], aa[f], bb[j]);
        }
        __syncthreads();
        if (more) { sstore(); __syncthreads(); }
    }
    #pragma unroll
    for (int f = 0; f < 2; f++)
        #pragma unroll
        for (int j = 0; j < 4; j++) {
            int row = m0 + wm + f * 16 + g;
            int col = d0 + wn + j * 8 + tg * 2;
            *(float2*)(Out + (size_t)row * Dm + col)       = make_float2(acc[f][j][0], acc[f][j][1]);
            *(float2*)(Out + (size_t)(row + 8) * Dm + col) = make_float2(acc[f][j][2], acc[f][j][3]);
        }
}

// ---------------- launch ----------------------------------------------------
extern "C" void kernel_launch(void* const* d_in, const int* in_sizes, int n_in,
                              void* d_out, int out_size) {
    const float* x        = (const float*)d_in[0];  // [4,1024,1024]
    const float* W_router = (const float*)d_in[1];  // [1024,256]
    const float* recipe_Q = (const float*)d_in[2];  // [256,32]
    const float* recipe_K = (const float*)d_in[3];
    const float* recipe_V = (const float*)d_in[4];
    const float* recipe_O = (const float*)d_in[5];
    const float* basis_qk = (const float*)d_in[6];  // [32,1024,512]
    const float* basis_vo = (const float*)d_in[7];  // [32,1024,512]
    float* out = (float*)d_out;                     // [4,1024,1024]

    float *scores, *tQ, *tK, *tV, *tO, *Qp, *Kp, *Vp, *ctx;
    cudaGetSymbolAddress((void**)&scores, g_scores);
    cudaGetSymbolAddress((void**)&tQ, g_trQ);
    cudaGetSymbolAddress((void**)&tK, g_trK);
    cudaGetSymbolAddress((void**)&tV, g_trV);
    cudaGetSymbolAddress((void**)&tO, g_trO);
    cudaGetSymbolAddress((void**)&Qp, g_Q);
    cudaGetSymbolAddress((void**)&Kp, g_Km);
    cudaGetSymbolAddress((void**)&Vp, g_V);
    cudaGetSymbolAddress((void**)&ctx, g_ctx);

    router_gemm<<<dim3(NN / 64, NT / 64), 256>>>(x, W_router, scores);
    route_kernel<<<NT, 32>>>(scores, recipe_Q, recipe_K, recipe_V, recipe_O, tQ, tK, tV, tO);
    qk_mma<<<dim3(RK / BN, NT / BM), 256>>>(x, basis_qk, tQ, tK, Qp, Kp);
    v_mma<<<dim3(RK / BN, NT / BM), 256>>>(x, basis_vo, tV, Vp);
    attn_kernel<<<dim3(Bsz * NH, Ssz / 8), 256>>>(Qp, Kp, Vp, ctx);
    o_mma<<<dim3(Dm / BN, NT / BM), 256>>>(ctx, basis_vo, tO, out);
}

// round 3
// speedup vs baseline: 4.1199x; 2.0410x over previous
#include <cuda_runtime.h>
#include <cuda_bf16.h>
#include <cfloat>
#include <cstdint>

#define Bsz 4
#define Ssz 1024
#define Dm  1024
#define NT  4096
#define NN  256
#define NB  32
#define RK  512
#define NH  16
#define DH  32
#define TOPK 8

// GEMM tiling
#define BM 128
#define BN 64
#define BK 16
#define KP 128          // resident k-panel width
#define XROW 132        // X panel row stride (floats): conflict-free + 16B aligned
#define BROW 72         // qk/v B tile row stride
#define OROW 20         // o B tile row stride
#define NSTAGE 4

// ---------------- scratch ---------------------------------------------------
__device__ float g_scores[NT * NN];
__device__ float g_trQ[NT * NB];
__device__ float g_trK[NT * NB];
__device__ float g_trV[NT * NB];
__device__ float g_trO[NT * NB];
__device__ float g_Q[NT * RK];
__device__ float g_Km[NT * RK];
__device__ float g_V[NT * RK];
__device__ float g_ctx[NT * RK];
__device__ float g_xc[NT * Dm];           // tf32-rounded x
__device__ float g_bqk[NB * Dm * RK];     // tf32-rounded basis_qk (64MB)
__device__ float g_bvo[NB * Dm * RK];     // tf32-rounded basis_vo (64MB)

// ---------------- helpers ---------------------------------------------------
__device__ __forceinline__ unsigned f2tf32(float x) {
    unsigned r;
    asm("cvt.rna.tf32.f32 %0, %1;" : "=r"(r) : "f"(x));
    return r;
}
__device__ __forceinline__ void mma_tf32(float* c, const unsigned* a, const unsigned* b) {
    asm volatile("mma.sync.aligned.m16n8k8.row.col.f32.tf32.tf32.f32 "
        "{%0,%1,%2,%3}, {%4,%5,%6,%7}, {%8,%9}, {%0,%1,%2,%3};"
        : "+f"(c[0]), "+f"(c[1]), "+f"(c[2]), "+f"(c[3])
        : "r"(a[0]), "r"(a[1]), "r"(a[2]), "r"(a[3]), "r"(b[0]), "r"(b[1]));
}
#define CP_ASYNC16(dst, src) \
    asm volatile("cp.async.cg.shared.global [%0], [%1], 16;" :: "r"(dst), "l"(src))
#define CP_COMMIT asm volatile("cp.async.commit_group;")

__global__ void cvt_tf32_kernel(const float4* __restrict__ s, float4* __restrict__ d, int n4) {
    for (int i = blockIdx.x * blockDim.x + threadIdx.x; i < n4; i += gridDim.x * blockDim.x) {
        float4 v = s[i];
        v.x = __uint_as_float(f2tf32(v.x));
        v.y = __uint_as_float(f2tf32(v.y));
        v.z = __uint_as_float(f2tf32(v.z));
        v.w = __uint_as_float(f2tf32(v.w));
        d[i] = v;
    }
}

// ---------------- 1) router GEMM (fp32 SIMT; protects top-k) ----------------
__global__ void router_gemm(const float* __restrict__ A, const float* __restrict__ Bw,
                            float* __restrict__ C) {
    __shared__ float As[64][16];
    __shared__ float Bs[16][65];
    const int tid = threadIdx.x;
    const int tx = tid & 15, ty = tid >> 4;
    const int m0 = blockIdx.y * 64, n0 = blockIdx.x * 64;
    float acc[4][4] = {};
    for (int k0 = 0; k0 < Dm; k0 += 16) {
        #pragma unroll
        for (int p = 0; p < 4; p++) {
            int e = tid + p * 256;
            As[e >> 4][e & 15] = A[(size_t)(m0 + (e >> 4)) * Dm + k0 + (e & 15)];
        }
        #pragma unroll
        for (int p = 0; p < 4; p++) {
            int e = tid + p * 256;
            Bs[e >> 6][e & 63] = Bw[(size_t)(k0 + (e >> 6)) * NN + n0 + (e & 63)];
        }
        __syncthreads();
        #pragma unroll
        for (int kk = 0; kk < 16; kk++) {
            float a[4], b[4];
            #pragma unroll
            for (int i = 0; i < 4; i++) a[i] = As[ty * 4 + i][kk];
            #pragma unroll
            for (int j = 0; j < 4; j++) b[j] = Bs[kk][tx * 4 + j];
            #pragma unroll
            for (int i = 0; i < 4; i++)
                #pragma unroll
                for (int j = 0; j < 4; j++) acc[i][j] += a[i] * b[j];
        }
        __syncthreads();
    }
    #pragma unroll
    for (int i = 0; i < 4; i++)
        #pragma unroll
        for (int j = 0; j < 4; j++)
            C[(size_t)(m0 + ty * 4 + i) * NN + n0 + tx * 4 + j] = acc[i][j];
}

// ---------------- 2) routing ------------------------------------------------
__global__ void route_kernel(const float* __restrict__ scores,
                             const float* __restrict__ rQ, const float* __restrict__ rK,
                             const float* __restrict__ rV, const float* __restrict__ rO,
                             float* __restrict__ tQ, float* __restrict__ tK,
                             float* __restrict__ tV, float* __restrict__ tO) {
    const int t = blockIdx.x;
    const int lane = threadIdx.x;
    const float* s = scores + (size_t)t * NN;
    float v[8];
    #pragma unroll
    for (int i = 0; i < 8; i++) v[i] = s[i * 32 + lane];
    float top_v[TOPK];
    int   top_i[TOPK];
    for (int it = 0; it < TOPK; it++) {
        float lm = -FLT_MAX; int li = 0;
        #pragma unroll
        for (int i = 0; i < 8; i++) if (v[i] > lm) { lm = v[i]; li = i; }
        int gi = li * 32 + lane;
        #pragma unroll
        for (int off = 16; off > 0; off >>= 1) {
            float ov = __shfl_xor_sync(0xffffffffu, lm, off);
            int   oi = __shfl_xor_sync(0xffffffffu, gi, off);
            if (ov > lm || (ov == lm && oi < gi)) { lm = ov; gi = oi; }
        }
        top_v[it] = lm; top_i[it] = gi;
        if (lane == (gi & 31)) v[gi >> 5] = -FLT_MAX;
    }
    float w[TOPK], ssum = 0.f;
    #pragma unroll
    for (int k = 0; k < TOPK; k++) { w[k] = expf(top_v[k] - top_v[0]); ssum += w[k]; }
    float inv = 1.f / ssum;
    #pragma unroll
    for (int k = 0; k < TOPK; k++) w[k] *= inv;
    const float* recs[4] = { rQ, rK, rV, rO };
    float* outs[4] = { tQ, tK, tV, tO };
    for (int rr = 0; rr < 4; rr++) {
        const float* R = recs[rr];
        float a = 0.f;
        #pragma unroll
        for (int k = 0; k < TOPK; k++) a += w[k] * R[top_i[k] * NB + lane];
        float mx = a;
        #pragma unroll
        for (int off = 16; off > 0; off >>= 1) mx = fmaxf(mx, __shfl_xor_sync(0xffffffffu, mx, off));
        float e = expf(a - mx);
        float sm = e;
        #pragma unroll
        for (int off = 16; off > 0; off >>= 1) sm += __shfl_xor_sync(0xffffffffu, sm, off);
        outs[rr][(size_t)t * NB + lane] = e / sm;
    }
}

// ---------------- 3) QK shared projection (per-n fold, resident X panel) ----
__global__ __launch_bounds__(256) void qk_mma(
        const float* __restrict__ X, const float* __restrict__ basis,
        const float* __restrict__ trQ, const float* __restrict__ trK,
        float* __restrict__ Qo, float* __restrict__ Ko) {
    extern __shared__ float smem[];
    float* Xs = smem;                          // [128][XROW]
    float* Bt = smem + BM * XROW;              // [4][16][BROW]
    const unsigned* Xu = (const unsigned*)Xs;
    const unsigned* Bu = (const unsigned*)Bt;
    const uint32_t xsb = (uint32_t)__cvta_generic_to_shared(Xs);
    const uint32_t bsb = (uint32_t)__cvta_generic_to_shared(Bt);

    const int tid = threadIdx.x;
    const int m0 = blockIdx.y * BM, r0 = blockIdx.x * BN;
    const int w = tid >> 5, lane = tid & 31;
    const int wm = (w >> 1) * 32, wn = (w & 1) * 32;
    const int g = lane >> 2, tg = lane & 3;

    float accQ[2][4][4] = {}, accK[2][4][4] = {}, accT[2][4][4] = {};

    const int xm = tid >> 5, xk4 = (tid & 31) << 2;       // X chunk base
    const int bk = tid >> 4, br4 = (tid & 15) << 2;       // B chunk

    for (int kp = 0; kp < Dm / KP; kp++) {
        __syncthreads();   // panel reuse guard
        {   // X panel: 16 chunks/thread
            const float* Xg = X + (size_t)m0 * Dm + kp * KP;
            #pragma unroll
            for (int i = 0; i < 16; i++) {
                int m = xm + i * 8;
                CP_ASYNC16(xsb + (uint32_t)(m * XROW + xk4) * 4,
                           Xg + (size_t)m * Dm + xk4);
            }
        }
        // first B stage shares group with X
        #pragma unroll
        for (int pre = 0; pre < 3; pre++) {
            int n = pre >> 3, ks = pre & 7;
            CP_ASYNC16(bsb + (uint32_t)((pre & 3) * (16 * BROW) + bk * BROW + br4) * 4,
                       basis + ((size_t)n * Dm + kp * KP + ks * 16 + bk) * RK + r0 + br4);
            CP_COMMIT;
        }
        for (int s = 0; s < 256; s++) {
            if (s < 253) { asm volatile("cp.async.wait_group 2;"); }
            else         { asm volatile("cp.async.wait_group 0;"); }
            __syncthreads();
            // compute stage s
            const unsigned* Bp = Bu + (s & 3) * (16 * BROW);
            const int kb = (s & 7) * 16;
            #pragma unroll
            for (int seg = 0; seg < 16; seg += 8) {
                unsigned aa[2][4], bb[4][2];
                const int kk = kb + seg + tg;
                #pragma unroll
                for (int f = 0; f < 2; f++) {
                    int r = (wm + f * 16 + g) * XROW + kk;
                    aa[f][0] = Xu[r];
                    aa[f][1] = Xu[r + 8 * XROW];
                    aa[f][2] = Xu[r + 4];
                    aa[f][3] = Xu[r + 8 * XROW + 4];
                }
                #pragma unroll
                for (int j = 0; j < 4; j++) {
                    int c = wn + j * 8 + g;
                    bb[j][0] = Bp[(seg + tg) * BROW + c];
                    bb[j][1] = Bp[(seg + tg + 4) * BROW + c];
                }
                #pragma unroll
                for (int f = 0; f < 2; f++)
                    #pragma unroll
                    for (int j = 0; j < 4; j++) mma_tf32(accT[f][j], aa[f], bb[j]);
            }
            if ((s & 7) == 7) {      // fold n
                int n = s >> 3;
                #pragma unroll
                for (int f = 0; f < 2; f++) {
                    int row = m0 + wm + f * 16 + g;
                    float wq0 = __ldg(trQ + (size_t)row * NB + n);
                    float wq8 = __ldg(trQ + (size_t)(row + 8) * NB + n);
                    float wk0 = __ldg(trK + (size_t)row * NB + n);
                    float wk8 = __ldg(trK + (size_t)(row + 8) * NB + n);
                    #pragma unroll
                    for (int j = 0; j < 4; j++) {
                        accQ[f][j][0] += wq0 * accT[f][j][0];
                        accQ[f][j][1] += wq0 * accT[f][j][1];
                        accQ[f][j][2] += wq8 * accT[f][j][2];
                        accQ[f][j][3] += wq8 * accT[f][j][3];
                        accK[f][j][0] += wk0 * accT[f][j][0];
                        accK[f][j][1] += wk0 * accT[f][j][1];
                        accK[f][j][2] += wk8 * accT[f][j][2];
                        accK[f][j][3] += wk8 * accT[f][j][3];
                        accT[f][j][0] = 0.f; accT[f][j][1] = 0.f;
                        accT[f][j][2] = 0.f; accT[f][j][3] = 0.f;
                    }
                }
            }
            if (s + 3 < 256) {
                int sp = s + 3;
                int n = sp >> 3, ks = sp & 7;
                CP_ASYNC16(bsb + (uint32_t)((sp & 3) * (16 * BROW) + bk * BROW + br4) * 4,
                           basis + ((size_t)n * Dm + kp * KP + ks * 16 + bk) * RK + r0 + br4);
                CP_COMMIT;
            }
        }
    }
    #pragma unroll
    for (int f = 0; f < 2; f++)
        #pragma unroll
        for (int j = 0; j < 4; j++) {
            int row = m0 + wm + f * 16 + g;
            int col = r0 + wn + j * 8 + tg * 2;
            *(float2*)(Qo + (size_t)row * RK + col)       = make_float2(accQ[f][j][0], accQ[f][j][1]);
            *(float2*)(Qo + (size_t)(row + 8) * RK + col) = make_float2(accQ[f][j][2], accQ[f][j][3]);
            *(float2*)(Ko + (size_t)row * RK + col)       = make_float2(accK[f][j][0], accK[f][j][1]);
            *(float2*)(Ko + (size_t)(row + 8) * RK + col) = make_float2(accK[f][j][2], accK[f][j][3]);
        }
}

// ---------------- 4) V projection (same skeleton, single fold target) -------
__global__ __launch_bounds__(256) void v_mma(
        const float* __restrict__ X, const float* __restrict__ basis,
        const float* __restrict__ trV, float* __restrict__ Vo) {
    extern __shared__ float smem[];
    float* Xs = smem;
    float* Bt = smem + BM * XROW;
    const unsigned* Xu = (const unsigned*)Xs;
    const unsigned* Bu = (const unsigned*)Bt;
    const uint32_t xsb = (uint32_t)__cvta_generic_to_shared(Xs);
    const uint32_t bsb = (uint32_t)__cvta_generic_to_shared(Bt);

    const int tid = threadIdx.x;
    const int m0 = blockIdx.y * BM, r0 = blockIdx.x * BN;
    const int w = tid >> 5, lane = tid & 31;
    const int wm = (w >> 1) * 32, wn = (w & 1) * 32;
    const int g = lane >> 2, tg = lane & 3;

    float accV[2][4][4] = {}, accT[2][4][4] = {};
    const int xm = tid >> 5, xk4 = (tid & 31) << 2;
    const int bk = tid >> 4, br4 = (tid & 15) << 2;

    for (int kp = 0; kp < Dm / KP; kp++) {
        __syncthreads();
        {
            const float* Xg = X + (size_t)m0 * Dm + kp * KP;
            #pragma unroll
            for (int i = 0; i < 16; i++) {
                int m = xm + i * 8;
                CP_ASYNC16(xsb + (uint32_t)(m * XROW + xk4) * 4,
                           Xg + (size_t)m * Dm + xk4);
            }
        }
        #pragma unroll
        for (int pre = 0; pre < 3; pre++) {
            int n = pre >> 3, ks = pre & 7;
            CP_ASYNC16(bsb + (uint32_t)((pre & 3) * (16 * BROW) + bk * BROW + br4) * 4,
                       basis + ((size_t)n * Dm + kp * KP + ks * 16 + bk) * RK + r0 + br4);
            CP_COMMIT;
        }
        for (int s = 0; s < 256; s++) {
            if (s < 253) { asm volatile("cp.async.wait_group 2;"); }
            else         { asm volatile("cp.async.wait_group 0;"); }
            __syncthreads();
            const unsigned* Bp = Bu + (s & 3) * (16 * BROW);
            const int kb = (s & 7) * 16;
            #pragma unroll
            for (int seg = 0; seg < 16; seg += 8) {
                unsigned aa[2][4], bb[4][2];
                const int kk = kb + seg + tg;
                #pragma unroll
                for (int f = 0; f < 2; f++) {
                    int r = (wm + f * 16 + g) * XROW + kk;
                    aa[f][0] = Xu[r];
                    aa[f][1] = Xu[r + 8 * XROW];
                    aa[f][2] = Xu[r + 4];
                    aa[f][3] = Xu[r + 8 * XROW + 4];
                }
                #pragma unroll
                for (int j = 0; j < 4; j++) {
                    int c = wn + j * 8 + g;
                    bb[j][0] = Bp[(seg + tg) * BROW + c];
                    bb[j][1] = Bp[(seg + tg + 4) * BROW + c];
                }
                #pragma unroll
                for (int f = 0; f < 2; f++)
                    #pragma unroll
                    for (int j = 0; j < 4; j++) mma_tf32(accT[f][j], aa[f], bb[j]);
            }
            if ((s & 7) == 7) {
                int n = s >> 3;
                #pragma unroll
                for (int f = 0; f < 2; f++) {
                    int row = m0 + wm + f * 16 + g;
                    float w0 = __ldg(trV + (size_t)row * NB + n);
                    float w8 = __ldg(trV + (size_t)(row + 8) * NB + n);
                    #pragma unroll
                    for (int j = 0; j < 4; j++) {
                        accV[f][j][0] += w0 * accT[f][j][0];
                        accV[f][j][1] += w0 * accT[f][j][1];
                        accV[f][j][2] += w8 * accT[f][j][2];
                        accV[f][j][3] += w8 * accT[f][j][3];
                        accT[f][j][0] = 0.f; accT[f][j][1] = 0.f;
                        accT[f][j][2] = 0.f; accT[f][j][3] = 0.f;
                    }
                }
            }
            if (s + 3 < 256) {
                int sp = s + 3;
                int n = sp >> 3, ks = sp & 7;
                CP_ASYNC16(bsb + (uint32_t)((sp & 3) * (16 * BROW) + bk * BROW + br4) * 4,
                           basis + ((size_t)n * Dm + kp * KP + ks * 16 + bk) * RK + r0 + br4);
                CP_COMMIT;
            }
        }
    }
    #pragma unroll
    for (int f = 0; f < 2; f++)
        #pragma unroll
        for (int j = 0; j < 4; j++) {
            int row = m0 + wm + f * 16 + g;
            int col = r0 + wn + j * 8 + tg * 2;
            *(float2*)(Vo + (size_t)row * RK + col)       = make_float2(accV[f][j][0], accV[f][j][1]);
            *(float2*)(Vo + (size_t)(row + 8) * RK + col) = make_float2(accV[f][j][2], accV[f][j][3]);
        }
}

// ---------------- 5) causal attention (warp per query row) ------------------
__global__ void attn_kernel(const float* __restrict__ Q, const float* __restrict__ Km,
                            const float* __restrict__ V, float* __restrict__ ctx) {
    __shared__ float Ks[64][32];
    __shared__ float Vs[64][32];
    const int bh = blockIdx.x;
    const int b = bh >> 4, h = bh & 15;
    const int warp = threadIdx.x >> 5, lane = threadIdx.x & 31;
    const int q = blockIdx.y * 8 + warp;
    const size_t tq = (size_t)b * Ssz + q;
    const float scale = 0.17677669529663688f;
    float qd = Q[tq * RK + h * DH + lane] * scale;
    float m = -FLT_MAX, l = 0.f, acc = 0.f;
    const int qmax = blockIdx.y * 8 + 7;
    for (int k0 = 0; k0 <= qmax; k0 += 64) {
        __syncthreads();
        #pragma unroll
        for (int p = 0; p < 8; p++) {
            int e = threadIdx.x + p * 256;
            int r = e >> 5, c = e & 31;
            size_t tk = ((size_t)b * Ssz + k0 + r) * RK + h * DH + c;
            Ks[r][c] = Km[tk];
            Vs[r][c] = V[tk];
        }
        __syncthreads();
        int kend = q - k0; if (kend > 63) kend = 63;
        for (int kk = 0; kk <= kend; kk++) {
            float sv = qd * Ks[kk][lane];
            #pragma unroll
            for (int off = 16; off > 0; off >>= 1) sv += __shfl_xor_sync(0xffffffffu, sv, off);
            float mn = fmaxf(m, sv);
            float p = __expf(sv - mn);
            float cr = __expf(m - mn);
            l = l * cr + p;
            acc = acc * cr + p * Vs[kk][lane];
            m = mn;
        }
    }
    ctx[tq * RK + h * DH + lane] = __uint_as_float(f2tf32(acc / l));  // pre-rounded for O GEMM
}

// ---------------- 6) O projection (per-n fold, resident ctx panel) ----------
// out[t,d] = sum_n trO[t,n] * (ctx[t,:] @ Bvo_n^T)[d]; B'[k=r][d] = bvo[n][d][r]
__global__ __launch_bounds__(256) void o_mma(
        const float* __restrict__ Cx, const float* __restrict__ basisvo,
        const float* __restrict__ trO, float* __restrict__ Out) {
    extern __shared__ float smem[];
    float* Xs = smem;                        // ctx panel [128][XROW]
    float* Bt = smem + BM * XROW;            // [4][64][OROW]
    const unsigned* Xu = (const unsigned*)Xs;
    const unsigned* Bu = (const unsigned*)Bt;
    const uint32_t xsb = (uint32_t)__cvta_generic_to_shared(Xs);
    const uint32_t bsb = (uint32_t)__cvta_generic_to_shared(Bt);

    const int tid = threadIdx.x;
    const int m0 = blockIdx.y * BM, d0 = blockIdx.x * BN;
    const int w = tid >> 5, lane = tid & 31;
    const int wm = (w >> 1) * 32, wn = (w & 1) * 32;
    const int g = lane >> 2, tg = lane & 3;

    float accO[2][4][4] = {}, accT[2][4][4] = {};
    const int xm = tid >> 5, xk4 = (tid & 31) << 2;
    const int bd = tid >> 2, bk4 = (tid & 3) << 2;

    for (int kp = 0; kp < RK / KP; kp++) {   // 4 panels
        __syncthreads();
        {
            const float* Xg = Cx + (size_t)m0 * RK + kp * KP;
            #pragma unroll
            for (int i = 0; i < 16; i++) {
                int m = xm + i * 8;
                CP_ASYNC16(xsb + (uint32_t)(m * XROW + xk4) * 4,
                           Xg + (size_t)m * RK + xk4);
            }
        }
        #pragma unroll
        for (int pre = 0; pre < 3; pre++) {
            int n = pre >> 3, ks = pre & 7;
            CP_ASYNC16(bsb + (uint32_t)((pre & 3) * (64 * OROW) + bd * OROW + bk4) * 4,
                       basisvo + ((size_t)n * Dm + d0 + bd) * RK + kp * KP + ks * 16 + bk4);
            CP_COMMIT;
        }
        for (int s = 0; s < 256; s++) {
            if (s < 253) { asm volatile("cp.async.wait_group 2;"); }
            else         { asm volatile("cp.async.wait_group 0;"); }
            __syncthreads();
            const unsigned* Bp = Bu + (s & 3) * (64 * OROW);
            const int kb = (s & 7) * 16;
            #pragma unroll
            for (int seg = 0; seg < 16; seg += 8) {
                unsigned aa[2][4], bb[4][2];
                const int kk = kb + seg + tg;
                #pragma unroll
                for (int f = 0; f < 2; f++) {
                    int r = (wm + f * 16 + g) * XROW + kk;
                    aa[f][0] = Xu[r];
                    aa[f][1] = Xu[r + 8 * XROW];
                    aa[f][2] = Xu[r + 4];
                    aa[f][3] = Xu[r + 8 * XROW + 4];
                }
                #pragma unroll
                for (int j = 0; j < 4; j++) {
                    int c = wn + j * 8 + g;
                    bb[j][0] = Bp[c * OROW + seg + tg];
                    bb[j][1] = Bp[c * OROW + seg + tg + 4];
                }
                #pragma unroll
                for (int f = 0; f < 2; f++)
                    #pragma unroll
                    for (int j = 0; j < 4; j++) mma_tf32(accT[f][j], aa[f], bb[j]);
            }
            if ((s & 7) == 7) {
                int n = s >> 3;
                #pragma unroll
                for (int f = 0; f < 2; f++) {
                    int row = m0 + wm + f * 16 + g;
                    float w0 = __ldg(trO + (size_t)row * NB + n);
                    float w8 = __ldg(trO + (size_t)(row + 8) * NB + n);
                    #pragma unroll
                    for (int j = 0; j < 4; j++) {
                        accO[f][j][0] += w0 * accT[f][j][0];
                        accO[f][j][1] += w0 * accT[f][j][1];
                        accO[f][j][2] += w8 * accT[f][j][2];
                        accO[f][j][3] += w8 * accT[f][j][3];
                        accT[f][j][0] = 0.f; accT[f][j][1] = 0.f;
                        accT[f][j][2] = 0.f; accT[f][j][3] = 0.f;
                    }
                }
            }
            if (s + 3 < 256) {
                int sp = s + 3;
                int n = sp >> 3, ks = sp & 7;
                CP_ASYNC16(bsb + (uint32_t)((sp & 3) * (64 * OROW) + bd * OROW + bk4) * 4,
                           basisvo + ((size_t)n * Dm + d0 + bd) * RK + kp * KP + ks * 16 + bk4);
                CP_COMMIT;
            }
        }
    }
    #pragma unroll
    for (int f = 0; f < 2; f++)
        #pragma unroll
        for (int j = 0; j < 4; j++) {
            int row = m0 + wm + f * 16 + g;
            int col = d0 + wn + j * 8 + tg * 2;
            *(float2*)(Out + (size_t)row * Dm + col)       = make_float2(accO[f][j][0], accO[f][j][1]);
            *(float2*)(Out + (size_t)(row + 8) * Dm + col) = make_float2(accO[f][j][2], accO[f][j][3]);
        }
}

// ---------------- launch ----------------------------------------------------
extern "C" void kernel_launch(void* const* d_in, const int* in_sizes, int n_in,
                              void* d_out, int out_size) {
    const float* x        = (const float*)d_in[0];
    const float* W_router = (const float*)d_in[1];
    const float* recipe_Q = (const float*)d_in[2];
    const float* recipe_K = (const float*)d_in[3];
    const float* recipe_V = (const float*)d_in[4];
    const float* recipe_O = (const float*)d_in[5];
    const float* basis_qk = (const float*)d_in[6];
    const float* basis_vo = (const float*)d_in[7];
    float* out = (float*)d_out;

    float *scores, *tQ, *tK, *tV, *tO, *Qp, *Kp, *Vp, *ctx, *xc, *bqk, *bvo;
    cudaGetSymbolAddress((void**)&scores, g_scores);
    cudaGetSymbolAddress((void**)&tQ, g_trQ);
    cudaGetSymbolAddress((void**)&tK, g_trK);
    cudaGetSymbolAddress((void**)&tV, g_trV);
    cudaGetSymbolAddress((void**)&tO, g_trO);
    cudaGetSymbolAddress((void**)&Qp, g_Q);
    cudaGetSymbolAddress((void**)&Kp, g_Km);
    cudaGetSymbolAddress((void**)&Vp, g_V);
    cudaGetSymbolAddress((void**)&ctx, g_ctx);
    cudaGetSymbolAddress((void**)&xc, g_xc);
    cudaGetSymbolAddress((void**)&bqk, g_bqk);
    cudaGetSymbolAddress((void**)&bvo, g_bvo);

    const int QK_SMEM = (BM * XROW + NSTAGE * 16 * BROW) * 4;   // 86016
    const int O_SMEM  = (BM * XROW + NSTAGE * 64 * OROW) * 4;   // 88064
    cudaFuncSetAttribute(qk_mma, cudaFuncAttributeMaxDynamicSharedMemorySize, QK_SMEM);
    cudaFuncSetAttribute(v_mma,  cudaFuncAttributeMaxDynamicSharedMemorySize, QK_SMEM);
    cudaFuncSetAttribute(o_mma,  cudaFuncAttributeMaxDynamicSharedMemorySize, O_SMEM);

    // pre-round inputs to tf32 containers (rna) once per launch
    cvt_tf32_kernel<<<1024, 256>>>((const float4*)x,        (float4*)xc,  NT * Dm / 4);
    cvt_tf32_kernel<<<2048, 256>>>((const float4*)basis_qk, (float4*)bqk, NB * Dm * RK / 4);
    cvt_tf32_kernel<<<2048, 256>>>((const float4*)basis_vo, (float4*)bvo, NB * Dm * RK / 4);

    router_gemm<<<dim3(NN / 64, NT / 64), 256>>>(x, W_router, scores);
    route_kernel<<<NT, 32>>>(scores, recipe_Q, recipe_K, recipe_V, recipe_O, tQ, tK, tV, tO);
    qk_mma<<<dim3(RK / BN, NT / BM), 256, QK_SMEM>>>(xc, bqk, tQ, tK, Qp, Kp);
    v_mma<<<dim3(RK / BN, NT / BM), 256, QK_SMEM>>>(xc, bvo, tV, Vp);
    attn_kernel<<<dim3(Bsz * NH, Ssz / 8), 256>>>(Qp, Kp, Vp, ctx);
    o_mma<<<dim3(Dm / BN, NT / BM), 256, O_SMEM>>>(ctx, bvo, tO, out);
}

// round 6
// speedup vs baseline: 6.3541x; 1.5423x over previous
#include <cuda_runtime.h>
#include <cuda_fp16.h>
#include <cfloat>
#include <cstdint>

#define Bsz 4
#define Ssz 1024
#define Dm  1024
#define NT  4096
#define NN  256
#define NB  32
#define RK  512
#define NH  16
#define DH  32
#define TOPK 8

// fp16 mma tiling
#define BM 128
#define BN 64
#define KP 128            // X panel width (halfs) for qk/v; floats for O ctx panel
#define XRH 136           // X panel row stride in halfs (68 words = 4 mod 32: conflict-free)
#define BRH 40            // B/A tile row stride in halfs (20 words: conflict-free)
#define CTXW 132          // O ctx panel row stride in floats

// ---------------- scratch ---------------------------------------------------
__device__ float  g_scores[NT * NN];
__device__ float  g_trQ[NT * NB];
__device__ float  g_trK[NT * NB];
__device__ float  g_trV[NT * NB];
__device__ float  g_trO[NT * NB];
__device__ float  g_Q[NT * RK];
__device__ float  g_Km[NT * RK];
__device__ float  g_V[NT * RK];
__device__ float  g_ctx[NT * RK];
__device__ __half g_xh[NT * Dm];             // fp16 x
__device__ __half g_bqkT[NB * RK * Dm];      // fp16 basis_qk^T [n][r][d]
__device__ __half g_bvoT[NB * RK * Dm];      // fp16 basis_vo^T [n][r][d]
__device__ __half g_bvoN[NB * Dm * RK];      // fp16 basis_vo native [n][d][r]

// ---------------- helpers ---------------------------------------------------
__device__ __forceinline__ void mma_f16(float* c, const unsigned* a, const unsigned* b) {
    asm volatile("mma.sync.aligned.m16n8k16.row.col.f32.f16.f16.f32 "
        "{%0,%1,%2,%3}, {%4,%5,%6,%7}, {%8,%9}, {%0,%1,%2,%3};"
        : "+f"(c[0]), "+f"(c[1]), "+f"(c[2]), "+f"(c[3])
        : "r"(a[0]), "r"(a[1]), "r"(a[2]), "r"(a[3]), "r"(b[0]), "r"(b[1]));
}
#define CP_ASYNC16(dst, src) \
    asm volatile("cp.async.cg.shared.global [%0], [%1], 16;" :: "r"(dst), "l"(src))
#define CP_COMMIT asm volatile("cp.async.commit_group;")
#define STS128(a, r0, r1, r2, r3) \
    asm volatile("st.shared.v4.b32 [%0], {%1, %2, %3, %4};" \
                 :: "r"(a), "r"(r0), "r"(r1), "r"(r2), "r"(r3) : "memory")
__device__ __forceinline__ unsigned h2u(__half2 h) { return *reinterpret_cast<unsigned*>(&h); }

// ---------------- preprocessing ---------------------------------------------
__global__ void cvt_half_kernel(const float4* __restrict__ s, uint2* __restrict__ d, int n4) {
    for (int i = blockIdx.x * blockDim.x + threadIdx.x; i < n4; i += gridDim.x * blockDim.x) {
        float4 v = s[i];
        __half2 h0 = __floats2half2_rn(v.x, v.y);
        __half2 h1 = __floats2half2_rn(v.z, v.w);
        d[i] = make_uint2(h2u(h0), h2u(h1));
    }
}
// [n][1024 d][512 r] fp32 -> [n][512 r][1024 d] fp16
__global__ void trans_cvt_h(const float* __restrict__ in, __half* __restrict__ out) {
    __shared__ float tile[32][33];
    const int n = blockIdx.z;
    const int d0 = blockIdx.y * 32, r0 = blockIdx.x * 32;
    const float* src = in + (size_t)n * Dm * RK;
    __half* dst = out + (size_t)n * RK * Dm;
    const int tx = threadIdx.x, ty = threadIdx.y;
    #pragma unroll
    for (int i = 0; i < 4; i++)
        tile[ty + i * 8][tx] = src[(size_t)(d0 + ty + i * 8) * RK + r0 + tx];
    __syncthreads();
    #pragma unroll
    for (int i = 0; i < 4; i++)
        dst[(size_t)(r0 + ty + i * 8) * Dm + d0 + tx] = __float2half(tile[tx][ty + i * 8]);
}

// ---------------- router GEMM (fp32 SIMT; protects top-k) -------------------
__global__ void router_gemm(const float* __restrict__ A, const float* __restrict__ Bw,
                            float* __restrict__ C) {
    __shared__ float As[64][16];
    __shared__ float Bs[16][65];
    const int tid = threadIdx.x;
    const int tx = tid & 15, ty = tid >> 4;
    const int m0 = blockIdx.y * 64, n0 = blockIdx.x * 64;
    float acc[4][4] = {};
    for (int k0 = 0; k0 < Dm; k0 += 16) {
        #pragma unroll
        for (int p = 0; p < 4; p++) {
            int e = tid + p * 256;
            As[e >> 4][e & 15] = A[(size_t)(m0 + (e >> 4)) * Dm + k0 + (e & 15)];
        }
        #pragma unroll
        for (int p = 0; p < 4; p++) {
            int e = tid + p * 256;
            Bs[e >> 6][e & 63] = Bw[(size_t)(k0 + (e >> 6)) * NN + n0 + (e & 63)];
        }
        __syncthreads();
        #pragma unroll
        for (int kk = 0; kk < 16; kk++) {
            float a[4], b[4];
            #pragma unroll
            for (int i = 0; i < 4; i++) a[i] = As[ty * 4 + i][kk];
            #pragma unroll
            for (int j = 0; j < 4; j++) b[j] = Bs[kk][tx * 4 + j];
            #pragma unroll
            for (int i = 0; i < 4; i++)
                #pragma unroll
                for (int j = 0; j < 4; j++) acc[i][j] += a[i] * b[j];
        }
        __syncthreads();
    }
    #pragma unroll
    for (int i = 0; i < 4; i++)
        #pragma unroll
        for (int j = 0; j < 4; j++)
            C[(size_t)(m0 + ty * 4 + i) * NN + n0 + tx * 4 + j] = acc[i][j];
}

// ---------------- routing ----------------------------------------------------
__global__ void route_kernel(const float* __restrict__ scores,
                             const float* __restrict__ rQ, const float* __restrict__ rK,
                             const float* __restrict__ rV, const float* __restrict__ rO,
                             float* __restrict__ tQ, float* __restrict__ tK,
                             float* __restrict__ tV, float* __restrict__ tO) {
    const int t = blockIdx.x;
    const int lane = threadIdx.x;
    const float* s = scores + (size_t)t * NN;
    float v[8];
    #pragma unroll
    for (int i = 0; i < 8; i++) v[i] = s[i * 32 + lane];
    float top_v[TOPK];
    int   top_i[TOPK];
    for (int it = 0; it < TOPK; it++) {
        float lm = -FLT_MAX; int li = 0;
        #pragma unroll
        for (int i = 0; i < 8; i++) if (v[i] > lm) { lm = v[i]; li = i; }
        int gi = li * 32 + lane;
        #pragma unroll
        for (int off = 16; off > 0; off >>= 1) {
            float ov = __shfl_xor_sync(0xffffffffu, lm, off);
            int   oi = __shfl_xor_sync(0xffffffffu, gi, off);
            if (ov > lm || (ov == lm && oi < gi)) { lm = ov; gi = oi; }
        }
        top_v[it] = lm; top_i[it] = gi;
        if (lane == (gi & 31)) v[gi >> 5] = -FLT_MAX;
    }
    float w[TOPK], ssum = 0.f;
    #pragma unroll
    for (int k = 0; k < TOPK; k++) { w[k] = expf(top_v[k] - top_v[0]); ssum += w[k]; }
    float inv = 1.f / ssum;
    #pragma unroll
    for (int k = 0; k < TOPK; k++) w[k] *= inv;
    const float* recs[4] = { rQ, rK, rV, rO };
    float* outs[4] = { tQ, tK, tV, tO };
    for (int rr = 0; rr < 4; rr++) {
        const float* R = recs[rr];
        float a = 0.f;
        #pragma unroll
        for (int k = 0; k < TOPK; k++) a += w[k] * R[top_i[k] * NB + lane];
        float mx = a;
        #pragma unroll
        for (int off = 16; off > 0; off >>= 1) mx = fmaxf(mx, __shfl_xor_sync(0xffffffffu, mx, off));
        float e = expf(a - mx);
        float sm = e;
        #pragma unroll
        for (int off = 16; off > 0; off >>= 1) sm += __shfl_xor_sync(0xffffffffu, sm, off);
        outs[rr][(size_t)t * NB + lane] = e / sm;
    }
}

// ---------------- QK fused projection, fp16 mma (resident X panel) ----------
__global__ __launch_bounds__(256) void qk_mma(
        const __half* __restrict__ Xh, const __half* __restrict__ Bt,
        const float* __restrict__ trQ, const float* __restrict__ trK,
        float* __restrict__ Qo, float* __restrict__ Ko) {
    extern __shared__ __half smh[];
    __half* Xs = smh;                        // [128][XRH]
    __half* Bs = smh + BM * XRH;             // [4][64][BRH]
    const uint32_t xsb = (uint32_t)__cvta_generic_to_shared(Xs);
    const uint32_t bsb = (uint32_t)__cvta_generic_to_shared(Bs);
    const int tid = threadIdx.x;
    const int m0 = blockIdx.y * BM, r0 = blockIdx.x * BN;
    const int w = tid >> 5, lane = tid & 31;
    const int wm = (w >> 1) * 32, wn = (w & 1) * 32;
    const int g = lane >> 2, tg = lane & 3;
    float accQ[2][4][4] = {}, accK[2][4][4] = {}, accT[2][4][4] = {};

    const int br = tid >> 2, bc = tid & 3;    // B stage: 1 cp.async per thread

    for (int kp = 0; kp < Dm / KP; kp++) {
        __syncthreads();
        {   // X panel: 128 rows x 128 halfs
            const __half* Xg = Xh + (size_t)m0 * Dm + kp * KP;
            #pragma unroll
            for (int i = 0; i < 8; i++) {
                int rr = (tid >> 4) + i * 16, cc = tid & 15;
                CP_ASYNC16(xsb + (uint32_t)(rr * XRH + cc * 8) * 2,
                           Xg + (size_t)rr * Dm + cc * 8);
            }
        }
        auto stageB = [&](int s2) {
            const int j = s2 & 3, n = s2 >> 2, ks = s2 & 3;
            CP_ASYNC16(bsb + (uint32_t)((j * 64 + br) * BRH + bc * 8) * 2,
                       Bt + ((size_t)n * RK + r0 + br) * Dm + kp * KP + ks * 32 + bc * 8);
        };
        stageB(0); CP_COMMIT;   // X joins this group
        stageB(1); CP_COMMIT;
        stageB(2); CP_COMMIT;
        for (int s = 0; s < 128; s++) {
            if (s + 3 < 128) { asm volatile("cp.async.wait_group 2;"); }
            else             { asm volatile("cp.async.wait_group 0;"); }
            __syncthreads();
            const __half* Bp = Bs + (s & 3) * (64 * BRH);
            const int kb = (s & 3) * 32;
            #pragma unroll
            for (int seg = 0; seg < 32; seg += 16) {
                unsigned aa[2][4], bb[4][2];
                const int kc = kb + seg + 2 * tg;
                #pragma unroll
                for (int mf = 0; mf < 2; mf++) {
                    const __half* xr = Xs + (wm + mf * 16 + g) * XRH;
                    aa[mf][0] = *(const unsigned*)(xr + kc);
                    aa[mf][1] = *(const unsigned*)(xr + 8 * XRH + kc);
                    aa[mf][2] = *(const unsigned*)(xr + kc + 8);
                    aa[mf][3] = *(const unsigned*)(xr + 8 * XRH + kc + 8);
                }
                const int kcb = seg + 2 * tg;
                #pragma unroll
                for (int j = 0; j < 4; j++) {
                    const __half* brw = Bp + (wn + j * 8 + g) * BRH;
                    bb[j][0] = *(const unsigned*)(brw + kcb);
                    bb[j][1] = *(const unsigned*)(brw + kcb + 8);
                }
                #pragma unroll
                for (int mf = 0; mf < 2; mf++)
                    #pragma unroll
                    for (int j = 0; j < 4; j++) mma_f16(accT[mf][j], aa[mf], bb[j]);
            }
            if ((s & 3) == 3) {
                const int n = s >> 2;
                #pragma unroll
                for (int mf = 0; mf < 2; mf++) {
                    const int row = m0 + wm + mf * 16 + g;
                    float wq0 = __ldg(trQ + (size_t)row * NB + n);
                    float wq8 = __ldg(trQ + (size_t)(row + 8) * NB + n);
                    float wk0 = __ldg(trK + (size_t)row * NB + n);
                    float wk8 = __ldg(trK + (size_t)(row + 8) * NB + n);
                    #pragma unroll
                    for (int j = 0; j < 4; j++) {
                        accQ[mf][j][0] += wq0 * accT[mf][j][0];
                        accQ[mf][j][1] += wq0 * accT[mf][j][1];
                        accQ[mf][j][2] += wq8 * accT[mf][j][2];
                        accQ[mf][j][3] += wq8 * accT[mf][j][3];
                        accK[mf][j][0] += wk0 * accT[mf][j][0];
                        accK[mf][j][1] += wk0 * accT[mf][j][1];
                        accK[mf][j][2] += wk8 * accT[mf][j][2];
                        accK[mf][j][3] += wk8 * accT[mf][j][3];
                        accT[mf][j][0] = 0.f; accT[mf][j][1] = 0.f;
                        accT[mf][j][2] = 0.f; accT[mf][j][3] = 0.f;
                    }
                }
            }
            if (s + 3 < 128) { stageB(s + 3); CP_COMMIT; }
        }
    }
    #pragma unroll
    for (int mf = 0; mf < 2; mf++)
        #pragma unroll
        for (int j = 0; j < 4; j++) {
            const int row = m0 + wm + mf * 16 + g;
            const int col = r0 + wn + j * 8 + tg * 2;
            *(float2*)(Qo + (size_t)row * RK + col)       = make_float2(accQ[mf][j][0], accQ[mf][j][1]);
            *(float2*)(Qo + (size_t)(row + 8) * RK + col) = make_float2(accQ[mf][j][2], accQ[mf][j][3]);
            *(float2*)(Ko + (size_t)row * RK + col)       = make_float2(accK[mf][j][0], accK[mf][j][1]);
            *(float2*)(Ko + (size_t)(row + 8) * RK + col) = make_float2(accK[mf][j][2], accK[mf][j][3]);
        }
}

// ---------------- V projection, fp16 mma -------------------------------------
__global__ __launch_bounds__(256) void v_mma(
        const __half* __restrict__ Xh, const __half* __restrict__ Bt,
        const float* __restrict__ trV, float* __restrict__ Vo) {
    extern __shared__ __half smh[];
    __half* Xs = smh;
    __half* Bs = smh + BM * XRH;
    const uint32_t xsb = (uint32_t)__cvta_generic_to_shared(Xs);
    const uint32_t bsb = (uint32_t)__cvta_generic_to_shared(Bs);
    const int tid = threadIdx.x;
    const int m0 = blockIdx.y * BM, r0 = blockIdx.x * BN;
    const int w = tid >> 5, lane = tid & 31;
    const int wm = (w >> 1) * 32, wn = (w & 1) * 32;
    const int g = lane >> 2, tg = lane & 3;
    float accV[2][4][4] = {}, accT[2][4][4] = {};
    const int br = tid >> 2, bc = tid & 3;

    for (int kp = 0; kp < Dm / KP; kp++) {
        __syncthreads();
        {
            const __half* Xg = Xh + (size_t)m0 * Dm + kp * KP;
            #pragma unroll
            for (int i = 0; i < 8; i++) {
                int rr = (tid >> 4) + i * 16, cc = tid & 15;
                CP_ASYNC16(xsb + (uint32_t)(rr * XRH + cc * 8) * 2,
                           Xg + (size_t)rr * Dm + cc * 8);
            }
        }
        auto stageB = [&](int s2) {
            const int j = s2 & 3, n = s2 >> 2, ks = s2 & 3;
            CP_ASYNC16(bsb + (uint32_t)((j * 64 + br) * BRH + bc * 8) * 2,
                       Bt + ((size_t)n * RK + r0 + br) * Dm + kp * KP + ks * 32 + bc * 8);
        };
        stageB(0); CP_COMMIT;
        stageB(1); CP_COMMIT;
        stageB(2); CP_COMMIT;
        for (int s = 0; s < 128; s++) {
            if (s + 3 < 128) { asm volatile("cp.async.wait_group 2;"); }
            else             { asm volatile("cp.async.wait_group 0;"); }
            __syncthreads();
            const __half* Bp = Bs + (s & 3) * (64 * BRH);
            const int kb = (s & 3) * 32;
            #pragma unroll
            for (int seg = 0; seg < 32; seg += 16) {
                unsigned aa[2][4], bb[4][2];
                const int kc = kb + seg + 2 * tg;
                #pragma unroll
                for (int mf = 0; mf < 2; mf++) {
                    const __half* xr = Xs + (wm + mf * 16 + g) * XRH;
                    aa[mf][0] = *(const unsigned*)(xr + kc);
                    aa[mf][1] = *(const unsigned*)(xr + 8 * XRH + kc);
                    aa[mf][2] = *(const unsigned*)(xr + kc + 8);
                    aa[mf][3] = *(const unsigned*)(xr + 8 * XRH + kc + 8);
                }
                const int kcb = seg + 2 * tg;
                #pragma unroll
                for (int j = 0; j < 4; j++) {
                    const __half* brw = Bp + (wn + j * 8 + g) * BRH;
                    bb[j][0] = *(const unsigned*)(brw + kcb);
                    bb[j][1] = *(const unsigned*)(brw + kcb + 8);
                }
                #pragma unroll
                for (int mf = 0; mf < 2; mf++)
                    #pragma unroll
                    for (int j = 0; j < 4; j++) mma_f16(accT[mf][j], aa[mf], bb[j]);
            }
            if ((s & 3) == 3) {
                const int n = s >> 2;
                #pragma unroll
                for (int mf = 0; mf < 2; mf++) {
                    const int row = m0 + wm + mf * 16 + g;
                    float w0 = __ldg(trV + (size_t)row * NB + n);
                    float w8 = __ldg(trV + (size_t)(row + 8) * NB + n);
                    #pragma unroll
                    for (int j = 0; j < 4; j++) {
                        accV[mf][j][0] += w0 * accT[mf][j][0];
                        accV[mf][j][1] += w0 * accT[mf][j][1];
                        accV[mf][j][2] += w8 * accT[mf][j][2];
                        accV[mf][j][3] += w8 * accT[mf][j][3];
                        accT[mf][j][0] = 0.f; accT[mf][j][1] = 0.f;
                        accT[mf][j][2] = 0.f; accT[mf][j][3] = 0.f;
                    }
                }
            }
            if (s + 3 < 128) { stageB(s + 3); CP_COMMIT; }
        }
    }
    #pragma unroll
    for (int mf = 0; mf < 2; mf++)
        #pragma unroll
        for (int j = 0; j < 4; j++) {
            const int row = m0 + wm + mf * 16 + g;
            const int col = r0 + wn + j * 8 + tg * 2;
            *(float2*)(Vo + (size_t)row * RK + col)       = make_float2(accV[mf][j][0], accV[mf][j][1]);
            *(float2*)(Vo + (size_t)(row + 8) * RK + col) = make_float2(accV[mf][j][2], accV[mf][j][3]);
        }
}

// ---------------- causal attention (lane=key layout) ------------------------
__global__ void attn_kernel(const float* __restrict__ Q, const float* __restrict__ Km,
                            const float* __restrict__ V, float* __restrict__ ctx) {
    __shared__ float Ks[64][33];
    __shared__ float Vs[64][33];
    const int bh = blockIdx.x;
    const int b = bh >> 4, h = bh & 15;
    const int warp = threadIdx.x >> 5, lane = threadIdx.x & 31;
    const int q = blockIdx.y * 8 + warp;
    const size_t tq = (size_t)b * Ssz + q;
    const float scale = 0.17677669529663688f;
    const float qd = Q[tq * RK + h * DH + lane] * scale;
    float qr[32];
    #pragma unroll
    for (int d = 0; d < 32; d++) qr[d] = __shfl_sync(0xffffffffu, qd, d);
    float m = -1e30f, l = 0.f, acc = 0.f;
    const int qmax = blockIdx.y * 8 + 7;
    for (int k0 = 0; k0 <= qmax; k0 += 64) {
        __syncthreads();
        #pragma unroll
        for (int p = 0; p < 8; p++) {
            int e = threadIdx.x + p * 256;
            int r = e >> 5, c = e & 31;
            size_t tk = ((size_t)b * Ssz + k0 + r) * RK + h * DH + c;
            Ks[r][c] = Km[tk];
            Vs[r][c] = V[tk];
        }
        __syncthreads();
        #pragma unroll
        for (int j0 = 0; j0 < 64; j0 += 32) {
            if (k0 + j0 > q) break;
            const int kidx = k0 + j0 + lane;
            float sv = 0.f;
            #pragma unroll
            for (int d = 0; d < 32; d++) sv += qr[d] * Ks[j0 + lane][d];
            if (kidx > q) sv = -1e30f;
            float mx = sv;
            #pragma unroll
            for (int off = 16; off > 0; off >>= 1)
                mx = fmaxf(mx, __shfl_xor_sync(0xffffffffu, mx, off));
            const float mn = fmaxf(m, mx);
            const float p = __expf(sv - mn);
            float sum = p;
            #pragma unroll
            for (int off = 16; off > 0; off >>= 1)
                sum += __shfl_xor_sync(0xffffffffu, sum, off);
            const float cr = __expf(m - mn);
            l = l * cr + sum;
            float a2 = 0.f;
            #pragma unroll
            for (int j = 0; j < 32; j++)
                a2 += __shfl_sync(0xffffffffu, p, j) * Vs[j0 + j][lane];
            acc = acc * cr + a2;
            m = mn;
        }
    }
    ctx[tq * RK + h * DH + lane] = acc / l;
}

// ---------------- O projection, fp16 mma (resident ctx panel) ---------------
// out[t,d] = sum_{n,r} (trO[t,n]*ctx[t,r]) * bvo[n][d][r]
__global__ __launch_bounds__(256) void o_mma(
        const float* __restrict__ Cx, const __half* __restrict__ BvN,
        const float* __restrict__ trO, float* __restrict__ Out) {
    extern __shared__ __half smh[];
    float*  ctxs = (float*)smh;                              // [128][CTXW]
    __half* Ah   = (__half*)((char*)smh + BM * CTXW * 4);    // [4][128][BRH]
    __half* Bh   = Ah + 4 * BM * BRH;                        // [4][64][BRH]
    const uint32_t ctxb = (uint32_t)__cvta_generic_to_shared(ctxs);
    const uint32_t bsb  = (uint32_t)__cvta_generic_to_shared(Bh);
    const int tid = threadIdx.x;
    const int m0 = blockIdx.y * BM, d0 = blockIdx.x * BN;
    const int w = tid >> 5, lane = tid & 31;
    const int wm = (w >> 1) * 32, wn = (w & 1) * 32;
    const int g = lane >> 2, tg = lane & 3;
    float accO[2][4][4] = {};
    const int br = tid >> 2, bc = tid & 3;

    for (int kp = 0; kp < RK / KP; kp++) {   // 4 panels over r
        __syncthreads();
        {   // ctx panel fp32 [128][128]
            #pragma unroll
            for (int i = 0; i < 16; i++) {
                int idx = tid + i * 256;
                int rr = idx >> 5, cc = idx & 31;
                CP_ASYNC16(ctxb + (uint32_t)(rr * CTXW + cc * 4) * 4,
                           Cx + (size_t)(m0 + rr) * RK + kp * KP + cc * 4);
            }
            CP_COMMIT;
            asm volatile("cp.async.wait_group 0;");
            __syncthreads();
        }
        auto stageA = [&](int s2) {
            const int j = s2 & 3, n = s2 >> 2, ks = s2 & 3;
            const int row = tid >> 1, off = (tid & 1) * 16;
            const float wv = __ldg(trO + (size_t)(m0 + row) * NB + n);
            const float* cr = ctxs + row * CTXW + ks * 32 + off;
            __half* dst = Ah + (j * BM + row) * BRH + off;
            #pragma unroll
            for (int q2 = 0; q2 < 2; q2++) {
                float4 v0 = *(const float4*)(cr + q2 * 8);
                float4 v1 = *(const float4*)(cr + q2 * 8 + 4);
                __half2 h0 = __floats2half2_rn(wv * v0.x, wv * v0.y);
                __half2 h1 = __floats2half2_rn(wv * v0.z, wv * v0.w);
                __half2 h2 = __floats2half2_rn(wv * v1.x, wv * v1.y);
                __half2 h3 = __floats2half2_rn(wv * v1.z, wv * v1.w);
                uint32_t da = (uint32_t)__cvta_generic_to_shared(dst + q2 * 8);
                STS128(da, h2u(h0), h2u(h1), h2u(h2), h2u(h3));
            }
        };
        auto stageB = [&](int s2) {
            const int j = s2 & 3, n = s2 >> 2, ks = s2 & 3;
            CP_ASYNC16(bsb + (uint32_t)((j * 64 + br) * BRH + bc * 8) * 2,
                       BvN + ((size_t)n * Dm + d0 + br) * RK + kp * KP + ks * 32 + bc * 8);
        };
        stageA(0); stageB(0); CP_COMMIT;
        stageA(1); stageB(1); CP_COMMIT;
        stageA(2); stageB(2); CP_COMMIT;
        for (int s = 0; s < 128; s++) {
            if (s + 3 < 128) { asm volatile("cp.async.wait_group 2;"); }
            else             { asm volatile("cp.async.wait_group 0;"); }
            __syncthreads();
            const __half* Ap = Ah + (s & 3) * (BM * BRH);
            const __half* Bp = Bh + (s & 3) * (64 * BRH);
            #pragma unroll
            for (int seg = 0; seg < 32; seg += 16) {
                unsigned aa[2][4], bb[4][2];
                const int kc = seg + 2 * tg;
                #pragma unroll
                for (int mf = 0; mf < 2; mf++) {
                    const __half* ar = Ap + (wm + mf * 16 + g) * BRH;
                    aa[mf][0] = *(const unsigned*)(ar + kc);
                    aa[mf][1] = *(const unsigned*)(ar + 8 * BRH + kc);
                    aa[mf][2] = *(const unsigned*)(ar + kc + 8);
                    aa[mf][3] = *(const unsigned*)(ar + 8 * BRH + kc + 8);
                }
                #pragma unroll
                for (int j = 0; j < 4; j++) {
                    const __half* brw = Bp + (wn + j * 8 + g) * BRH;
                    bb[j][0] = *(const unsigned*)(brw + kc);
                    bb[j][1] = *(const unsigned*)(brw + kc + 8);
                }
                #pragma unroll
                for (int mf = 0; mf < 2; mf++)
                    #pragma unroll
                    for (int j = 0; j < 4; j++) mma_f16(accO[mf][j], aa[mf], bb[j]);
            }
            if (s + 3 < 128) { stageA(s + 3); stageB(s + 3); CP_COMMIT; }
        }
    }
    #pragma unroll
    for (int mf = 0; mf < 2; mf++)
        #pragma unroll
        for (int j = 0; j < 4; j++) {
            const int row = m0 + wm + mf * 16 + g;
            const int col = d0 + wn + j * 8 + tg * 2;
            *(float2*)(Out + (size_t)row * Dm + col)       = make_float2(accO[mf][j][0], accO[mf][j][1]);
            *(float2*)(Out + (size_t)(row + 8) * Dm + col) = make_float2(accO[mf][j][2], accO[mf][j][3]);
        }
}

// ---------------- launch ----------------------------------------------------
extern "C" void kernel_launch(void* const* d_in, const int* in_sizes, int n_in,
                              void* d_out, int out_size) {
    const float* x        = (const float*)d_in[0];
    const float* W_router = (const float*)d_in[1];
    const float* recipe_Q = (const float*)d_in[2];
    const float* recipe_K = (const float*)d_in[3];
    const float* recipe_V = (const float*)d_in[4];
    const float* recipe_O = (const float*)d_in[5];
    const float* basis_qk = (const float*)d_in[6];
    const float* basis_vo = (const float*)d_in[7];
    float* out = (float*)d_out;

    float *scores, *tQ, *tK, *tV, *tO, *Qp, *Kp, *Vp, *ctx;
    __half *xh, *bqkT, *bvoT, *bvoN;
    cudaGetSymbolAddress((void**)&scores, g_scores);
    cudaGetSymbolAddress((void**)&tQ, g_trQ);
    cudaGetSymbolAddress((void**)&tK, g_trK);
    cudaGetSymbolAddress((void**)&tV, g_trV);
    cudaGetSymbolAddress((void**)&tO, g_trO);
    cudaGetSymbolAddress((void**)&Qp, g_Q);
    cudaGetSymbolAddress((void**)&Kp, g_Km);
    cudaGetSymbolAddress((void**)&Vp, g_V);
    cudaGetSymbolAddress((void**)&ctx, g_ctx);
    cudaGetSymbolAddress((void**)&xh, g_xh);
    cudaGetSymbolAddress((void**)&bqkT, g_bqkT);
    cudaGetSymbolAddress((void**)&bvoT, g_bvoT);
    cudaGetSymbolAddress((void**)&bvoN, g_bvoN);

    const int QK_SMEM = (BM * XRH + 4 * 64 * BRH) * 2;                    // 55296
    const int O_SMEM  = BM * CTXW * 4 + (4 * BM * BRH + 4 * 64 * BRH) * 2; // 129024
    cudaFuncSetAttribute(qk_mma, cudaFuncAttributeMaxDynamicSharedMemorySize, QK_SMEM);
    cudaFuncSetAttribute(v_mma,  cudaFuncAttributeMaxDynamicSharedMemorySize, QK_SMEM);
    cudaFuncSetAttribute(o_mma,  cudaFuncAttributeMaxDynamicSharedMemorySize, O_SMEM);

    // fp16 conversions
    cvt_half_kernel<<<1024, 256>>>((const float4*)x, (uint2*)xh, NT * Dm / 4);
    trans_cvt_h<<<dim3(RK / 32, Dm / 32, NB), dim3(32, 8)>>>(basis_qk, bqkT);
    trans_cvt_h<<<dim3(RK / 32, Dm / 32, NB), dim3(32, 8)>>>(basis_vo, bvoT);
    cvt_half_kernel<<<2048, 256>>>((const float4*)basis_vo, (uint2*)bvoN, NB * Dm * RK / 4);

    router_gemm<<<dim3(NN / 64, NT / 64), 256>>>(x, W_router, scores);
    route_kernel<<<NT, 32>>>(scores, recipe_Q, recipe_K, recipe_V, recipe_O, tQ, tK, tV, tO);

    qk_mma<<<dim3(RK / BN, NT / BM), 256, QK_SMEM>>>(xh, bqkT, tQ, tK, Qp, Kp);
    v_mma<<<dim3(RK / BN, NT / BM), 256, QK_SMEM>>>(xh, bvoT, tV, Vp);
    attn_kernel<<<dim3(Bsz * NH, Ssz / 8), 256>>>(Qp, Kp, Vp, ctx);
    o_mma<<<dim3(Dm / BN, NT / BM), 256, O_SMEM>>>(ctx, bvoN, tO, out);
}

// round 7
// speedup vs baseline: 6.7411x; 1.0609x over previous
#include <cuda_runtime.h>
#include <cuda_fp16.h>
#include <cfloat>
#include <cstdint>

#define Bsz 4
#define Ssz 1024
#define Dm  1024
#define NT  4096
#define NN  256
#define NB  32
#define RK  512
#define NH  16
#define DH  32
#define TOPK 8

// fp16 mma tiling
#define BM 128
#define BN 64
#define KP 128            // X panel width (halfs) for qk/v; floats for O ctx panel
#define XRH 136           // X panel row stride in halfs (68 words = 4 mod 32: conflict-free)
#define BRH 40            // B/A tile row stride in halfs (20 words: conflict-free)
#define CTXW 132          // O ctx panel row stride in floats
#define NSTG 6            // cp.async ring depth

// ---------------- scratch ---------------------------------------------------
__device__ float  g_scores[NT * NN];
__device__ float  g_trQ[NT * NB];
__device__ float  g_trK[NT * NB];
__device__ float  g_trV[NT * NB];
__device__ float  g_trO[NT * NB];
__device__ float  g_Q[NT * RK];
__device__ float  g_Km[NT * RK];
__device__ float  g_V[NT * RK];
__device__ float  g_ctx[NT * RK];
__device__ __half g_xh[NT * Dm];             // fp16 x
__device__ __half g_bqkT[NB * RK * Dm];      // fp16 basis_qk^T [n][r][d]
__device__ __half g_bvoT[NB * RK * Dm];      // fp16 basis_vo^T [n][r][d]
__device__ __half g_bvoN[NB * Dm * RK];      // fp16 basis_vo native [n][d][r]

// ---------------- helpers ---------------------------------------------------
__device__ __forceinline__ void mma_f16(float* c, const unsigned* a, const unsigned* b) {
    asm volatile("mma.sync.aligned.m16n8k16.row.col.f32.f16.f16.f32 "
        "{%0,%1,%2,%3}, {%4,%5,%6,%7}, {%8,%9}, {%0,%1,%2,%3};"
        : "+f"(c[0]), "+f"(c[1]), "+f"(c[2]), "+f"(c[3])
        : "r"(a[0]), "r"(a[1]), "r"(a[2]), "r"(a[3]), "r"(b[0]), "r"(b[1]));
}
#define CP_ASYNC16(dst, src) \
    asm volatile("cp.async.cg.shared.global [%0], [%1], 16;" :: "r"(dst), "l"(src))
#define CP_COMMIT asm volatile("cp.async.commit_group;")
#define STS128(a, r0, r1, r2, r3) \
    asm volatile("st.shared.v4.b32 [%0], {%1, %2, %3, %4};" \
                 :: "r"(a), "r"(r0), "r"(r1), "r"(r2), "r"(r3) : "memory")
#define LDSM_X4(r0, r1, r2, r3, a) \
    asm volatile("ldmatrix.sync.aligned.m8n8.x4.shared.b16 {%0, %1, %2, %3}, [%4];" \
        : "=r"(r0), "=r"(r1), "=r"(r2), "=r"(r3) : "r"(a))
__device__ __forceinline__ unsigned h2u(__half2 h) { return *reinterpret_cast<unsigned*>(&h); }

// ---------------- preprocessing ---------------------------------------------
__global__ void cvt_half_kernel(const float4* __restrict__ s, uint2* __restrict__ d, int n4) {
    for (int i = blockIdx.x * blockDim.x + threadIdx.x; i < n4; i += gridDim.x * blockDim.x) {
        float4 v = s[i];
        __half2 h0 = __floats2half2_rn(v.x, v.y);
        __half2 h1 = __floats2half2_rn(v.z, v.w);
        d[i] = make_uint2(h2u(h0), h2u(h1));
    }
}
// [n][1024 d][512 r] fp32 -> [n][512 r][1024 d] fp16
__global__ void trans_cvt_h(const float* __restrict__ in, __half* __restrict__ out) {
    __shared__ float tile[32][33];
    const int n = blockIdx.z;
    const int d0 = blockIdx.y * 32, r0 = blockIdx.x * 32;
    const float* src = in + (size_t)n * Dm * RK;
    __half* dst = out + (size_t)n * RK * Dm;
    const int tx = threadIdx.x, ty = threadIdx.y;
    #pragma unroll
    for (int i = 0; i < 4; i++)
        tile[ty + i * 8][tx] = src[(size_t)(d0 + ty + i * 8) * RK + r0 + tx];
    __syncthreads();
    #pragma unroll
    for (int i = 0; i < 4; i++)
        dst[(size_t)(r0 + ty + i * 8) * Dm + d0 + tx] = __float2half(tile[tx][ty + i * 8]);
}

// ---------------- router GEMM (fp32 SIMT; protects top-k) -------------------
__global__ void router_gemm(const float* __restrict__ A, const float* __restrict__ Bw,
                            float* __restrict__ C) {
    __shared__ float As[64][16];
    __shared__ float Bs[16][65];
    const int tid = threadIdx.x;
    const int tx = tid & 15, ty = tid >> 4;
    const int m0 = blockIdx.y * 64, n0 = blockIdx.x * 64;
    float acc[4][4] = {};
    for (int k0 = 0; k0 < Dm; k0 += 16) {
        #pragma unroll
        for (int p = 0; p < 4; p++) {
            int e = tid + p * 256;
            As[e >> 4][e & 15] = A[(size_t)(m0 + (e >> 4)) * Dm + k0 + (e & 15)];
        }
        #pragma unroll
        for (int p = 0; p < 4; p++) {
            int e = tid + p * 256;
            Bs[e >> 6][e & 63] = Bw[(size_t)(k0 + (e >> 6)) * NN + n0 + (e & 63)];
        }
        __syncthreads();
        #pragma unroll
        for (int kk = 0; kk < 16; kk++) {
            float a[4], b[4];
            #pragma unroll
            for (int i = 0; i < 4; i++) a[i] = As[ty * 4 + i][kk];
            #pragma unroll
            for (int j = 0; j < 4; j++) b[j] = Bs[kk][tx * 4 + j];
            #pragma unroll
            for (int i = 0; i < 4; i++)
                #pragma unroll
                for (int j = 0; j < 4; j++) acc[i][j] += a[i] * b[j];
        }
        __syncthreads();
    }
    #pragma unroll
    for (int i = 0; i < 4; i++)
        #pragma unroll
        for (int j = 0; j < 4; j++)
            C[(size_t)(m0 + ty * 4 + i) * NN + n0 + tx * 4 + j] = acc[i][j];
}

// ---------------- routing ----------------------------------------------------
__global__ void route_kernel(const float* __restrict__ scores,
                             const float* __restrict__ rQ, const float* __restrict__ rK,
                             const float* __restrict__ rV, const float* __restrict__ rO,
                             float* __restrict__ tQ, float* __restrict__ tK,
                             float* __restrict__ tV, float* __restrict__ tO) {
    const int t = blockIdx.x;
    const int lane = threadIdx.x;
    const float* s = scores + (size_t)t * NN;
    float v[8];
    #pragma unroll
    for (int i = 0; i < 8; i++) v[i] = s[i * 32 + lane];
    float top_v[TOPK];
    int   top_i[TOPK];
    for (int it = 0; it < TOPK; it++) {
        float lm = -FLT_MAX; int li = 0;
        #pragma unroll
        for (int i = 0; i < 8; i++) if (v[i] > lm) { lm = v[i]; li = i; }
        int gi = li * 32 + lane;
        #pragma unroll
        for (int off = 16; off > 0; off >>= 1) {
            float ov = __shfl_xor_sync(0xffffffffu, lm, off);
            int   oi = __shfl_xor_sync(0xffffffffu, gi, off);
            if (ov > lm || (ov == lm && oi < gi)) { lm = ov; gi = oi; }
        }
        top_v[it] = lm; top_i[it] = gi;
        if (lane == (gi & 31)) v[gi >> 5] = -FLT_MAX;
    }
    float w[TOPK], ssum = 0.f;
    #pragma unroll
    for (int k = 0; k < TOPK; k++) { w[k] = expf(top_v[k] - top_v[0]); ssum += w[k]; }
    float inv = 1.f / ssum;
    #pragma unroll
    for (int k = 0; k < TOPK; k++) w[k] *= inv;
    const float* recs[4] = { rQ, rK, rV, rO };
    float* outs[4] = { tQ, tK, tV, tO };
    for (int rr = 0; rr < 4; rr++) {
        const float* R = recs[rr];
        float a = 0.f;
        #pragma unroll
        for (int k = 0; k < TOPK; k++) a += w[k] * R[top_i[k] * NB + lane];
        float mx = a;
        #pragma unroll
        for (int off = 16; off > 0; off >>= 1) mx = fmaxf(mx, __shfl_xor_sync(0xffffffffu, mx, off));
        float e = expf(a - mx);
        float sm = e;
        #pragma unroll
        for (int off = 16; off > 0; off >>= 1) sm += __shfl_xor_sync(0xffffffffu, sm, off);
        outs[rr][(size_t)t * NB + lane] = e / sm;
    }
}

// ---------------- QK fused projection, fp16 mma + ldmatrix ------------------
__global__ __launch_bounds__(256) void qk_mma(
        const __half* __restrict__ Xh, const __half* __restrict__ Bt,
        const float* __restrict__ trQ, const float* __restrict__ trK,
        float* __restrict__ Qo, float* __restrict__ Ko) {
    extern __shared__ __half smh[];
    __half* Xs = smh;                        // [128][XRH]
    __half* Bs = smh + BM * XRH;             // [NSTG][64][BRH]
    const uint32_t xsb = (uint32_t)__cvta_generic_to_shared(Xs);
    const uint32_t bsb = (uint32_t)__cvta_generic_to_shared(Bs);
    const int tid = threadIdx.x;
    const int m0 = blockIdx.y * BM, r0 = blockIdx.x * BN;
    const int w = tid >> 5, lane = tid & 31;
    const int wm = (w >> 1) * 32, wn = (w & 1) * 32;
    const int g = lane >> 2, tg = lane & 3;
    float accQ[2][4][4] = {}, accK[2][4][4] = {}, accT[2][4][4] = {};

    const int br = tid >> 2, bc = tid & 3;    // B stage: 1 cp.async per thread
    // ldmatrix lane-invariant addresses
    const uint32_t xA0 = xsb + (uint32_t)(((wm + (lane & 15)) * XRH + (lane >> 4) * 8) * 2);
    const uint32_t xA1 = xA0 + (uint32_t)(16 * XRH * 2);
    const uint32_t bInv = (uint32_t)(((wn + (lane & 7) + 8 * (lane >> 4)) * BRH
                                      + ((lane >> 3) & 1) * 8) * 2);

    for (int kp = 0; kp < Dm / KP; kp++) {
        __syncthreads();
        {   // X panel: 128 rows x 128 halfs
            const __half* Xg = Xh + (size_t)m0 * Dm + kp * KP;
            #pragma unroll
            for (int i = 0; i < 8; i++) {
                int rr = (tid >> 4) + i * 16, cc = tid & 15;
                CP_ASYNC16(xsb + (uint32_t)(rr * XRH + cc * 8) * 2,
                           Xg + (size_t)rr * Dm + cc * 8);
            }
        }
        auto stageB = [&](int s2) {
            const int j = s2 % NSTG, n = s2 >> 2, ks = s2 & 3;
            CP_ASYNC16(bsb + (uint32_t)((j * 64 + br) * BRH + bc * 8) * 2,
                       Bt + ((size_t)n * RK + r0 + br) * Dm + kp * KP + ks * 32 + bc * 8);
        };
        stageB(0); CP_COMMIT;   // X joins this group
        stageB(1); CP_COMMIT;
        stageB(2); CP_COMMIT;
        stageB(3); CP_COMMIT;
        stageB(4); CP_COMMIT;
        for (int s = 0; s < 128; s++) {
            if (s + 5 < 128) { asm volatile("cp.async.wait_group 4;"); }
            else             { asm volatile("cp.async.wait_group 0;"); }
            __syncthreads();
            const uint32_t bB = bsb + (uint32_t)((s % NSTG) * (64 * BRH) * 2);
            const int kb = (s & 3) * 32;
            #pragma unroll
            for (int seg = 0; seg < 32; seg += 16) {
                unsigned aa[2][4], bb[4][2];
                const int kc0 = kb + seg;
                LDSM_X4(aa[0][0], aa[0][1], aa[0][2], aa[0][3], xA0 + kc0 * 2);
                LDSM_X4(aa[1][0], aa[1][1], aa[1][2], aa[1][3], xA1 + kc0 * 2);
                LDSM_X4(bb[0][0], bb[0][1], bb[1][0], bb[1][1], bB + bInv + seg * 2);
                LDSM_X4(bb[2][0], bb[2][1], bb[3][0], bb[3][1],
                        bB + bInv + (uint32_t)(16 * BRH * 2) + seg * 2);
                #pragma unroll
                for (int mf = 0; mf < 2; mf++)
                    #pragma unroll
                    for (int j = 0; j < 4; j++) mma_f16(accT[mf][j], aa[mf], bb[j]);
            }
            if ((s & 3) == 3) {
                const int n = s >> 2;
                #pragma unroll
                for (int mf = 0; mf < 2; mf++) {
                    const int row = m0 + wm + mf * 16 + g;
                    float wq0 = __ldg(trQ + (size_t)row * NB + n);
                    float wq8 = __ldg(trQ + (size_t)(row + 8) * NB + n);
                    float wk0 = __ldg(trK + (size_t)row * NB + n);
                    float wk8 = __ldg(trK + (size_t)(row + 8) * NB + n);
                    #pragma unroll
                    for (int j = 0; j < 4; j++) {
                        accQ[mf][j][0] += wq0 * accT[mf][j][0];
                        accQ[mf][j][1] += wq0 * accT[mf][j][1];
                        accQ[mf][j][2] += wq8 * accT[mf][j][2];
                        accQ[mf][j][3] += wq8 * accT[mf][j][3];
                        accK[mf][j][0] += wk0 * accT[mf][j][0];
                        accK[mf][j][1] += wk0 * accT[mf][j][1];
                        accK[mf][j][2] += wk8 * accT[mf][j][2];
                        accK[mf][j][3] += wk8 * accT[mf][j][3];
                        accT[mf][j][0] = 0.f; accT[mf][j][1] = 0.f;
                        accT[mf][j][2] = 0.f; accT[mf][j][3] = 0.f;
                    }
                }
            }
            if (s + 5 < 128) { stageB(s + 5); CP_COMMIT; }
        }
    }
    #pragma unroll
    for (int mf = 0; mf < 2; mf++)
        #pragma unroll
        for (int j = 0; j < 4; j++) {
            const int row = m0 + wm + mf * 16 + g;
            const int col = r0 + wn + j * 8 + tg * 2;
            *(float2*)(Qo + (size_t)row * RK + col)       = make_float2(accQ[mf][j][0], accQ[mf][j][1]);
            *(float2*)(Qo + (size_t)(row + 8) * RK + col) = make_float2(accQ[mf][j][2], accQ[mf][j][3]);
            *(float2*)(Ko + (size_t)row * RK + col)       = make_float2(accK[mf][j][0], accK[mf][j][1]);
            *(float2*)(Ko + (size_t)(row + 8) * RK + col) = make_float2(accK[mf][j][2], accK[mf][j][3]);
        }
}

// ---------------- V projection, fp16 mma + ldmatrix --------------------------
__global__ __launch_bounds__(256) void v_mma(
        const __half* __restrict__ Xh, const __half* __restrict__ Bt,
        const float* __restrict__ trV, float* __restrict__ Vo) {
    extern __shared__ __half smh[];
    __half* Xs = smh;
    __half* Bs = smh + BM * XRH;
    const uint32_t xsb = (uint32_t)__cvta_generic_to_shared(Xs);
    const uint32_t bsb = (uint32_t)__cvta_generic_to_shared(Bs);
    const int tid = threadIdx.x;
    const int m0 = blockIdx.y * BM, r0 = blockIdx.x * BN;
    const int w = tid >> 5, lane = tid & 31;
    const int wm = (w >> 1) * 32, wn = (w & 1) * 32;
    const int g = lane >> 2, tg = lane & 3;
    float accV[2][4][4] = {}, accT[2][4][4] = {};
    const int br = tid >> 2, bc = tid & 3;
    const uint32_t xA0 = xsb + (uint32_t)(((wm + (lane & 15)) * XRH + (lane >> 4) * 8) * 2);
    const uint32_t xA1 = xA0 + (uint32_t)(16 * XRH * 2);
    const uint32_t bInv = (uint32_t)(((wn + (lane & 7) + 8 * (lane >> 4)) * BRH
                                      + ((lane >> 3) & 1) * 8) * 2);

    for (int kp = 0; kp < Dm / KP; kp++) {
        __syncthreads();
        {
            const __half* Xg = Xh + (size_t)m0 * Dm + kp * KP;
            #pragma unroll
            for (int i = 0; i < 8; i++) {
                int rr = (tid >> 4) + i * 16, cc = tid & 15;
                CP_ASYNC16(xsb + (uint32_t)(rr * XRH + cc * 8) * 2,
                           Xg + (size_t)rr * Dm + cc * 8);
            }
        }
        auto stageB = [&](int s2) {
            const int j = s2 % NSTG, n = s2 >> 2, ks = s2 & 3;
            CP_ASYNC16(bsb + (uint32_t)((j * 64 + br) * BRH + bc * 8) * 2,
                       Bt + ((size_t)n * RK + r0 + br) * Dm + kp * KP + ks * 32 + bc * 8);
        };
        stageB(0); CP_COMMIT;
        stageB(1); CP_COMMIT;
        stageB(2); CP_COMMIT;
        stageB(3); CP_COMMIT;
        stageB(4); CP_COMMIT;
        for (int s = 0; s < 128; s++) {
            if (s + 5 < 128) { asm volatile("cp.async.wait_group 4;"); }
            else             { asm volatile("cp.async.wait_group 0;"); }
            __syncthreads();
            const uint32_t bB = bsb + (uint32_t)((s % NSTG) * (64 * BRH) * 2);
            const int kb = (s & 3) * 32;
            #pragma unroll
            for (int seg = 0; seg < 32; seg += 16) {
                unsigned aa[2][4], bb[4][2];
                const int kc0 = kb + seg;
                LDSM_X4(aa[0][0], aa[0][1], aa[0][2], aa[0][3], xA0 + kc0 * 2);
                LDSM_X4(aa[1][0], aa[1][1], aa[1][2], aa[1][3], xA1 + kc0 * 2);
                LDSM_X4(bb[0][0], bb[0][1], bb[1][0], bb[1][1], bB + bInv + seg * 2);
                LDSM_X4(bb[2][0], bb[2][1], bb[3][0], bb[3][1],
                        bB + bInv + (uint32_t)(16 * BRH * 2) + seg * 2);
                #pragma unroll
                for (int mf = 0; mf < 2; mf++)
                    #pragma unroll
                    for (int j = 0; j < 4; j++) mma_f16(accT[mf][j], aa[mf], bb[j]);
            }
            if ((s & 3) == 3) {
                const int n = s >> 2;
                #pragma unroll
                for (int mf = 0; mf < 2; mf++) {
                    const int row = m0 + wm + mf * 16 + g;
                    float w0 = __ldg(trV + (size_t)row * NB + n);
                    float w8 = __ldg(trV + (size_t)(row + 8) * NB + n);
                    #pragma unroll
                    for (int j = 0; j < 4; j++) {
                        accV[mf][j][0] += w0 * accT[mf][j][0];
                        accV[mf][j][1] += w0 * accT[mf][j][1];
                        accV[mf][j][2] += w8 * accT[mf][j][2];
                        accV[mf][j][3] += w8 * accT[mf][j][3];
                        accT[mf][j][0] = 0.f; accT[mf][j][1] = 0.f;
                        accT[mf][j][2] = 0.f; accT[mf][j][3] = 0.f;
                    }
                }
            }
            if (s + 5 < 128) { stageB(s + 5); CP_COMMIT; }
        }
    }
    #pragma unroll
    for (int mf = 0; mf < 2; mf++)
        #pragma unroll
        for (int j = 0; j < 4; j++) {
            const int row = m0 + wm + mf * 16 + g;
            const int col = r0 + wn + j * 8 + tg * 2;
            *(float2*)(Vo + (size_t)row * RK + col)       = make_float2(accV[mf][j][0], accV[mf][j][1]);
            *(float2*)(Vo + (size_t)(row + 8) * RK + col) = make_float2(accV[mf][j][2], accV[mf][j][3]);
        }
}

// ---------------- causal attention (lane=key layout) ------------------------
__global__ void attn_kernel(const float* __restrict__ Q, const float* __restrict__ Km,
                            const float* __restrict__ V, float* __restrict__ ctx) {
    __shared__ float Ks[64][33];
    __shared__ float Vs[64][33];
    const int bh = blockIdx.x;
    const int b = bh >> 4, h = bh & 15;
    const int warp = threadIdx.x >> 5, lane = threadIdx.x & 31;
    const int q = blockIdx.y * 8 + warp;
    const size_t tq = (size_t)b * Ssz + q;
    const float scale = 0.17677669529663688f;
    const float qd = Q[tq * RK + h * DH + lane] * scale;
    float qr[32];
    #pragma unroll
    for (int d = 0; d < 32; d++) qr[d] = __shfl_sync(0xffffffffu, qd, d);
    float m = -1e30f, l = 0.f, acc = 0.f;
    const int qmax = blockIdx.y * 8 + 7;
    for (int k0 = 0; k0 <= qmax; k0 += 64) {
        __syncthreads();
        #pragma unroll
        for (int p = 0; p < 8; p++) {
            int e = threadIdx.x + p * 256;
            int r = e >> 5, c = e & 31;
            size_t tk = ((size_t)b * Ssz + k0 + r) * RK + h * DH + c;
            Ks[r][c] = Km[tk];
            Vs[r][c] = V[tk];
        }
        __syncthreads();
        #pragma unroll
        for (int j0 = 0; j0 < 64; j0 += 32) {
            if (k0 + j0 > q) break;
            const int kidx = k0 + j0 + lane;
            float sv = 0.f;
            #pragma unroll
            for (int d = 0; d < 32; d++) sv += qr[d] * Ks[j0 + lane][d];
            if (kidx > q) sv = -1e30f;
            float mx = sv;
            #pragma unroll
            for (int off = 16; off > 0; off >>= 1)
                mx = fmaxf(mx, __shfl_xor_sync(0xffffffffu, mx, off));
            const float mn = fmaxf(m, mx);
            const float p = __expf(sv - mn);
            float sum = p;
            #pragma unroll
            for (int off = 16; off > 0; off >>= 1)
                sum += __shfl_xor_sync(0xffffffffu, sum, off);
            const float cr = __expf(m - mn);
            l = l * cr + sum;
            float a2 = 0.f;
            #pragma unroll
            for (int j = 0; j < 32; j++)
                a2 += __shfl_sync(0xffffffffu, p, j) * Vs[j0 + j][lane];
            acc = acc * cr + a2;
            m = mn;
        }
    }
    ctx[tq * RK + h * DH + lane] = acc / l;
}

// ---------------- O projection, fp16 mma + ldmatrix (resident ctx panel) ----
// out[t,d] = sum_{n,r} (trO[t,n]*ctx[t,r]) * bvo[n][d][r]
__global__ __launch_bounds__(256) void o_mma(
        const float* __restrict__ Cx, const __half* __restrict__ BvN,
        const float* __restrict__ trO, float* __restrict__ Out) {
    extern __shared__ __half smh[];
    float*  ctxs = (float*)smh;                              // [128][CTXW]
    __half* Ah   = (__half*)((char*)smh + BM * CTXW * 4);    // [NSTG][128][BRH]
    __half* Bh   = Ah + NSTG * BM * BRH;                     // [NSTG][64][BRH]
    const uint32_t ctxb = (uint32_t)__cvta_generic_to_shared(ctxs);
    const uint32_t asb  = (uint32_t)__cvta_generic_to_shared(Ah);
    const uint32_t bsb  = (uint32_t)__cvta_generic_to_shared(Bh);
    const int tid = threadIdx.x;
    const int m0 = blockIdx.y * BM, d0 = blockIdx.x * BN;
    const int w = tid >> 5, lane = tid & 31;
    const int wm = (w >> 1) * 32, wn = (w & 1) * 32;
    const int g = lane >> 2, tg = lane & 3;
    float accO[2][4][4] = {};
    const int br = tid >> 2, bc = tid & 3;
    const uint32_t aInv = (uint32_t)(((wm + (lane & 15)) * BRH + (lane >> 4) * 8) * 2);
    const uint32_t bInv = (uint32_t)(((wn + (lane & 7) + 8 * (lane >> 4)) * BRH
                                      + ((lane >> 3) & 1) * 8) * 2);

    for (int kp = 0; kp < RK / KP; kp++) {   // 4 panels over r
        __syncthreads();
        {   // ctx panel fp32 [128][128]
            #pragma unroll
            for (int i = 0; i < 16; i++) {
                int idx = tid + i * 256;
                int rr = idx >> 5, cc = idx & 31;
                CP_ASYNC16(ctxb + (uint32_t)(rr * CTXW + cc * 4) * 4,
                           Cx + (size_t)(m0 + rr) * RK + kp * KP + cc * 4);
            }
            CP_COMMIT;
            asm volatile("cp.async.wait_group 0;");
            __syncthreads();
        }
        auto stageA = [&](int s2) {
            const int j = s2 % NSTG, n = s2 >> 2, ks = s2 & 3;
            const int row = tid >> 1, off = (tid & 1) * 16;
            const float wv = __ldg(trO + (size_t)(m0 + row) * NB + n);
            const float* cr = ctxs + row * CTXW + ks * 32 + off;
            __half* dst = Ah + (j * BM + row) * BRH + off;
            #pragma unroll
            for (int q2 = 0; q2 < 2; q2++) {
                float4 v0 = *(const float4*)(cr + q2 * 8);
                float4 v1 = *(const float4*)(cr + q2 * 8 + 4);
                __half2 h0 = __floats2half2_rn(wv * v0.x, wv * v0.y);
                __half2 h1 = __floats2half2_rn(wv * v0.z, wv * v0.w);
                __half2 h2 = __floats2half2_rn(wv * v1.x, wv * v1.y);
                __half2 h3 = __floats2half2_rn(wv * v1.z, wv * v1.w);
                uint32_t da = (uint32_t)__cvta_generic_to_shared(dst + q2 * 8);
                STS128(da, h2u(h0), h2u(h1), h2u(h2), h2u(h3));
            }
        };
        auto stageB = [&](int s2) {
            const int j = s2 % NSTG, n = s2 >> 2, ks = s2 & 3;
            CP_ASYNC16(bsb + (uint32_t)((j * 64 + br) * BRH + bc * 8) * 2,
                       BvN + ((size_t)n * Dm + d0 + br) * RK + kp * KP + ks * 32 + bc * 8);
        };
        stageA(0); stageB(0); CP_COMMIT;
        stageA(1); stageB(1); CP_COMMIT;
        stageA(2); stageB(2); CP_COMMIT;
        stageA(3); stageB(3); CP_COMMIT;
        stageA(4); stageB(4); CP_COMMIT;
        for (int s = 0; s < 128; s++) {
            if (s + 5 < 128) { asm volatile("cp.async.wait_group 4;"); }
            else             { asm volatile("cp.async.wait_group 0;"); }
            __syncthreads();
            const uint32_t aB = asb + (uint32_t)((s % NSTG) * (BM * BRH) * 2);
            const uint32_t bB = bsb + (uint32_t)((s % NSTG) * (64 * BRH) * 2);
            #pragma unroll
            for (int seg = 0; seg < 32; seg += 16) {
                unsigned aa[2][4], bb[4][2];
                LDSM_X4(aa[0][0], aa[0][1], aa[0][2], aa[0][3], aB + aInv + seg * 2);
                LDSM_X4(aa[1][0], aa[1][1], aa[1][2], aa[1][3],
                        aB + aInv + (uint32_t)(16 * BRH * 2) + seg * 2);
                LDSM_X4(bb[0][0], bb[0][1], bb[1][0], bb[1][1], bB + bInv + seg * 2);
                LDSM_X4(bb[2][0], bb[2][1], bb[3][0], bb[3][1],
                        bB + bInv + (uint32_t)(16 * BRH * 2) + seg * 2);
                #pragma unroll
                for (int mf = 0; mf < 2; mf++)
                    #pragma unroll
                    for (int j = 0; j < 4; j++) mma_f16(accO[mf][j], aa[mf], bb[j]);
            }
            if (s + 5 < 128) { stageA(s + 5); stageB(s + 5); CP_COMMIT; }
        }
    }
    #pragma unroll
    for (int mf = 0; mf < 2; mf++)
        #pragma unroll
        for (int j = 0; j < 4; j++) {
            const int row = m0 + wm + mf * 16 + g;
            const int col = d0 + wn + j * 8 + tg * 2;
            *(float2*)(Out + (size_t)row * Dm + col)       = make_float2(accO[mf][j][0], accO[mf][j][1]);
            *(float2*)(Out + (size_t)(row + 8) * Dm + col) = make_float2(accO[mf][j][2], accO[mf][j][3]);
        }
}

// ---------------- launch ----------------------------------------------------
extern "C" void kernel_launch(void* const* d_in, const int* in_sizes, int n_in,
                              void* d_out, int out_size) {
    const float* x        = (const float*)d_in[0];
    const float* W_router = (const float*)d_in[1];
    const float* recipe_Q = (const float*)d_in[2];
    const float* recipe_K = (const float*)d_in[3];
    const float* recipe_V = (const float*)d_in[4];
    const float* recipe_O = (const float*)d_in[5];
    const float* basis_qk = (const float*)d_in[6];
    const float* basis_vo = (const float*)d_in[7];
    float* out = (float*)d_out;

    float *scores, *tQ, *tK, *tV, *tO, *Qp, *Kp, *Vp, *ctx;
    __half *xh, *bqkT, *bvoT, *bvoN;
    cudaGetSymbolAddress((void**)&scores, g_scores);
    cudaGetSymbolAddress((void**)&tQ, g_trQ);
    cudaGetSymbolAddress((void**)&tK, g_trK);
    cudaGetSymbolAddress((void**)&tV, g_trV);
    cudaGetSymbolAddress((void**)&tO, g_trO);
    cudaGetSymbolAddress((void**)&Qp, g_Q);
    cudaGetSymbolAddress((void**)&Kp, g_Km);
    cudaGetSymbolAddress((void**)&Vp, g_V);
    cudaGetSymbolAddress((void**)&ctx, g_ctx);
    cudaGetSymbolAddress((void**)&xh, g_xh);
    cudaGetSymbolAddress((void**)&bqkT, g_bqkT);
    cudaGetSymbolAddress((void**)&bvoT, g_bvoT);
    cudaGetSymbolAddress((void**)&bvoN, g_bvoN);

    const int QK_SMEM = (BM * XRH + NSTG * 64 * BRH) * 2;                        // 65536
    const int O_SMEM  = BM * CTXW * 4 + (NSTG * BM * BRH + NSTG * 64 * BRH) * 2; // 159744
    cudaFuncSetAttribute(qk_mma, cudaFuncAttributeMaxDynamicSharedMemorySize, QK_SMEM);
    cudaFuncSetAttribute(v_mma,  cudaFuncAttributeMaxDynamicSharedMemorySize, QK_SMEM);
    cudaFuncSetAttribute(o_mma,  cudaFuncAttributeMaxDynamicSharedMemorySize, O_SMEM);

    // fp16 conversions
    cvt_half_kernel<<<1024, 256>>>((const float4*)x, (uint2*)xh, NT * Dm / 4);
    trans_cvt_h<<<dim3(RK / 32, Dm / 32, NB), dim3(32, 8)>>>(basis_qk, bqkT);
    trans_cvt_h<<<dim3(RK / 32, Dm / 32, NB), dim3(32, 8)>>>(basis_vo, bvoT);
    cvt_half_kernel<<<2048, 256>>>((const float4*)basis_vo, (uint2*)bvoN, NB * Dm * RK / 4);

    router_gemm<<<dim3(NN / 64, NT / 64), 256>>>(x, W_router, scores);
    route_kernel<<<NT, 32>>>(scores, recipe_Q, recipe_K, recipe_V, recipe_O, tQ, tK, tV, tO);

    qk_mma<<<dim3(RK / BN, NT / BM), 256, QK_SMEM>>>(xh, bqkT, tQ, tK, Qp, Kp);
    v_mma<<<dim3(RK / BN, NT / BM), 256, QK_SMEM>>>(xh, bvoT, tV, Vp);
    attn_kernel<<<dim3(Bsz * NH, Ssz / 8), 256>>>(Qp, Kp, Vp, ctx);
    o_mma<<<dim3(Dm / BN, NT / BM), 256, O_SMEM>>>(ctx, bvoN, tO, out);
}

// round 10
// speedup vs baseline: 7.2853x; 1.0807x over previous
#include <cuda_runtime.h>
#include <cuda_fp16.h>
#include <cfloat>
#include <cstdint>

#define Bsz 4
#define Ssz 1024
#define Dm  1024
#define NT  4096
#define NN  256
#define NB  32
#define RK  512
#define NH  16
#define DH  32
#define TOPK 8

// fp16 mma tiling
#define BM 128
#define BN 64
#define KP 128            // X panel width (halfs) for qk/v; floats for O ctx panel
#define XRH 136           // X panel row stride in halfs (68 words = 4 mod 32: conflict-free)
#define BRH 40            // B/A tile row stride in halfs (20 words: conflict-free)
#define CTXW 132          // O ctx panel row stride in floats
#define NSTG 6            // cp.async ring depth
#define WROW 33           // SMEM weight-tile row stride (floats)

// ---------------- scratch ---------------------------------------------------
__device__ float  g_scores[NT * NN];
__device__ float  g_trQ[NT * NB];
__device__ float  g_trK[NT * NB];
__device__ float  g_trV[NT * NB];
__device__ float  g_trO[NT * NB];
__device__ float  g_Q[NT * RK];
__device__ float  g_Km[NT * RK];
__device__ float  g_V[NT * RK];
__device__ float  g_ctx[NT * RK];
__device__ __half g_xh[NT * Dm];             // fp16 x
__device__ __half g_bqkT[NB * RK * Dm];      // fp16 basis_qk^T [n][r][d]
__device__ __half g_bvoT[NB * RK * Dm];      // fp16 basis_vo^T [n][r][d]
__device__ __half g_bvoN[NB * Dm * RK];      // fp16 basis_vo native [n][d][r]

// ---------------- helpers ---------------------------------------------------
__device__ __forceinline__ void mma_f16(float* c, const unsigned* a, const unsigned* b) {
    asm volatile("mma.sync.aligned.m16n8k16.row.col.f32.f16.f16.f32 "
        "{%0,%1,%2,%3}, {%4,%5,%6,%7}, {%8,%9}, {%0,%1,%2,%3};"
        : "+f"(c[0]), "+f"(c[1]), "+f"(c[2]), "+f"(c[3])
        : "r"(a[0]), "r"(a[1]), "r"(a[2]), "r"(a[3]), "r"(b[0]), "r"(b[1]));
}
#define CP_ASYNC16(dst, src) \
    asm volatile("cp.async.cg.shared.global [%0], [%1], 16;" :: "r"(dst), "l"(src))
#define CP_COMMIT asm volatile("cp.async.commit_group;")
#define STS128(a, r0, r1, r2, r3) \
    asm volatile("st.shared.v4.b32 [%0], {%1, %2, %3, %4};" \
                 :: "r"(a), "r"(r0), "r"(r1), "r"(r2), "r"(r3) : "memory")
#define LDSM_X4(r0, r1, r2, r3, a) \
    asm volatile("ldmatrix.sync.aligned.m8n8.x4.shared.b16 {%0, %1, %2, %3}, [%4];" \
        : "=r"(r0), "=r"(r1), "=r"(r2), "=r"(r3) : "r"(a))
__device__ __forceinline__ unsigned h2u(__half2 h) { return *reinterpret_cast<unsigned*>(&h); }

// ---------------- preprocessing ---------------------------------------------
__global__ void cvt_half_kernel(const float4* __restrict__ s, uint2* __restrict__ d, int n4) {
    for (int i = blockIdx.x * blockDim.x + threadIdx.x; i < n4; i += gridDim.x * blockDim.x) {
        float4 v = s[i];
        __half2 h0 = __floats2half2_rn(v.x, v.y);
        __half2 h1 = __floats2half2_rn(v.z, v.w);
        d[i] = make_uint2(h2u(h0), h2u(h1));
    }
}
// [n][1024 d][512 r] fp32 -> [n][512 r][1024 d] fp16
__global__ void trans_cvt_h(const float* __restrict__ in, __half* __restrict__ out) {
    __shared__ float tile[32][33];
    const int n = blockIdx.z;
    const int d0 = blockIdx.y * 32, r0 = blockIdx.x * 32;
    const float* src = in + (size_t)n * Dm * RK;
    __half* dst = out + (size_t)n * RK * Dm;
    const int tx = threadIdx.x, ty = threadIdx.y;
    #pragma unroll
    for (int i = 0; i < 4; i++)
        tile[ty + i * 8][tx] = src[(size_t)(d0 + ty + i * 8) * RK + r0 + tx];
    __syncthreads();
    #pragma unroll
    for (int i = 0; i < 4; i++)
        dst[(size_t)(r0 + ty + i * 8) * Dm + d0 + tx] = __float2half(tile[tx][ty + i * 8]);
}
// basis_vo: produce BOTH bvoT (transposed) and bvoN (native) fp16 in one pass
__global__ void trans_cvt_dual(const float* __restrict__ in, __half* __restrict__ outT,
                               __half* __restrict__ outN) {
    __shared__ float tile[32][33];
    const int n = blockIdx.z;
    const int d0 = blockIdx.y * 32, r0 = blockIdx.x * 32;
    const float* src = in + (size_t)n * Dm * RK;
    __half* dstT = outT + (size_t)n * RK * Dm;
    __half* dstN = outN + (size_t)n * Dm * RK;
    const int tx = threadIdx.x, ty = threadIdx.y;
    #pragma unroll
    for (int i = 0; i < 4; i++) {
        float v = src[(size_t)(d0 + ty + i * 8) * RK + r0 + tx];
        tile[ty + i * 8][tx] = v;
        dstN[(size_t)(d0 + ty + i * 8) * RK + r0 + tx] = __float2half(v);
    }
    __syncthreads();
    #pragma unroll
    for (int i = 0; i < 4; i++)
        dstT[(size_t)(r0 + ty + i * 8) * Dm + d0 + tx] = __float2half(tile[tx][ty + i * 8]);
}

// ---------------- router GEMM (fp32 SIMT, cp.async double-buffered) ---------
__global__ __launch_bounds__(256) void router_gemm(const float* __restrict__ A,
                                                   const float* __restrict__ Bw,
                                                   float* __restrict__ C) {
    __shared__ float As[2][64][20];
    __shared__ float Bs[2][16][68];
    const int tid = threadIdx.x;
    const int tx = tid & 15, ty = tid >> 4;
    const int m0 = blockIdx.y * 64, n0 = blockIdx.x * 64;
    const uint32_t asb = (uint32_t)__cvta_generic_to_shared(&As[0][0][0]);
    const uint32_t bsb = (uint32_t)__cvta_generic_to_shared(&Bs[0][0][0]);
    const int ar = tid >> 2, ac = (tid & 3) * 4;
    const int brr = tid >> 4, bcc = (tid & 15) * 4;
    float acc[4][4] = {};
    auto load = [&](int kt, int buf) {
        CP_ASYNC16(asb + (uint32_t)((buf * 64 * 20 + ar * 20 + ac) * 4),
                   A + (size_t)(m0 + ar) * Dm + kt * 16 + ac);
        CP_ASYNC16(bsb + (uint32_t)((buf * 16 * 68 + brr * 68 + bcc) * 4),
                   Bw + (size_t)(kt * 16 + brr) * NN + n0 + bcc);
    };
    load(0, 0); CP_COMMIT;
    for (int kt = 0; kt < Dm / 16; kt++) {
        const int buf = kt & 1;
        if (kt + 1 < Dm / 16) {
            load(kt + 1, buf ^ 1); CP_COMMIT;
            asm volatile("cp.async.wait_group 1;");
        } else {
            asm volatile("cp.async.wait_group 0;");
        }
        __syncthreads();
        #pragma unroll
        for (int kk = 0; kk < 16; kk++) {
            float4 bv = *(const float4*)&Bs[buf][kk][tx * 4];
            float a0 = As[buf][ty * 4 + 0][kk];
            float a1 = As[buf][ty * 4 + 1][kk];
            float a2 = As[buf][ty * 4 + 2][kk];
            float a3 = As[buf][ty * 4 + 3][kk];
            acc[0][0] += a0 * bv.x; acc[0][1] += a0 * bv.y; acc[0][2] += a0 * bv.z; acc[0][3] += a0 * bv.w;
            acc[1][0] += a1 * bv.x; acc[1][1] += a1 * bv.y; acc[1][2] += a1 * bv.z; acc[1][3] += a1 * bv.w;
            acc[2][0] += a2 * bv.x; acc[2][1] += a2 * bv.y; acc[2][2] += a2 * bv.z; acc[2][3] += a2 * bv.w;
            acc[3][0] += a3 * bv.x; acc[3][1] += a3 * bv.y; acc[3][2] += a3 * bv.z; acc[3][3] += a3 * bv.w;
        }
        __syncthreads();
    }
    #pragma unroll
    for (int i = 0; i < 4; i++)
        *(float4*)&C[(size_t)(m0 + ty * 4 + i) * NN + n0 + tx * 4] =
            make_float4(acc[i][0], acc[i][1], acc[i][2], acc[i][3]);
}

// ---------------- routing ----------------------------------------------------
__global__ void route_kernel(const float* __restrict__ scores,
                             const float* __restrict__ rQ, const float* __restrict__ rK,
                             const float* __restrict__ rV, const float* __restrict__ rO,
                             float* __restrict__ tQ, float* __restrict__ tK,
                             float* __restrict__ tV, float* __restrict__ tO) {
    const int t = blockIdx.x;
    const int lane = threadIdx.x;
    const float* s = scores + (size_t)t * NN;
    float v[8];
    #pragma unroll
    for (int i = 0; i < 8; i++) v[i] = s[i * 32 + lane];
    float top_v[TOPK];
    int   top_i[TOPK];
    for (int it = 0; it < TOPK; it++) {
        float lm = -FLT_MAX; int li = 0;
        #pragma unroll
        for (int i = 0; i < 8; i++) if (v[i] > lm) { lm = v[i]; li = i; }
        int gi = li * 32 + lane;
        #pragma unroll
        for (int off = 16; off > 0; off >>= 1) {
            float ov = __shfl_xor_sync(0xffffffffu, lm, off);
            int   oi = __shfl_xor_sync(0xffffffffu, gi, off);
            if (ov > lm || (ov == lm && oi < gi)) { lm = ov; gi = oi; }
        }
        top_v[it] = lm; top_i[it] = gi;
        if (lane == (gi & 31)) v[gi >> 5] = -FLT_MAX;
    }
    float w[TOPK], ssum = 0.f;
    #pragma unroll
    for (int k = 0; k < TOPK; k++) { w[k] = expf(top_v[k] - top_v[0]); ssum += w[k]; }
    float inv = 1.f / ssum;
    #pragma unroll
    for (int k = 0; k < TOPK; k++) w[k] *= inv;
    const float* recs[4] = { rQ, rK, rV, rO };
    float* outs[4] = { tQ, tK, tV, tO };
    for (int rr = 0; rr < 4; rr++) {
        const float* R = recs[rr];
        float a = 0.f;
        #pragma unroll
        for (int k = 0; k < TOPK; k++) a += w[k] * R[top_i[k] * NB + lane];
        float mx = a;
        #pragma unroll
        for (int off = 16; off > 0; off >>= 1) mx = fmaxf(mx, __shfl_xor_sync(0xffffffffu, mx, off));
        float e = expf(a - mx);
        float sm = e;
        #pragma unroll
        for (int off = 16; off > 0; off >>= 1) sm += __shfl_xor_sync(0xffffffffu, sm, off);
        outs[rr][(size_t)t * NB + lane] = e / sm;
    }
}

// ---------------- QK fused projection, fp16 mma + ldmatrix ------------------
// SMEM: [Xs][B ring][trQs][trKs]
__global__ __launch_bounds__(256) void qk_mma(
        const __half* __restrict__ Xh, const __half* __restrict__ Bt,
        const float* __restrict__ trQ, const float* __restrict__ trK,
        float* __restrict__ Qo, float* __restrict__ Ko) {
    extern __shared__ __half smh[];
    __half* Xs = smh;                        // [128][XRH]
    __half* Bs = smh + BM * XRH;             // [NSTG][64][BRH]
    float* trQs = (float*)(smh + BM * XRH + NSTG * 64 * BRH);   // [128][WROW]
    float* trKs = trQs + BM * WROW;
    const uint32_t xsb = (uint32_t)__cvta_generic_to_shared(Xs);
    const uint32_t bsb = (uint32_t)__cvta_generic_to_shared(Bs);
    const int tid = threadIdx.x;
    const int m0 = blockIdx.y * BM, r0 = blockIdx.x * BN;
    const int w = tid >> 5, lane = tid & 31;
    const int wm = (w >> 1) * 32, wn = (w & 1) * 32;
    const int g = lane >> 2, tg = lane & 3;
    float accQ[2][4][4] = {}, accK[2][4][4] = {}, accT[2][4][4] = {};

    // stage routing weights to SMEM once
    #pragma unroll
    for (int i = 0; i < BM * NB / 256; i++) {
        int e = tid + i * 256;
        int row = e >> 5, c = e & 31;
        trQs[row * WROW + c] = trQ[(size_t)(m0 + row) * NB + c];
        trKs[row * WROW + c] = trK[(size_t)(m0 + row) * NB + c];
    }

    const int br = tid >> 2, bc = tid & 3;
    const uint32_t xA0 = xsb + (uint32_t)(((wm + (lane & 15)) * XRH + (lane >> 4) * 8) * 2);
    const uint32_t xA1 = xA0 + (uint32_t)(16 * XRH * 2);
    const uint32_t bInv = (uint32_t)(((wn + (lane & 7) + 8 * (lane >> 4)) * BRH
                                      + ((lane >> 3) & 1) * 8) * 2);

    for (int kp = 0; kp < Dm / KP; kp++) {
        __syncthreads();
        {   // X panel
            const __half* Xg = Xh + (size_t)m0 * Dm + kp * KP;
            #pragma unroll
            for (int i = 0; i < 8; i++) {
                int rr = (tid >> 4) + i * 16, cc = tid & 15;
                CP_ASYNC16(xsb + (uint32_t)(rr * XRH + cc * 8) * 2,
                           Xg + (size_t)rr * Dm + cc * 8);
            }
        }
        auto stageB = [&](int s2) {
            const int j = s2 % NSTG, n = s2 >> 2, ks = s2 & 3;
            CP_ASYNC16(bsb + (uint32_t)((j * 64 + br) * BRH + bc * 8) * 2,
                       Bt + ((size_t)n * RK + r0 + br) * Dm + kp * KP + ks * 32 + bc * 8);
        };
        stageB(0); CP_COMMIT;
        stageB(1); CP_COMMIT;
        stageB(2); CP_COMMIT;
        stageB(3); CP_COMMIT;
        stageB(4); CP_COMMIT;
        for (int s = 0; s < 128; s++) {
            if (s + 5 < 128) { asm volatile("cp.async.wait_group 4;"); }
            else             { asm volatile("cp.async.wait_group 0;"); }
            __syncthreads();
            const uint32_t bB = bsb + (uint32_t)((s % NSTG) * (64 * BRH) * 2);
            const int kb = (s & 3) * 32;
            #pragma unroll
            for (int seg = 0; seg < 32; seg += 16) {
                unsigned aa[2][4], bb[4][2];
                const int kc0 = kb + seg;
                LDSM_X4(aa[0][0], aa[0][1], aa[0][2], aa[0][3], xA0 + kc0 * 2);
                LDSM_X4(aa[1][0], aa[1][1], aa[1][2], aa[1][3], xA1 + kc0 * 2);
                LDSM_X4(bb[0][0], bb[0][1], bb[1][0], bb[1][1], bB + bInv + seg * 2);
                LDSM_X4(bb[2][0], bb[2][1], bb[3][0], bb[3][1],
                        bB + bInv + (uint32_t)(16 * BRH * 2) + seg * 2);
                #pragma unroll
                for (int mf = 0; mf < 2; mf++)
                    #pragma unroll
                    for (int j = 0; j < 4; j++) mma_f16(accT[mf][j], aa[mf], bb[j]);
            }
            if ((s & 3) == 3) {
                const int n = s >> 2;
                #pragma unroll
                for (int mf = 0; mf < 2; mf++) {
                    const int rL = wm + mf * 16 + g;
                    float wq0 = trQs[rL * WROW + n];
                    float wq8 = trQs[(rL + 8) * WROW + n];
                    float wk0 = trKs[rL * WROW + n];
                    float wk8 = trKs[(rL + 8) * WROW + n];
                    #pragma unroll
                    for (int j = 0; j < 4; j++) {
                        accQ[mf][j][0] += wq0 * accT[mf][j][0];
                        accQ[mf][j][1] += wq0 * accT[mf][j][1];
                        accQ[mf][j][2] += wq8 * accT[mf][j][2];
                        accQ[mf][j][3] += wq8 * accT[mf][j][3];
                        accK[mf][j][0] += wk0 * accT[mf][j][0];
                        accK[mf][j][1] += wk0 * accT[mf][j][1];
                        accK[mf][j][2] += wk8 * accT[mf][j][2];
                        accK[mf][j][3] += wk8 * accT[mf][j][3];
                        accT[mf][j][0] = 0.f; accT[mf][j][1] = 0.f;
                        accT[mf][j][2] = 0.f; accT[mf][j][3] = 0.f;
                    }
                }
            }
            if (s + 5 < 128) { stageB(s + 5); CP_COMMIT; }
        }
    }
    #pragma unroll
    for (int mf = 0; mf < 2; mf++)
        #pragma unroll
        for (int j = 0; j < 4; j++) {
            const int row = m0 + wm + mf * 16 + g;
            const int col = r0 + wn + j * 8 + tg * 2;
            *(float2*)(Qo + (size_t)row * RK + col)       = make_float2(accQ[mf][j][0], accQ[mf][j][1]);
            *(float2*)(Qo + (size_t)(row + 8) * RK + col) = make_float2(accQ[mf][j][2], accQ[mf][j][3]);
            *(float2*)(Ko + (size_t)row * RK + col)       = make_float2(accK[mf][j][0], accK[mf][j][1]);
            *(float2*)(Ko + (size_t)(row + 8) * RK + col) = make_float2(accK[mf][j][2], accK[mf][j][3]);
        }
}

// ---------------- V projection, fp16 mma + ldmatrix --------------------------
__global__ __launch_bounds__(256) void v_mma(
        const __half* __restrict__ Xh, const __half* __restrict__ Bt,
        const float* __restrict__ trV, float* __restrict__ Vo) {
    extern __shared__ __half smh[];
    __half* Xs = smh;
    __half* Bs = smh + BM * XRH;
    float* trVs = (float*)(smh + BM * XRH + NSTG * 64 * BRH);   // [128][WROW]
    const uint32_t xsb = (uint32_t)__cvta_generic_to_shared(Xs);
    const uint32_t bsb = (uint32_t)__cvta_generic_to_shared(Bs);
    const int tid = threadIdx.x;
    const int m0 = blockIdx.y * BM, r0 = blockIdx.x * BN;
    const int w = tid >> 5, lane = tid & 31;
    const int wm = (w >> 1) * 32, wn = (w & 1) * 32;
    const int g = lane >> 2, tg = lane & 3;
    float accV[2][4][4] = {}, accT[2][4][4] = {};

    #pragma unroll
    for (int i = 0; i < BM * NB / 256; i++) {
        int e = tid + i * 256;
        int row = e >> 5, c = e & 31;
        trVs[row * WROW + c] = trV[(size_t)(m0 + row) * NB + c];
    }

    const int br = tid >> 2, bc = tid & 3;
    const uint32_t xA0 = xsb + (uint32_t)(((wm + (lane & 15)) * XRH + (lane >> 4) * 8) * 2);
    const uint32_t xA1 = xA0 + (uint32_t)(16 * XRH * 2);
    const uint32_t bInv = (uint32_t)(((wn + (lane & 7) + 8 * (lane >> 4)) * BRH
                                      + ((lane >> 3) & 1) * 8) * 2);

    for (int kp = 0; kp < Dm / KP; kp++) {
        __syncthreads();
        {
            const __half* Xg = Xh + (size_t)m0 * Dm + kp * KP;
            #pragma unroll
            for (int i = 0; i < 8; i++) {
                int rr = (tid >> 4) + i * 16, cc = tid & 15;
                CP_ASYNC16(xsb + (uint32_t)(rr * XRH + cc * 8) * 2,
                           Xg + (size_t)rr * Dm + cc * 8);
            }
        }
        auto stageB = [&](int s2) {
            const int j = s2 % NSTG, n = s2 >> 2, ks = s2 & 3;
            CP_ASYNC16(bsb + (uint32_t)((j * 64 + br) * BRH + bc * 8) * 2,
                       Bt + ((size_t)n * RK + r0 + br) * Dm + kp * KP + ks * 32 + bc * 8);
        };
        stageB(0); CP_COMMIT;
        stageB(1); CP_COMMIT;
        stageB(2); CP_COMMIT;
        stageB(3); CP_COMMIT;
        stageB(4); CP_COMMIT;
        for (int s = 0; s < 128; s++) {
            if (s + 5 < 128) { asm volatile("cp.async.wait_group 4;"); }
            else             { asm volatile("cp.async.wait_group 0;"); }
            __syncthreads();
            const uint32_t bB = bsb + (uint32_t)((s % NSTG) * (64 * BRH) * 2);
            const int kb = (s & 3) * 32;
            #pragma unroll
            for (int seg = 0; seg < 32; seg += 16) {
                unsigned aa[2][4], bb[4][2];
                const int kc0 = kb + seg;
                LDSM_X4(aa[0][0], aa[0][1], aa[0][2], aa[0][3], xA0 + kc0 * 2);
                LDSM_X4(aa[1][0], aa[1][1], aa[1][2], aa[1][3], xA1 + kc0 * 2);
                LDSM_X4(bb[0][0], bb[0][1], bb[1][0], bb[1][1], bB + bInv + seg * 2);
                LDSM_X4(bb[2][0], bb[2][1], bb[3][0], bb[3][1],
                        bB + bInv + (uint32_t)(16 * BRH * 2) + seg * 2);
                #pragma unroll
                for (int mf = 0; mf < 2; mf++)
                    #pragma unroll
                    for (int j = 0; j < 4; j++) mma_f16(accT[mf][j], aa[mf], bb[j]);
            }
            if ((s & 3) == 3) {
                const int n = s >> 2;
                #pragma unroll
                for (int mf = 0; mf < 2; mf++) {
                    const int rL = wm + mf * 16 + g;
                    float w0 = trVs[rL * WROW + n];
                    float w8 = trVs[(rL + 8) * WROW + n];
                    #pragma unroll
                    for (int j = 0; j < 4; j++) {
                        accV[mf][j][0] += w0 * accT[mf][j][0];
                        accV[mf][j][1] += w0 * accT[mf][j][1];
                        accV[mf][j][2] += w8 * accT[mf][j][2];
                        accV[mf][j][3] += w8 * accT[mf][j][3];
                        accT[mf][j][0] = 0.f; accT[mf][j][1] = 0.f;
                        accT[mf][j][2] = 0.f; accT[mf][j][3] = 0.f;
                    }
                }
            }
            if (s + 5 < 128) { stageB(s + 5); CP_COMMIT; }
        }
    }
    #pragma unroll
    for (int mf = 0; mf < 2; mf++)
        #pragma unroll
        for (int j = 0; j < 4; j++) {
            const int row = m0 + wm + mf * 16 + g;
            const int col = r0 + wn + j * 8 + tg * 2;
            *(float2*)(Vo + (size_t)row * RK + col)       = make_float2(accV[mf][j][0], accV[mf][j][1]);
            *(float2*)(Vo + (size_t)(row + 8) * RK + col) = make_float2(accV[mf][j][2], accV[mf][j][3]);
        }
}

// ---------------- causal attention (lane=key layout) ------------------------
__global__ void attn_kernel(const float* __restrict__ Q, const float* __restrict__ Km,
                            const float* __restrict__ V, float* __restrict__ ctx) {
    __shared__ float Ks[64][33];
    __shared__ float Vs[64][33];
    const int bh = blockIdx.x;
    const int b = bh >> 4, h = bh & 15;
    const int warp = threadIdx.x >> 5, lane = threadIdx.x & 31;
    const int q = blockIdx.y * 8 + warp;
    const size_t tq = (size_t)b * Ssz + q;
    const float scale = 0.17677669529663688f;
    const float qd = Q[tq * RK + h * DH + lane] * scale;
    float qr[32];
    #pragma unroll
    for (int d = 0; d < 32; d++) qr[d] = __shfl_sync(0xffffffffu, qd, d);
    float m = -1e30f, l = 0.f, acc = 0.f;
    const int qmax = blockIdx.y * 8 + 7;
    for (int k0 = 0; k0 <= qmax; k0 += 64) {
        __syncthreads();
        #pragma unroll
        for (int p = 0; p < 8; p++) {
            int e = threadIdx.x + p * 256;
            int r = e >> 5, c = e & 31;
            size_t tk = ((size_t)b * Ssz + k0 + r) * RK + h * DH + c;
            Ks[r][c] = Km[tk];
            Vs[r][c] = V[tk];
        }
        __syncthreads();
        #pragma unroll
        for (int j0 = 0; j0 < 64; j0 += 32) {
            if (k0 + j0 > q) break;
            const int kidx = k0 + j0 + lane;
            float sv = 0.f;
            #pragma unroll
            for (int d = 0; d < 32; d++) sv += qr[d] * Ks[j0 + lane][d];
            if (kidx > q) sv = -1e30f;
            float mx = sv;
            #pragma unroll
            for (int off = 16; off > 0; off >>= 1)
                mx = fmaxf(mx, __shfl_xor_sync(0xffffffffu, mx, off));
            const float mn = fmaxf(m, mx);
            const float p = __expf(sv - mn);
            float sum = p;
            #pragma unroll
            for (int off = 16; off > 0; off >>= 1)
                sum += __shfl_xor_sync(0xffffffffu, sum, off);
            const float cr = __expf(m - mn);
            l = l * cr + sum;
            float a2 = 0.f;
            #pragma unroll
            for (int j = 0; j < 32; j++)
                a2 += __shfl_sync(0xffffffffu, p, j) * Vs[j0 + j][lane];
            acc = acc * cr + a2;
            m = mn;
        }
    }
    ctx[tq * RK + h * DH + lane] = acc / l;
}

// ---------------- O projection, fp16 mma + ldmatrix (resident ctx panel) ----
// SMEM: [trOs][ctxs][A ring][B ring]
__global__ __launch_bounds__(256) void o_mma(
        const float* __restrict__ Cx, const __half* __restrict__ BvN,
        const float* __restrict__ trO, float* __restrict__ Out) {
    extern __shared__ __half smh[];
    float*  trOs = (float*)smh;                                  // [128][WROW]
    float*  ctxs = trOs + BM * WROW;                             // [128][CTXW]
    __half* Ah   = (__half*)(ctxs + BM * CTXW);                  // [NSTG][128][BRH]
    __half* Bh   = Ah + NSTG * BM * BRH;                         // [NSTG][64][BRH]
    const uint32_t ctxb = (uint32_t)__cvta_generic_to_shared(ctxs);
    const uint32_t asb  = (uint32_t)__cvta_generic_to_shared(Ah);
    const uint32_t bsb  = (uint32_t)__cvta_generic_to_shared(Bh);
    const int tid = threadIdx.x;
    const int m0 = blockIdx.y * BM, d0 = blockIdx.x * BN;
    const int w = tid >> 5, lane = tid & 31;
    const int wm = (w >> 1) * 32, wn = (w & 1) * 32;
    const int g = lane >> 2, tg = lane & 3;
    float accO[2][4][4] = {};
    const int br = tid >> 2, bc = tid & 3;
    const uint32_t aInv = (uint32_t)(((wm + (lane & 15)) * BRH + (lane >> 4) * 8) * 2);
    const uint32_t bInv = (uint32_t)(((wn + (lane & 7) + 8 * (lane >> 4)) * BRH
                                      + ((lane >> 3) & 1) * 8) * 2);

    #pragma unroll
    for (int i = 0; i < BM * NB / 256; i++) {
        int e = tid + i * 256;
        int row = e >> 5, c = e & 31;
        trOs[row * WROW + c] = trO[(size_t)(m0 + row) * NB + c];
    }

    for (int kp = 0; kp < RK / KP; kp++) {   // 4 panels over r
        __syncthreads();
        {   // ctx panel fp32 [128][128]
            #pragma unroll
            for (int i = 0; i < 16; i++) {
                int idx = tid + i * 256;
                int rr = idx >> 5, cc = idx & 31;
                CP_ASYNC16(ctxb + (uint32_t)(rr * CTXW + cc * 4) * 4,
                           Cx + (size_t)(m0 + rr) * RK + kp * KP + cc * 4);
            }
            CP_COMMIT;
            asm volatile("cp.async.wait_group 0;");
            __syncthreads();
        }
        auto stageA = [&](int s2) {
            const int j = s2 % NSTG, n = s2 >> 2, ks = s2 & 3;
            const int row = tid >> 1, off = (tid & 1) * 16;
            const float wv = trOs[row * WROW + n];
            const float* cr = ctxs + row * CTXW + ks * 32 + off;
            __half* dst = Ah + (j * BM + row) * BRH + off;
            #pragma unroll
            for (int q2 = 0; q2 < 2; q2++) {
                float4 v0 = *(const float4*)(cr + q2 * 8);
                float4 v1 = *(const float4*)(cr + q2 * 8 + 4);
                __half2 h0 = __floats2half2_rn(wv * v0.x, wv * v0.y);
                __half2 h1 = __floats2half2_rn(wv * v0.z, wv * v0.w);
                __half2 h2 = __floats2half2_rn(wv * v1.x, wv * v1.y);
                __half2 h3 = __floats2half2_rn(wv * v1.z, wv * v1.w);
                uint32_t da = (uint32_t)__cvta_generic_to_shared(dst + q2 * 8);
                STS128(da, h2u(h0), h2u(h1), h2u(h2), h2u(h3));
            }
        };
        auto stageB = [&](int s2) {
            const int j = s2 % NSTG, n = s2 >> 2, ks = s2 & 3;
            CP_ASYNC16(bsb + (uint32_t)((j * 64 + br) * BRH + bc * 8) * 2,
                       BvN + ((size_t)n * Dm + d0 + br) * RK + kp * KP + ks * 32 + bc * 8);
        };
        stageA(0); stageB(0); CP_COMMIT;
        stageA(1); stageB(1); CP_COMMIT;
        stageA(2); stageB(2); CP_COMMIT;
        stageA(3); stageB(3); CP_COMMIT;
        stageA(4); stageB(4); CP_COMMIT;
        for (int s = 0; s < 128; s++) {
            if (s + 5 < 128) { asm volatile("cp.async.wait_group 4;"); }
            else             { asm volatile("cp.async.wait_group 0;"); }
            __syncthreads();
            const uint32_t aB = asb + (uint32_t)((s % NSTG) * (BM * BRH) * 2);
            const uint32_t bB = bsb + (uint32_t)((s % NSTG) * (64 * BRH) * 2);
            #pragma unroll
            for (int seg = 0; seg < 32; seg += 16) {
                unsigned aa[2][4], bb[4][2];
                LDSM_X4(aa[0][0], aa[0][1], aa[0][2], aa[0][3], aB + aInv + seg * 2);
                LDSM_X4(aa[1][0], aa[1][1], aa[1][2], aa[1][3],
                        aB + aInv + (uint32_t)(16 * BRH * 2) + seg * 2);
                LDSM_X4(bb[0][0], bb[0][1], bb[1][0], bb[1][1], bB + bInv + seg * 2);
                LDSM_X4(bb[2][0], bb[2][1], bb[3][0], bb[3][1],
                        bB + bInv + (uint32_t)(16 * BRH * 2) + seg * 2);
                #pragma unroll
                for (int mf = 0; mf < 2; mf++)
                    #pragma unroll
                    for (int j = 0; j < 4; j++) mma_f16(accO[mf][j], aa[mf], bb[j]);
            }
            if (s + 5 < 128) { stageA(s + 5); stageB(s + 5); CP_COMMIT; }
        }
    }
    #pragma unroll
    for (int mf = 0; mf < 2; mf++)
        #pragma unroll
        for (int j = 0; j < 4; j++) {
            const int row = m0 + wm + mf * 16 + g;
            const int col = d0 + wn + j * 8 + tg * 2;
            *(float2*)(Out + (size_t)row * Dm + col)       = make_float2(accO[mf][j][0], accO[mf][j][1]);
            *(float2*)(Out + (size_t)(row + 8) * Dm + col) = make_float2(accO[mf][j][2], accO[mf][j][3]);
        }
}

// ---------------- launch ----------------------------------------------------
extern "C" void kernel_launch(void* const* d_in, const int* in_sizes, int n_in,
                              void* d_out, int out_size) {
    const float* x        = (const float*)d_in[0];
    const float* W_router = (const float*)d_in[1];
    const float* recipe_Q = (const float*)d_in[2];
    const float* recipe_K = (const float*)d_in[3];
    const float* recipe_V = (const float*)d_in[4];
    const float* recipe_O = (const float*)d_in[5];
    const float* basis_qk = (const float*)d_in[6];
    const float* basis_vo = (const float*)d_in[7];
    float* out = (float*)d_out;

    float *scores, *tQ, *tK, *tV, *tO, *Qp, *Kp, *Vp, *ctx;
    __half *xh, *bqkT, *bvoT, *bvoN;
    cudaGetSymbolAddress((void**)&scores, g_scores);
    cudaGetSymbolAddress((void**)&tQ, g_trQ);
    cudaGetSymbolAddress((void**)&tK, g_trK);
    cudaGetSymbolAddress((void**)&tV, g_trV);
    cudaGetSymbolAddress((void**)&tO, g_trO);
    cudaGetSymbolAddress((void**)&Qp, g_Q);
    cudaGetSymbolAddress((void**)&Kp, g_Km);
    cudaGetSymbolAddress((void**)&Vp, g_V);
    cudaGetSymbolAddress((void**)&ctx, g_ctx);
    cudaGetSymbolAddress((void**)&xh, g_xh);
    cudaGetSymbolAddress((void**)&bqkT, g_bqkT);
    cudaGetSymbolAddress((void**)&bvoT, g_bvoT);
    cudaGetSymbolAddress((void**)&bvoN, g_bvoN);

    const int QK_SMEM = (BM * XRH + NSTG * 64 * BRH) * 2 + 2 * BM * WROW * 4;   // 99328
    const int V_SMEM  = (BM * XRH + NSTG * 64 * BRH) * 2 + BM * WROW * 4;       // 82432
    const int O_SMEM  = BM * WROW * 4 + BM * CTXW * 4
                      + (NSTG * BM * BRH + NSTG * 64 * BRH) * 2;                // 176640
    cudaFuncSetAttribute(qk_mma, cudaFuncAttributeMaxDynamicSharedMemorySize, QK_SMEM);
    cudaFuncSetAttribute(v_mma,  cudaFuncAttributeMaxDynamicSharedMemorySize, V_SMEM);
    cudaFuncSetAttribute(o_mma,  cudaFuncAttributeMaxDynamicSharedMemorySize, O_SMEM);

    // launch order chosen so qk_mma is launch #6 (ncu -s 5 -c 1 capture slot)
    cvt_half_kernel<<<1024, 256>>>((const float4*)x, (uint2*)xh, NT * Dm / 4);          // 1
    trans_cvt_h<<<dim3(RK / 32, Dm / 32, NB), dim3(32, 8)>>>(basis_qk, bqkT);           // 2
    router_gemm<<<dim3(NN / 64, NT / 64), 256>>>(x, W_router, scores);                  // 3
    route_kernel<<<NT, 32>>>(scores, recipe_Q, recipe_K, recipe_V, recipe_O,
                             tQ, tK, tV, tO);                                           // 4
    trans_cvt_dual<<<dim3(RK / 32, Dm / 32, NB), dim3(32, 8)>>>(basis_vo, bvoT, bvoN);  // 5
    qk_mma<<<dim3(RK / BN, NT / BM), 256, QK_SMEM>>>(xh, bqkT, tQ, tK, Qp, Kp);         // 6 <- profiled
    v_mma<<<dim3(RK / BN, NT / BM), 256, V_SMEM>>>(xh, bvoT, tV, Vp);                   // 7
    attn_kernel<<<dim3(Bsz * NH, Ssz / 8), 256>>>(Qp, Kp, Vp, ctx);                     // 8
    o_mma<<<dim3(Dm / BN, NT / BM), 256, O_SMEM>>>(ctx, bvoN, tO, out);                 // 9
}

// round 11
// speedup vs baseline: 7.3304x; 1.0062x over previous
#include <cuda_runtime.h>
#include <cuda_fp16.h>
#include <cfloat>
#include <cstdint>

#define Bsz 4
#define Ssz 1024
#define Dm  1024
#define NT  4096
#define NN  256
#define NB  32
#define RK  512
#define NH  16
#define DH  32
#define TOPK 8

// fp16 mma tiling
#define BM 128
#define BN 64
#define KP 128            // X panel width (halfs) for qk/v; floats for O ctx panel
#define XRH 136           // X panel row stride in halfs (68 words = 4 mod 32: conflict-free)
#define BRH 40            // B/A tile row stride in halfs (20 words: conflict-free)
#define CTXW 132          // O ctx panel row stride in floats
#define NSTG 6            // cp.async ring depth
#define WROW 33           // SMEM weight-tile row stride (floats)

// ---------------- scratch ---------------------------------------------------
__device__ float  g_scores[NT * NN];
__device__ float  g_trQ[NT * NB];
__device__ float  g_trK[NT * NB];
__device__ float  g_trV[NT * NB];
__device__ float  g_trO[NT * NB];
__device__ float  g_Q[NT * RK];
__device__ float  g_Km[NT * RK];
__device__ float  g_V[NT * RK];
__device__ float  g_ctx[NT * RK];
__device__ __half g_xh[NT * Dm];             // fp16 x
__device__ __half g_bqkT[NB * RK * Dm];      // fp16 basis_qk^T [n][r][d]
__device__ __half g_bvoT[NB * RK * Dm];      // fp16 basis_vo^T [n][r][d]
__device__ __half g_bvoN[NB * Dm * RK];      // fp16 basis_vo native [n][d][r]

// ---------------- helpers ---------------------------------------------------
__device__ __forceinline__ void mma_f16(float* c, const unsigned* a, const unsigned* b) {
    asm volatile("mma.sync.aligned.m16n8k16.row.col.f32.f16.f16.f32 "
        "{%0,%1,%2,%3}, {%4,%5,%6,%7}, {%8,%9}, {%0,%1,%2,%3};"
        : "+f"(c[0]), "+f"(c[1]), "+f"(c[2]), "+f"(c[3])
        : "r"(a[0]), "r"(a[1]), "r"(a[2]), "r"(a[3]), "r"(b[0]), "r"(b[1]));
}
#define CP_ASYNC16(dst, src) \
    asm volatile("cp.async.cg.shared.global [%0], [%1], 16;" :: "r"(dst), "l"(src))
#define CP_COMMIT asm volatile("cp.async.commit_group;")
#define STS128(a, r0, r1, r2, r3) \
    asm volatile("st.shared.v4.b32 [%0], {%1, %2, %3, %4};" \
                 :: "r"(a), "r"(r0), "r"(r1), "r"(r2), "r"(r3) : "memory")
#define LDSM_X4(r0, r1, r2, r3, a) \
    asm volatile("ldmatrix.sync.aligned.m8n8.x4.shared.b16 {%0, %1, %2, %3}, [%4];" \
        : "=r"(r0), "=r"(r1), "=r"(r2), "=r"(r3) : "r"(a))
__device__ __forceinline__ unsigned h2u(__half2 h) { return *reinterpret_cast<unsigned*>(&h); }

// ---------------- preprocessing ---------------------------------------------
__global__ void cvt_half_kernel(const float4* __restrict__ s, uint2* __restrict__ d, int n4) {
    for (int i = blockIdx.x * blockDim.x + threadIdx.x; i < n4; i += gridDim.x * blockDim.x) {
        float4 v = s[i];
        __half2 h0 = __floats2half2_rn(v.x, v.y);
        __half2 h1 = __floats2half2_rn(v.z, v.w);
        d[i] = make_uint2(h2u(h0), h2u(h1));
    }
}
// [n][1024 d][512 r] fp32 -> [n][512 r][1024 d] fp16
__global__ void trans_cvt_h(const float* __restrict__ in, __half* __restrict__ out) {
    __shared__ float tile[32][33];
    const int n = blockIdx.z;
    const int d0 = blockIdx.y * 32, r0 = blockIdx.x * 32;
    const float* src = in + (size_t)n * Dm * RK;
    __half* dst = out + (size_t)n * RK * Dm;
    const int tx = threadIdx.x, ty = threadIdx.y;
    #pragma unroll
    for (int i = 0; i < 4; i++)
        tile[ty + i * 8][tx] = src[(size_t)(d0 + ty + i * 8) * RK + r0 + tx];
    __syncthreads();
    #pragma unroll
    for (int i = 0; i < 4; i++)
        dst[(size_t)(r0 + ty + i * 8) * Dm + d0 + tx] = __float2half(tile[tx][ty + i * 8]);
}
// basis_vo: produce BOTH bvoT (transposed) and bvoN (native) fp16 in one pass
__global__ void trans_cvt_dual(const float* __restrict__ in, __half* __restrict__ outT,
                               __half* __restrict__ outN) {
    __shared__ float tile[32][33];
    const int n = blockIdx.z;
    const int d0 = blockIdx.y * 32, r0 = blockIdx.x * 32;
    const float* src = in + (size_t)n * Dm * RK;
    __half* dstT = outT + (size_t)n * RK * Dm;
    __half* dstN = outN + (size_t)n * Dm * RK;
    const int tx = threadIdx.x, ty = threadIdx.y;
    #pragma unroll
    for (int i = 0; i < 4; i++) {
        float v = src[(size_t)(d0 + ty + i * 8) * RK + r0 + tx];
        tile[ty + i * 8][tx] = v;
        dstN[(size_t)(d0 + ty + i * 8) * RK + r0 + tx] = __float2half(v);
    }
    __syncthreads();
    #pragma unroll
    for (int i = 0; i < 4; i++)
        dstT[(size_t)(r0 + ty + i * 8) * Dm + d0 + tx] = __float2half(tile[tx][ty + i * 8]);
}

// ---------------- router GEMM (fp32 SIMT, cp.async double-buffered) ---------
__global__ __launch_bounds__(256) void router_gemm(const float* __restrict__ A,
                                                   const float* __restrict__ Bw,
                                                   float* __restrict__ C) {
    __shared__ float As[2][64][20];
    __shared__ float Bs[2][16][68];
    const int tid = threadIdx.x;
    const int tx = tid & 15, ty = tid >> 4;
    const int m0 = blockIdx.y * 64, n0 = blockIdx.x * 64;
    const uint32_t asb = (uint32_t)__cvta_generic_to_shared(&As[0][0][0]);
    const uint32_t bsb = (uint32_t)__cvta_generic_to_shared(&Bs[0][0][0]);
    const int ar = tid >> 2, ac = (tid & 3) * 4;
    const int brr = tid >> 4, bcc = (tid & 15) * 4;
    float acc[4][4] = {};
    auto load = [&](int kt, int buf) {
        CP_ASYNC16(asb + (uint32_t)((buf * 64 * 20 + ar * 20 + ac) * 4),
                   A + (size_t)(m0 + ar) * Dm + kt * 16 + ac);
        CP_ASYNC16(bsb + (uint32_t)((buf * 16 * 68 + brr * 68 + bcc) * 4),
                   Bw + (size_t)(kt * 16 + brr) * NN + n0 + bcc);
    };
    load(0, 0); CP_COMMIT;
    for (int kt = 0; kt < Dm / 16; kt++) {
        const int buf = kt & 1;
        if (kt + 1 < Dm / 16) {
            load(kt + 1, buf ^ 1); CP_COMMIT;
            asm volatile("cp.async.wait_group 1;");
        } else {
            asm volatile("cp.async.wait_group 0;");
        }
        __syncthreads();
        #pragma unroll
        for (int kk = 0; kk < 16; kk++) {
            float4 bv = *(const float4*)&Bs[buf][kk][tx * 4];
            float a0 = As[buf][ty * 4 + 0][kk];
            float a1 = As[buf][ty * 4 + 1][kk];
            float a2 = As[buf][ty * 4 + 2][kk];
            float a3 = As[buf][ty * 4 + 3][kk];
            acc[0][0] += a0 * bv.x; acc[0][1] += a0 * bv.y; acc[0][2] += a0 * bv.z; acc[0][3] += a0 * bv.w;
            acc[1][0] += a1 * bv.x; acc[1][1] += a1 * bv.y; acc[1][2] += a1 * bv.z; acc[1][3] += a1 * bv.w;
            acc[2][0] += a2 * bv.x; acc[2][1] += a2 * bv.y; acc[2][2] += a2 * bv.z; acc[2][3] += a2 * bv.w;
            acc[3][0] += a3 * bv.x; acc[3][1] += a3 * bv.y; acc[3][2] += a3 * bv.z; acc[3][3] += a3 * bv.w;
        }
        __syncthreads();
    }
    #pragma unroll
    for (int i = 0; i < 4; i++)
        *(float4*)&C[(size_t)(m0 + ty * 4 + i) * NN + n0 + tx * 4] =
            make_float4(acc[i][0], acc[i][1], acc[i][2], acc[i][3]);
}

// ---------------- routing ----------------------------------------------------
__global__ void route_kernel(const float* __restrict__ scores,
                             const float* __restrict__ rQ, const float* __restrict__ rK,
                             const float* __restrict__ rV, const float* __restrict__ rO,
                             float* __restrict__ tQ, float* __restrict__ tK,
                             float* __restrict__ tV, float* __restrict__ tO) {
    const int t = blockIdx.x;
    const int lane = threadIdx.x;
    const float* s = scores + (size_t)t * NN;
    float v[8];
    #pragma unroll
    for (int i = 0; i < 8; i++) v[i] = s[i * 32 + lane];
    float top_v[TOPK];
    int   top_i[TOPK];
    for (int it = 0; it < TOPK; it++) {
        float lm = -FLT_MAX; int li = 0;
        #pragma unroll
        for (int i = 0; i < 8; i++) if (v[i] > lm) { lm = v[i]; li = i; }
        int gi = li * 32 + lane;
        #pragma unroll
        for (int off = 16; off > 0; off >>= 1) {
            float ov = __shfl_xor_sync(0xffffffffu, lm, off);
            int   oi = __shfl_xor_sync(0xffffffffu, gi, off);
            if (ov > lm || (ov == lm && oi < gi)) { lm = ov; gi = oi; }
        }
        top_v[it] = lm; top_i[it] = gi;
        if (lane == (gi & 31)) v[gi >> 5] = -FLT_MAX;
    }
    float w[TOPK], ssum = 0.f;
    #pragma unroll
    for (int k = 0; k < TOPK; k++) { w[k] = expf(top_v[k] - top_v[0]); ssum += w[k]; }
    float inv = 1.f / ssum;
    #pragma unroll
    for (int k = 0; k < TOPK; k++) w[k] *= inv;
    const float* recs[4] = { rQ, rK, rV, rO };
    float* outs[4] = { tQ, tK, tV, tO };
    for (int rr = 0; rr < 4; rr++) {
        const float* R = recs[rr];
        float a = 0.f;
        #pragma unroll
        for (int k = 0; k < TOPK; k++) a += w[k] * R[top_i[k] * NB + lane];
        float mx = a;
        #pragma unroll
        for (int off = 16; off > 0; off >>= 1) mx = fmaxf(mx, __shfl_xor_sync(0xffffffffu, mx, off));
        float e = expf(a - mx);
        float sm = e;
        #pragma unroll
        for (int off = 16; off > 0; off >>= 1) sm += __shfl_xor_sync(0xffffffffu, sm, off);
        outs[rr][(size_t)t * NB + lane] = e / sm;
    }
}

// ---------------- QK fused projection, fp16 mma + ldmatrix ------------------
// SMEM: [Xs][B ring][trQs][trKs]
__global__ __launch_bounds__(256) void qk_mma(
        const __half* __restrict__ Xh, const __half* __restrict__ Bt,
        const float* __restrict__ trQ, const float* __restrict__ trK,
        float* __restrict__ Qo, float* __restrict__ Ko) {
    extern __shared__ __half smh[];
    __half* Xs = smh;                        // [128][XRH]
    __half* Bs = smh + BM * XRH;             // [NSTG][64][BRH]
    float* trQs = (float*)(smh + BM * XRH + NSTG * 64 * BRH);   // [128][WROW]
    float* trKs = trQs + BM * WROW;
    const uint32_t xsb = (uint32_t)__cvta_generic_to_shared(Xs);
    const uint32_t bsb = (uint32_t)__cvta_generic_to_shared(Bs);
    const int tid = threadIdx.x;
    const int m0 = blockIdx.y * BM, r0 = blockIdx.x * BN;
    const int w = tid >> 5, lane = tid & 31;
    const int wm = (w >> 1) * 32, wn = (w & 1) * 32;
    const int g = lane >> 2, tg = lane & 3;
    float accQ[2][4][4] = {}, accK[2][4][4] = {}, accT[2][4][4] = {};

    // stage routing weights to SMEM once
    #pragma unroll
    for (int i = 0; i < BM * NB / 256; i++) {
        int e = tid + i * 256;
        int row = e >> 5, c = e & 31;
        trQs[row * WROW + c] = trQ[(size_t)(m0 + row) * NB + c];
        trKs[row * WROW + c] = trK[(size_t)(m0 + row) * NB + c];
    }

    const int br = tid >> 2, bc = tid & 3;
    const uint32_t xA0 = xsb + (uint32_t)(((wm + (lane & 15)) * XRH + (lane >> 4) * 8) * 2);
    const uint32_t xA1 = xA0 + (uint32_t)(16 * XRH * 2);
    const uint32_t bInv = (uint32_t)(((wn + (lane & 7) + 8 * (lane >> 4)) * BRH
                                      + ((lane >> 3) & 1) * 8) * 2);

    for (int kp = 0; kp < Dm / KP; kp++) {
        __syncthreads();
        {   // X panel
            const __half* Xg = Xh + (size_t)m0 * Dm + kp * KP;
            #pragma unroll
            for (int i = 0; i < 8; i++) {
                int rr = (tid >> 4) + i * 16, cc = tid & 15;
                CP_ASYNC16(xsb + (uint32_t)(rr * XRH + cc * 8) * 2,
                           Xg + (size_t)rr * Dm + cc * 8);
            }
        }
        auto stageB = [&](int s2) {
            const int j = s2 % NSTG, n = s2 >> 2, ks = s2 & 3;
            CP_ASYNC16(bsb + (uint32_t)((j * 64 + br) * BRH + bc * 8) * 2,
                       Bt + ((size_t)n * RK + r0 + br) * Dm + kp * KP + ks * 32 + bc * 8);
        };
        stageB(0); CP_COMMIT;
        stageB(1); CP_COMMIT;
        stageB(2); CP_COMMIT;
        stageB(3); CP_COMMIT;
        stageB(4); CP_COMMIT;
        for (int s = 0; s < 128; s++) {
            if (s + 5 < 128) { asm volatile("cp.async.wait_group 4;"); }
            else             { asm volatile("cp.async.wait_group 0;"); }
            __syncthreads();
            const uint32_t bB = bsb + (uint32_t)((s % NSTG) * (64 * BRH) * 2);
            const int kb = (s & 3) * 32;
            #pragma unroll
            for (int seg = 0; seg < 32; seg += 16) {
                unsigned aa[2][4], bb[4][2];
                const int kc0 = kb + seg;
                LDSM_X4(aa[0][0], aa[0][1], aa[0][2], aa[0][3], xA0 + kc0 * 2);
                LDSM_X4(aa[1][0], aa[1][1], aa[1][2], aa[1][3], xA1 + kc0 * 2);
                LDSM_X4(bb[0][0], bb[0][1], bb[1][0], bb[1][1], bB + bInv + seg * 2);
                LDSM_X4(bb[2][0], bb[2][1], bb[3][0], bb[3][1],
                        bB + bInv + (uint32_t)(16 * BRH * 2) + seg * 2);
                #pragma unroll
                for (int mf = 0; mf < 2; mf++)
                    #pragma unroll
                    for (int j = 0; j < 4; j++) mma_f16(accT[mf][j], aa[mf], bb[j]);
            }
            if ((s & 3) == 3) {
                const int n = s >> 2;
                #pragma unroll
                for (int mf = 0; mf < 2; mf++) {
                    const int rL = wm + mf * 16 + g;
                    float wq0 = trQs[rL * WROW + n];
                    float wq8 = trQs[(rL + 8) * WROW + n];
                    float wk0 = trKs[rL * WROW + n];
                    float wk8 = trKs[(rL + 8) * WROW + n];
                    #pragma unroll
                    for (int j = 0; j < 4; j++) {
                        accQ[mf][j][0] += wq0 * accT[mf][j][0];
                        accQ[mf][j][1] += wq0 * accT[mf][j][1];
                        accQ[mf][j][2] += wq8 * accT[mf][j][2];
                        accQ[mf][j][3] += wq8 * accT[mf][j][3];
                        accK[mf][j][0] += wk0 * accT[mf][j][0];
                        accK[mf][j][1] += wk0 * accT[mf][j][1];
                        accK[mf][j][2] += wk8 * accT[mf][j][2];
                        accK[mf][j][3] += wk8 * accT[mf][j][3];
                        accT[mf][j][0] = 0.f; accT[mf][j][1] = 0.f;
                        accT[mf][j][2] = 0.f; accT[mf][j][3] = 0.f;
                    }
                }
            }
            if (s + 5 < 128) { stageB(s + 5); CP_COMMIT; }
        }
    }
    #pragma unroll
    for (int mf = 0; mf < 2; mf++)
        #pragma unroll
        for (int j = 0; j < 4; j++) {
            const int row = m0 + wm + mf * 16 + g;
            const int col = r0 + wn + j * 8 + tg * 2;
            *(float2*)(Qo + (size_t)row * RK + col)       = make_float2(accQ[mf][j][0], accQ[mf][j][1]);
            *(float2*)(Qo + (size_t)(row + 8) * RK + col) = make_float2(accQ[mf][j][2], accQ[mf][j][3]);
            *(float2*)(Ko + (size_t)row * RK + col)       = make_float2(accK[mf][j][0], accK[mf][j][1]);
            *(float2*)(Ko + (size_t)(row + 8) * RK + col) = make_float2(accK[mf][j][2], accK[mf][j][3]);
        }
}

// ---------------- V projection, fp16 mma + ldmatrix --------------------------
__global__ __launch_bounds__(256) void v_mma(
        const __half* __restrict__ Xh, const __half* __restrict__ Bt,
        const float* __restrict__ trV, float* __restrict__ Vo) {
    extern __shared__ __half smh[];
    __half* Xs = smh;
    __half* Bs = smh + BM * XRH;
    float* trVs = (float*)(smh + BM * XRH + NSTG * 64 * BRH);   // [128][WROW]
    const uint32_t xsb = (uint32_t)__cvta_generic_to_shared(Xs);
    const uint32_t bsb = (uint32_t)__cvta_generic_to_shared(Bs);
    const int tid = threadIdx.x;
    const int m0 = blockIdx.y * BM, r0 = blockIdx.x * BN;
    const int w = tid >> 5, lane = tid & 31;
    const int wm = (w >> 1) * 32, wn = (w & 1) * 32;
    const int g = lane >> 2, tg = lane & 3;
    float accV[2][4][4] = {}, accT[2][4][4] = {};

    #pragma unroll
    for (int i = 0; i < BM * NB / 256; i++) {
        int e = tid + i * 256;
        int row = e >> 5, c = e & 31;
        trVs[row * WROW + c] = trV[(size_t)(m0 + row) * NB + c];
    }

    const int br = tid >> 2, bc = tid & 3;
    const uint32_t xA0 = xsb + (uint32_t)(((wm + (lane & 15)) * XRH + (lane >> 4) * 8) * 2);
    const uint32_t xA1 = xA0 + (uint32_t)(16 * XRH * 2);
    const uint32_t bInv = (uint32_t)(((wn + (lane & 7) + 8 * (lane >> 4)) * BRH
                                      + ((lane >> 3) & 1) * 8) * 2);

    for (int kp = 0; kp < Dm / KP; kp++) {
        __syncthreads();
        {
            const __half* Xg = Xh + (size_t)m0 * Dm + kp * KP;
            #pragma unroll
            for (int i = 0; i < 8; i++) {
                int rr = (tid >> 4) + i * 16, cc = tid & 15;
                CP_ASYNC16(xsb + (uint32_t)(rr * XRH + cc * 8) * 2,
                           Xg + (size_t)rr * Dm + cc * 8);
            }
        }
        auto stageB = [&](int s2) {
            const int j = s2 % NSTG, n = s2 >> 2, ks = s2 & 3;
            CP_ASYNC16(bsb + (uint32_t)((j * 64 + br) * BRH + bc * 8) * 2,
                       Bt + ((size_t)n * RK + r0 + br) * Dm + kp * KP + ks * 32 + bc * 8);
        };
        stageB(0); CP_COMMIT;
        stageB(1); CP_COMMIT;
        stageB(2); CP_COMMIT;
        stageB(3); CP_COMMIT;
        stageB(4); CP_COMMIT;
        for (int s = 0; s < 128; s++) {
            if (s + 5 < 128) { asm volatile("cp.async.wait_group 4;"); }
            else             { asm volatile("cp.async.wait_group 0;"); }
            __syncthreads();
            const uint32_t bB = bsb + (uint32_t)((s % NSTG) * (64 * BRH) * 2);
            const int kb = (s & 3) * 32;
            #pragma unroll
            for (int seg = 0; seg < 32; seg += 16) {
                unsigned aa[2][4], bb[4][2];
                const int kc0 = kb + seg;
                LDSM_X4(aa[0][0], aa[0][1], aa[0][2], aa[0][3], xA0 + kc0 * 2);
                LDSM_X4(aa[1][0], aa[1][1], aa[1][2], aa[1][3], xA1 + kc0 * 2);
                LDSM_X4(bb[0][0], bb[0][1], bb[1][0], bb[1][1], bB + bInv + seg * 2);
                LDSM_X4(bb[2][0], bb[2][1], bb[3][0], bb[3][1],
                        bB + bInv + (uint32_t)(16 * BRH * 2) + seg * 2);
                #pragma unroll
                for (int mf = 0; mf < 2; mf++)
                    #pragma unroll
                    for (int j = 0; j < 4; j++) mma_f16(accT[mf][j], aa[mf], bb[j]);
            }
            if ((s & 3) == 3) {
                const int n = s >> 2;
                #pragma unroll
                for (int mf = 0; mf < 2; mf++) {
                    const int rL = wm + mf * 16 + g;
                    float w0 = trVs[rL * WROW + n];
                    float w8 = trVs[(rL + 8) * WROW + n];
                    #pragma unroll
                    for (int j = 0; j < 4; j++) {
                        accV[mf][j][0] += w0 * accT[mf][j][0];
                        accV[mf][j][1] += w0 * accT[mf][j][1];
                        accV[mf][j][2] += w8 * accT[mf][j][2];
                        accV[mf][j][3] += w8 * accT[mf][j][3];
                        accT[mf][j][0] = 0.f; accT[mf][j][1] = 0.f;
                        accT[mf][j][2] = 0.f; accT[mf][j][3] = 0.f;
                    }
                }
            }
            if (s + 5 < 128) { stageB(s + 5); CP_COMMIT; }
        }
    }
    #pragma unroll
    for (int mf = 0; mf < 2; mf++)
        #pragma unroll
        for (int j = 0; j < 4; j++) {
            const int row = m0 + wm + mf * 16 + g;
            const int col = r0 + wn + j * 8 + tg * 2;
            *(float2*)(Vo + (size_t)row * RK + col)       = make_float2(accV[mf][j][0], accV[mf][j][1]);
            *(float2*)(Vo + (size_t)(row + 8) * RK + col) = make_float2(accV[mf][j][2], accV[mf][j][3]);
        }
}

// ---------------- causal attention (lane=key layout) ------------------------
__global__ void attn_kernel(const float* __restrict__ Q, const float* __restrict__ Km,
                            const float* __restrict__ V, float* __restrict__ ctx) {
    __shared__ float Ks[64][33];
    __shared__ float Vs[64][33];
    const int bh = blockIdx.x;
    const int b = bh >> 4, h = bh & 15;
    const int warp = threadIdx.x >> 5, lane = threadIdx.x & 31;
    const int q = blockIdx.y * 8 + warp;
    const size_t tq = (size_t)b * Ssz + q;
    const float scale = 0.17677669529663688f;
    const float qd = Q[tq * RK + h * DH + lane] * scale;
    float qr[32];
    #pragma unroll
    for (int d = 0; d < 32; d++) qr[d] = __shfl_sync(0xffffffffu, qd, d);
    float m = -1e30f, l = 0.f, acc = 0.f;
    const int qmax = blockIdx.y * 8 + 7;
    for (int k0 = 0; k0 <= qmax; k0 += 64) {
        __syncthreads();
        #pragma unroll
        for (int p = 0; p < 8; p++) {
            int e = threadIdx.x + p * 256;
            int r = e >> 5, c = e & 31;
            size_t tk = ((size_t)b * Ssz + k0 + r) * RK + h * DH + c;
            Ks[r][c] = Km[tk];
            Vs[r][c] = V[tk];
        }
        __syncthreads();
        #pragma unroll
        for (int j0 = 0; j0 < 64; j0 += 32) {
            if (k0 + j0 > q) break;
            const int kidx = k0 + j0 + lane;
            float sv = 0.f;
            #pragma unroll
            for (int d = 0; d < 32; d++) sv += qr[d] * Ks[j0 + lane][d];
            if (kidx > q) sv = -1e30f;
            float mx = sv;
            #pragma unroll
            for (int off = 16; off > 0; off >>= 1)
                mx = fmaxf(mx, __shfl_xor_sync(0xffffffffu, mx, off));
            const float mn = fmaxf(m, mx);
            const float p = __expf(sv - mn);
            float sum = p;
            #pragma unroll
            for (int off = 16; off > 0; off >>= 1)
                sum += __shfl_xor_sync(0xffffffffu, sum, off);
            const float cr = __expf(m - mn);
            l = l * cr + sum;
            float a2 = 0.f;
            #pragma unroll
            for (int j = 0; j < 32; j++)
                a2 += __shfl_sync(0xffffffffu, p, j) * Vs[j0 + j][lane];
            acc = acc * cr + a2;
            m = mn;
        }
    }
    ctx[tq * RK + h * DH + lane] = acc / l;
}

// ---------------- O projection, fp16 mma + ldmatrix (resident ctx panel) ----
// SMEM: [trOs][ctxs][A ring][B ring]
__global__ __launch_bounds__(256) void o_mma(
        const float* __restrict__ Cx, const __half* __restrict__ BvN,
        const float* __restrict__ trO, float* __restrict__ Out) {
    extern __shared__ __half smh[];
    float*  trOs = (float*)smh;                                  // [128][WROW]
    float*  ctxs = trOs + BM * WROW;                             // [128][CTXW]
    __half* Ah   = (__half*)(ctxs + BM * CTXW);                  // [NSTG][128][BRH]
    __half* Bh   = Ah + NSTG * BM * BRH;                         // [NSTG][64][BRH]
    const uint32_t ctxb = (uint32_t)__cvta_generic_to_shared(ctxs);
    const uint32_t asb  = (uint32_t)__cvta_generic_to_shared(Ah);
    const uint32_t bsb  = (uint32_t)__cvta_generic_to_shared(Bh);
    const int tid = threadIdx.x;
    const int m0 = blockIdx.y * BM, d0 = blockIdx.x * BN;
    const int w = tid >> 5, lane = tid & 31;
    const int wm = (w >> 1) * 32, wn = (w & 1) * 32;
    const int g = lane >> 2, tg = lane & 3;
    float accO[2][4][4] = {};
    const int br = tid >> 2, bc = tid & 3;
    const uint32_t aInv = (uint32_t)(((wm + (lane & 15)) * BRH + (lane >> 4) * 8) * 2);
    const uint32_t bInv = (uint32_t)(((wn + (lane & 7) + 8 * (lane >> 4)) * BRH
                                      + ((lane >> 3) & 1) * 8) * 2);

    #pragma unroll
    for (int i = 0; i < BM * NB / 256; i++) {
        int e = tid + i * 256;
        int row = e >> 5, c = e & 31;
        trOs[row * WROW + c] = trO[(size_t)(m0 + row) * NB + c];
    }

    for (int kp = 0; kp < RK / KP; kp++) {   // 4 panels over r
        __syncthreads();
        {   // ctx panel fp32 [128][128]
            #pragma unroll
            for (int i = 0; i < 16; i++) {
                int idx = tid + i * 256;
                int rr = idx >> 5, cc = idx & 31;
                CP_ASYNC16(ctxb + (uint32_t)(rr * CTXW + cc * 4) * 4,
                           Cx + (size_t)(m0 + rr) * RK + kp * KP + cc * 4);
            }
            CP_COMMIT;
            asm volatile("cp.async.wait_group 0;");
            __syncthreads();
        }
        auto stageA = [&](int s2) {
            const int j = s2 % NSTG, n = s2 >> 2, ks = s2 & 3;
            const int row = tid >> 1, off = (tid & 1) * 16;
            const float wv = trOs[row * WROW + n];
            const float* cr = ctxs + row * CTXW + ks * 32 + off;
            __half* dst = Ah + (j * BM + row) * BRH + off;
            #pragma unroll
            for (int q2 = 0; q2 < 2; q2++) {
                float4 v0 = *(const float4*)(cr + q2 * 8);
                float4 v1 = *(const float4*)(cr + q2 * 8 + 4);
                __half2 h0 = __floats2half2_rn(wv * v0.x, wv * v0.y);
                __half2 h1 = __floats2half2_rn(wv * v0.z, wv * v0.w);
                __half2 h2 = __floats2half2_rn(wv * v1.x, wv * v1.y);
                __half2 h3 = __floats2half2_rn(wv * v1.z, wv * v1.w);
                uint32_t da = (uint32_t)__cvta_generic_to_shared(dst + q2 * 8);
                STS128(da, h2u(h0), h2u(h1), h2u(h2), h2u(h3));
            }
        };
        auto stageB = [&](int s2) {
            const int j = s2 % NSTG, n = s2 >> 2, ks = s2 & 3;
            CP_ASYNC16(bsb + (uint32_t)((j * 64 + br) * BRH + bc * 8) * 2,
                       BvN + ((size_t)n * Dm + d0 + br) * RK + kp * KP + ks * 32 + bc * 8);
        };
        stageA(0); stageB(0); CP_COMMIT;
        stageA(1); stageB(1); CP_COMMIT;
        stageA(2); stageB(2); CP_COMMIT;
        stageA(3); stageB(3); CP_COMMIT;
        stageA(4); stageB(4); CP_COMMIT;
        for (int s = 0; s < 128; s++) {
            if (s + 5 < 128) { asm volatile("cp.async.wait_group 4;"); }
            else             { asm volatile("cp.async.wait_group 0;"); }
            __syncthreads();
            const uint32_t aB = asb + (uint32_t)((s % NSTG) * (BM * BRH) * 2);
            const uint32_t bB = bsb + (uint32_t)((s % NSTG) * (64 * BRH) * 2);
            #pragma unroll
            for (int seg = 0; seg < 32; seg += 16) {
                unsigned aa[2][4], bb[4][2];
                LDSM_X4(aa[0][0], aa[0][1], aa[0][2], aa[0][3], aB + aInv + seg * 2);
                LDSM_X4(aa[1][0], aa[1][1], aa[1][2], aa[1][3],
                        aB + aInv + (uint32_t)(16 * BRH * 2) + seg * 2);
                LDSM_X4(bb[0][0], bb[0][1], bb[1][0], bb[1][1], bB + bInv + seg * 2);
                LDSM_X4(bb[2][0], bb[2][1], bb[3][0], bb[3][1],
                        bB + bInv + (uint32_t)(16 * BRH * 2) + seg * 2);
                #pragma unroll
                for (int mf = 0; mf < 2; mf++)
                    #pragma unroll
                    for (int j = 0; j < 4; j++) mma_f16(accO[mf][j], aa[mf], bb[j]);
            }
            if (s + 5 < 128) { stageA(s + 5); stageB(s + 5); CP_COMMIT; }
        }
    }
    #pragma unroll
    for (int mf = 0; mf < 2; mf++)
        #pragma unroll
        for (int j = 0; j < 4; j++) {
            const int row = m0 + wm + mf * 16 + g;
            const int col = d0 + wn + j * 8 + tg * 2;
            *(float2*)(Out + (size_t)row * Dm + col)       = make_float2(accO[mf][j][0], accO[mf][j][1]);
            *(float2*)(Out + (size_t)(row + 8) * Dm + col) = make_float2(accO[mf][j][2], accO[mf][j][3]);
        }
}

// ---------------- launch ----------------------------------------------------
extern "C" void kernel_launch(void* const* d_in, const int* in_sizes, int n_in,
                              void* d_out, int out_size) {
    const float* x        = (const float*)d_in[0];
    const float* W_router = (const float*)d_in[1];
    const float* recipe_Q = (const float*)d_in[2];
    const float* recipe_K = (const float*)d_in[3];
    const float* recipe_V = (const float*)d_in[4];
    const float* recipe_O = (const float*)d_in[5];
    const float* basis_qk = (const float*)d_in[6];
    const float* basis_vo = (const float*)d_in[7];
    float* out = (float*)d_out;

    float *scores, *tQ, *tK, *tV, *tO, *Qp, *Kp, *Vp, *ctx;
    __half *xh, *bqkT, *bvoT, *bvoN;
    cudaGetSymbolAddress((void**)&scores, g_scores);
    cudaGetSymbolAddress((void**)&tQ, g_trQ);
    cudaGetSymbolAddress((void**)&tK, g_trK);
    cudaGetSymbolAddress((void**)&tV, g_trV);
    cudaGetSymbolAddress((void**)&tO, g_trO);
    cudaGetSymbolAddress((void**)&Qp, g_Q);
    cudaGetSymbolAddress((void**)&Kp, g_Km);
    cudaGetSymbolAddress((void**)&Vp, g_V);
    cudaGetSymbolAddress((void**)&ctx, g_ctx);
    cudaGetSymbolAddress((void**)&xh, g_xh);
    cudaGetSymbolAddress((void**)&bqkT, g_bqkT);
    cudaGetSymbolAddress((void**)&bvoT, g_bvoT);
    cudaGetSymbolAddress((void**)&bvoN, g_bvoN);

    const int QK_SMEM = (BM * XRH + NSTG * 64 * BRH) * 2 + 2 * BM * WROW * 4;   // 99328
    const int V_SMEM  = (BM * XRH + NSTG * 64 * BRH) * 2 + BM * WROW * 4;       // 82432
    const int O_SMEM  = BM * WROW * 4 + BM * CTXW * 4
                      + (NSTG * BM * BRH + NSTG * 64 * BRH) * 2;                // 176640
    cudaFuncSetAttribute(qk_mma, cudaFuncAttributeMaxDynamicSharedMemorySize, QK_SMEM);
    cudaFuncSetAttribute(v_mma,  cudaFuncAttributeMaxDynamicSharedMemorySize, V_SMEM);
    cudaFuncSetAttribute(o_mma,  cudaFuncAttributeMaxDynamicSharedMemorySize, O_SMEM);

    // launch order chosen so qk_mma is launch #6 (ncu -s 5 -c 1 capture slot)
    cvt_half_kernel<<<1024, 256>>>((const float4*)x, (uint2*)xh, NT * Dm / 4);          // 1
    trans_cvt_h<<<dim3(RK / 32, Dm / 32, NB), dim3(32, 8)>>>(basis_qk, bqkT);           // 2
    router_gemm<<<dim3(NN / 64, NT / 64), 256>>>(x, W_router, scores);                  // 3
    route_kernel<<<NT, 32>>>(scores, recipe_Q, recipe_K, recipe_V, recipe_O,
                             tQ, tK, tV, tO);                                           // 4
    trans_cvt_dual<<<dim3(RK / 32, Dm / 32, NB), dim3(32, 8)>>>(basis_vo, bvoT, bvoN);  // 5
    qk_mma<<<dim3(RK / BN, NT / BM), 256, QK_SMEM>>>(xh, bqkT, tQ, tK, Qp, Kp);         // 6 <- profiled
    v_mma<<<dim3(RK / BN, NT / BM), 256, V_SMEM>>>(xh, bvoT, tV, Vp);                   // 7
    attn_kernel<<<dim3(Bsz * NH, Ssz / 8), 256>>>(Qp, Kp, Vp, ctx);                     // 8
    o_mma<<<dim3(Dm / BN, NT / BM), 256, O_SMEM>>>(ctx, bvoN, tO, out);                 // 9
}

// round 12
// speedup vs baseline: 7.8515x; 1.0711x over previous
#include <cuda_runtime.h>
#include <cuda_fp16.h>
#include <cfloat>
#include <cstdint>

#define Bsz 4
#define Ssz 1024
#define Dm  1024
#define NT  4096
#define NN  256
#define NB  32
#define RK  512
#define NH  16
#define DH  32
#define TOPK 8

// fp16 mma tiling
#define BM 128
#define BN 64
#define KP 128            // X panel width (halfs) for qk/v; floats for O ctx panel
#define XRH 136           // X panel row stride in halfs (68 words = 4 mod 32: conflict-free)
#define BRH 40            // B/A tile row stride in halfs (20 words: conflict-free)
#define CTXW 132          // O ctx panel row stride in floats
#define NSTG 6            // cp.async ring depth
#define WROW 33           // SMEM weight-tile row stride (floats)

// ---------------- scratch ---------------------------------------------------
__device__ float  g_scores[NT * NN];
__device__ float  g_trQ[NT * NB];
__device__ float  g_trK[NT * NB];
__device__ float  g_trV[NT * NB];
__device__ float  g_trO[NT * NB];
__device__ float  g_Q[NT * RK];
__device__ float  g_Km[NT * RK];
__device__ float  g_V[NT * RK];
__device__ float  g_ctx[NT * RK];
__device__ __half g_xh[NT * Dm];             // fp16 x
__device__ __half g_bqkT[NB * RK * Dm];      // fp16 basis_qk^T [n][r][d]
__device__ __half g_bvoT[NB * RK * Dm];      // fp16 basis_vo^T [n][r][d]
__device__ __half g_bvoN[NB * Dm * RK];      // fp16 basis_vo native [n][d][r]

// ---------------- helpers ---------------------------------------------------
__device__ __forceinline__ void mma_f16(float* c, const unsigned* a, const unsigned* b) {
    asm volatile("mma.sync.aligned.m16n8k16.row.col.f32.f16.f16.f32 "
        "{%0,%1,%2,%3}, {%4,%5,%6,%7}, {%8,%9}, {%0,%1,%2,%3};"
        : "+f"(c[0]), "+f"(c[1]), "+f"(c[2]), "+f"(c[3])
        : "r"(a[0]), "r"(a[1]), "r"(a[2]), "r"(a[3]), "r"(b[0]), "r"(b[1]));
}
#define CP_ASYNC16(dst, src) \
    asm volatile("cp.async.cg.shared.global [%0], [%1], 16;" :: "r"(dst), "l"(src))
#define CP_COMMIT asm volatile("cp.async.commit_group;")
#define STS128(a, r0, r1, r2, r3) \
    asm volatile("st.shared.v4.b32 [%0], {%1, %2, %3, %4};" \
                 :: "r"(a), "r"(r0), "r"(r1), "r"(r2), "r"(r3) : "memory")
#define LDSM_X4(r0, r1, r2, r3, a) \
    asm volatile("ldmatrix.sync.aligned.m8n8.x4.shared.b16 {%0, %1, %2, %3}, [%4];" \
        : "=r"(r0), "=r"(r1), "=r"(r2), "=r"(r3) : "r"(a))
__device__ __forceinline__ unsigned h2u(__half2 h) { return *reinterpret_cast<unsigned*>(&h); }

// ---------------- preprocessing ---------------------------------------------
__global__ void cvt_half_kernel(const float4* __restrict__ s, uint2* __restrict__ d, int n4) {
    for (int i = blockIdx.x * blockDim.x + threadIdx.x; i < n4; i += gridDim.x * blockDim.x) {
        float4 v = s[i];
        __half2 h0 = __floats2half2_rn(v.x, v.y);
        __half2 h1 = __floats2half2_rn(v.z, v.w);
        d[i] = make_uint2(h2u(h0), h2u(h1));
    }
}
// [n][1024 d][512 r] fp32 -> [n][512 r][1024 d] fp16
__global__ void trans_cvt_h(const float* __restrict__ in, __half* __restrict__ out) {
    __shared__ float tile[32][33];
    const int n = blockIdx.z;
    const int d0 = blockIdx.y * 32, r0 = blockIdx.x * 32;
    const float* src = in + (size_t)n * Dm * RK;
    __half* dst = out + (size_t)n * RK * Dm;
    const int tx = threadIdx.x, ty = threadIdx.y;
    #pragma unroll
    for (int i = 0; i < 4; i++)
        tile[ty + i * 8][tx] = src[(size_t)(d0 + ty + i * 8) * RK + r0 + tx];
    __syncthreads();
    #pragma unroll
    for (int i = 0; i < 4; i++)
        dst[(size_t)(r0 + ty + i * 8) * Dm + d0 + tx] = __float2half(tile[tx][ty + i * 8]);
}
// basis_vo: produce BOTH bvoT (transposed) and bvoN (native) fp16 in one pass
__global__ void trans_cvt_dual(const float* __restrict__ in, __half* __restrict__ outT,
                               __half* __restrict__ outN) {
    __shared__ float tile[32][33];
    const int n = blockIdx.z;
    const int d0 = blockIdx.y * 32, r0 = blockIdx.x * 32;
    const float* src = in + (size_t)n * Dm * RK;
    __half* dstT = outT + (size_t)n * RK * Dm;
    __half* dstN = outN + (size_t)n * Dm * RK;
    const int tx = threadIdx.x, ty = threadIdx.y;
    #pragma unroll
    for (int i = 0; i < 4; i++) {
        float v = src[(size_t)(d0 + ty + i * 8) * RK + r0 + tx];
        tile[ty + i * 8][tx] = v;
        dstN[(size_t)(d0 + ty + i * 8) * RK + r0 + tx] = __float2half(v);
    }
    __syncthreads();
    #pragma unroll
    for (int i = 0; i < 4; i++)
        dstT[(size_t)(r0 + ty + i * 8) * Dm + d0 + tx] = __float2half(tile[tx][ty + i * 8]);
}

// ---------------- router GEMM (fp32 SIMT, cp.async double-buffered) ---------
__global__ __launch_bounds__(256) void router_gemm(const float* __restrict__ A,
                                                   const float* __restrict__ Bw,
                                                   float* __restrict__ C) {
    __shared__ float As[2][64][20];
    __shared__ float Bs[2][16][68];
    const int tid = threadIdx.x;
    const int tx = tid & 15, ty = tid >> 4;
    const int m0 = blockIdx.y * 64, n0 = blockIdx.x * 64;
    const uint32_t asb = (uint32_t)__cvta_generic_to_shared(&As[0][0][0]);
    const uint32_t bsb = (uint32_t)__cvta_generic_to_shared(&Bs[0][0][0]);
    const int ar = tid >> 2, ac = (tid & 3) * 4;
    const int brr = tid >> 4, bcc = (tid & 15) * 4;
    float acc[4][4] = {};
    auto load = [&](int kt, int buf) {
        CP_ASYNC16(asb + (uint32_t)((buf * 64 * 20 + ar * 20 + ac) * 4),
                   A + (size_t)(m0 + ar) * Dm + kt * 16 + ac);
        CP_ASYNC16(bsb + (uint32_t)((buf * 16 * 68 + brr * 68 + bcc) * 4),
                   Bw + (size_t)(kt * 16 + brr) * NN + n0 + bcc);
    };
    load(0, 0); CP_COMMIT;
    for (int kt = 0; kt < Dm / 16; kt++) {
        const int buf = kt & 1;
        if (kt + 1 < Dm / 16) {
            load(kt + 1, buf ^ 1); CP_COMMIT;
            asm volatile("cp.async.wait_group 1;");
        } else {
            asm volatile("cp.async.wait_group 0;");
        }
        __syncthreads();
        #pragma unroll
        for (int kk = 0; kk < 16; kk++) {
            float4 bv = *(const float4*)&Bs[buf][kk][tx * 4];
            float a0 = As[buf][ty * 4 + 0][kk];
            float a1 = As[buf][ty * 4 + 1][kk];
            float a2 = As[buf][ty * 4 + 2][kk];
            float a3 = As[buf][ty * 4 + 3][kk];
            acc[0][0] += a0 * bv.x; acc[0][1] += a0 * bv.y; acc[0][2] += a0 * bv.z; acc[0][3] += a0 * bv.w;
            acc[1][0] += a1 * bv.x; acc[1][1] += a1 * bv.y; acc[1][2] += a1 * bv.z; acc[1][3] += a1 * bv.w;
            acc[2][0] += a2 * bv.x; acc[2][1] += a2 * bv.y; acc[2][2] += a2 * bv.z; acc[2][3] += a2 * bv.w;
            acc[3][0] += a3 * bv.x; acc[3][1] += a3 * bv.y; acc[3][2] += a3 * bv.z; acc[3][3] += a3 * bv.w;
        }
        __syncthreads();
    }
    #pragma unroll
    for (int i = 0; i < 4; i++)
        *(float4*)&C[(size_t)(m0 + ty * 4 + i) * NN + n0 + tx * 4] =
            make_float4(acc[i][0], acc[i][1], acc[i][2], acc[i][3]);
}

// ---------------- routing ----------------------------------------------------
__global__ void route_kernel(const float* __restrict__ scores,
                             const float* __restrict__ rQ, const float* __restrict__ rK,
                             const float* __restrict__ rV, const float* __restrict__ rO,
                             float* __restrict__ tQ, float* __restrict__ tK,
                             float* __restrict__ tV, float* __restrict__ tO) {
    const int t = blockIdx.x;
    const int lane = threadIdx.x;
    const float* s = scores + (size_t)t * NN;
    float v[8];
    #pragma unroll
    for (int i = 0; i < 8; i++) v[i] = s[i * 32 + lane];
    float top_v[TOPK];
    int   top_i[TOPK];
    for (int it = 0; it < TOPK; it++) {
        float lm = -FLT_MAX; int li = 0;
        #pragma unroll
        for (int i = 0; i < 8; i++) if (v[i] > lm) { lm = v[i]; li = i; }
        int gi = li * 32 + lane;
        #pragma unroll
        for (int off = 16; off > 0; off >>= 1) {
            float ov = __shfl_xor_sync(0xffffffffu, lm, off);
            int   oi = __shfl_xor_sync(0xffffffffu, gi, off);
            if (ov > lm || (ov == lm && oi < gi)) { lm = ov; gi = oi; }
        }
        top_v[it] = lm; top_i[it] = gi;
        if (lane == (gi & 31)) v[gi >> 5] = -FLT_MAX;
    }
    float w[TOPK], ssum = 0.f;
    #pragma unroll
    for (int k = 0; k < TOPK; k++) { w[k] = expf(top_v[k] - top_v[0]); ssum += w[k]; }
    float inv = 1.f / ssum;
    #pragma unroll
    for (int k = 0; k < TOPK; k++) w[k] *= inv;
    const float* recs[4] = { rQ, rK, rV, rO };
    float* outs[4] = { tQ, tK, tV, tO };
    for (int rr = 0; rr < 4; rr++) {
        const float* R = recs[rr];
        float a = 0.f;
        #pragma unroll
        for (int k = 0; k < TOPK; k++) a += w[k] * R[top_i[k] * NB + lane];
        float mx = a;
        #pragma unroll
        for (int off = 16; off > 0; off >>= 1) mx = fmaxf(mx, __shfl_xor_sync(0xffffffffu, mx, off));
        float e = expf(a - mx);
        float sm = e;
        #pragma unroll
        for (int off = 16; off > 0; off >>= 1) sm += __shfl_xor_sync(0xffffffffu, sm, off);
        outs[rr][(size_t)t * NB + lane] = e / sm;
    }
}

// ---------------- QK fused projection, fp16 mma + ldmatrix ------------------
// stage-pair mainloop: one wait_group+syncthreads per 64 k-values
__global__ __launch_bounds__(256) void qk_mma(
        const __half* __restrict__ Xh, const __half* __restrict__ Bt,
        const float* __restrict__ trQ, const float* __restrict__ trK,
        float* __restrict__ Qo, float* __restrict__ Ko) {
    extern __shared__ __half smh[];
    __half* Xs = smh;                        // [128][XRH]
    __half* Bs = smh + BM * XRH;             // [NSTG][64][BRH]
    float* trQs = (float*)(smh + BM * XRH + NSTG * 64 * BRH);   // [128][WROW]
    float* trKs = trQs + BM * WROW;
    const uint32_t xsb = (uint32_t)__cvta_generic_to_shared(Xs);
    const uint32_t bsb = (uint32_t)__cvta_generic_to_shared(Bs);
    const int tid = threadIdx.x;
    const int m0 = blockIdx.y * BM, r0 = blockIdx.x * BN;
    const int w = tid >> 5, lane = tid & 31;
    const int wm = (w >> 1) * 32, wn = (w & 1) * 32;
    const int g = lane >> 2, tg = lane & 3;
    float accQ[2][4][4] = {}, accK[2][4][4] = {}, accT[2][4][4] = {};

    // stage routing weights to SMEM once
    #pragma unroll
    for (int i = 0; i < BM * NB / 256; i++) {
        int e = tid + i * 256;
        int row = e >> 5, c = e & 31;
        trQs[row * WROW + c] = trQ[(size_t)(m0 + row) * NB + c];
        trKs[row * WROW + c] = trK[(size_t)(m0 + row) * NB + c];
    }

    const int br = tid >> 2, bc = tid & 3;
    const uint32_t xA0 = xsb + (uint32_t)(((wm + (lane & 15)) * XRH + (lane >> 4) * 8) * 2);
    const uint32_t xA1 = xA0 + (uint32_t)(16 * XRH * 2);
    const uint32_t bInv = (uint32_t)(((wn + (lane & 7) + 8 * (lane >> 4)) * BRH
                                      + ((lane >> 3) & 1) * 8) * 2);

    for (int kp = 0; kp < Dm / KP; kp++) {
        __syncthreads();   // guard X panel reuse
        {   // X panel
            const __half* Xg = Xh + (size_t)m0 * Dm + kp * KP;
            #pragma unroll
            for (int i = 0; i < 8; i++) {
                int rr = (tid >> 4) + i * 16, cc = tid & 15;
                CP_ASYNC16(xsb + (uint32_t)(rr * XRH + cc * 8) * 2,
                           Xg + (size_t)rr * Dm + cc * 8);
            }
        }
        auto stageB = [&](int s2) {
            const int j = s2 % NSTG, n = s2 >> 2, ks = s2 & 3;
            CP_ASYNC16(bsb + (uint32_t)((j * 64 + br) * BRH + bc * 8) * 2,
                       Bt + ((size_t)n * RK + r0 + br) * Dm + kp * KP + ks * 32 + bc * 8);
        };
        stageB(0); CP_COMMIT;   // X joins this group
        stageB(1); CP_COMMIT;
        stageB(2); CP_COMMIT;
        stageB(3); CP_COMMIT;
        for (int s = 0; s < 128; s += 2) {
            if (s + 2 < 128) { asm volatile("cp.async.wait_group 2;"); }
            else             { asm volatile("cp.async.wait_group 0;"); }
            __syncthreads();
            if (s + 4 < 128) {
                stageB(s + 4); CP_COMMIT;
                stageB(s + 5); CP_COMMIT;
            }
            #pragma unroll
            for (int sub = 0; sub < 2; sub++) {
                const int ss = s + sub;
                const uint32_t bB = bsb + (uint32_t)((ss % NSTG) * (64 * BRH) * 2);
                const int kb = (ss & 3) * 32;
                #pragma unroll
                for (int seg = 0; seg < 32; seg += 16) {
                    unsigned aa[2][4], bb[4][2];
                    const int kc0 = kb + seg;
                    LDSM_X4(aa[0][0], aa[0][1], aa[0][2], aa[0][3], xA0 + kc0 * 2);
                    LDSM_X4(aa[1][0], aa[1][1], aa[1][2], aa[1][3], xA1 + kc0 * 2);
                    LDSM_X4(bb[0][0], bb[0][1], bb[1][0], bb[1][1], bB + bInv + seg * 2);
                    LDSM_X4(bb[2][0], bb[2][1], bb[3][0], bb[3][1],
                            bB + bInv + (uint32_t)(16 * BRH * 2) + seg * 2);
                    #pragma unroll
                    for (int mf = 0; mf < 2; mf++)
                        #pragma unroll
                        for (int j = 0; j < 4; j++) mma_f16(accT[mf][j], aa[mf], bb[j]);
                }
            }
            if (((s + 1) & 3) == 3) {
                const int n = (s + 1) >> 2;
                #pragma unroll
                for (int mf = 0; mf < 2; mf++) {
                    const int rL = wm + mf * 16 + g;
                    float wq0 = trQs[rL * WROW + n];
                    float wq8 = trQs[(rL + 8) * WROW + n];
                    float wk0 = trKs[rL * WROW + n];
                    float wk8 = trKs[(rL + 8) * WROW + n];
                    #pragma unroll
                    for (int j = 0; j < 4; j++) {
                        accQ[mf][j][0] += wq0 * accT[mf][j][0];
                        accQ[mf][j][1] += wq0 * accT[mf][j][1];
                        accQ[mf][j][2] += wq8 * accT[mf][j][2];
                        accQ[mf][j][3] += wq8 * accT[mf][j][3];
                        accK[mf][j][0] += wk0 * accT[mf][j][0];
                        accK[mf][j][1] += wk0 * accT[mf][j][1];
                        accK[mf][j][2] += wk8 * accT[mf][j][2];
                        accK[mf][j][3] += wk8 * accT[mf][j][3];
                        accT[mf][j][0] = 0.f; accT[mf][j][1] = 0.f;
                        accT[mf][j][2] = 0.f; accT[mf][j][3] = 0.f;
                    }
                }
            }
        }
    }
    #pragma unroll
    for (int mf = 0; mf < 2; mf++)
        #pragma unroll
        for (int j = 0; j < 4; j++) {
            const int row = m0 + wm + mf * 16 + g;
            const int col = r0 + wn + j * 8 + tg * 2;
            *(float2*)(Qo + (size_t)row * RK + col)       = make_float2(accQ[mf][j][0], accQ[mf][j][1]);
            *(float2*)(Qo + (size_t)(row + 8) * RK + col) = make_float2(accQ[mf][j][2], accQ[mf][j][3]);
            *(float2*)(Ko + (size_t)row * RK + col)       = make_float2(accK[mf][j][0], accK[mf][j][1]);
            *(float2*)(Ko + (size_t)(row + 8) * RK + col) = make_float2(accK[mf][j][2], accK[mf][j][3]);
        }
}

// ---------------- V projection, fp16 mma + ldmatrix (stage pairs) ------------
__global__ __launch_bounds__(256) void v_mma(
        const __half* __restrict__ Xh, const __half* __restrict__ Bt,
        const float* __restrict__ trV, float* __restrict__ Vo) {
    extern __shared__ __half smh[];
    __half* Xs = smh;
    __half* Bs = smh + BM * XRH;
    float* trVs = (float*)(smh + BM * XRH + NSTG * 64 * BRH);   // [128][WROW]
    const uint32_t xsb = (uint32_t)__cvta_generic_to_shared(Xs);
    const uint32_t bsb = (uint32_t)__cvta_generic_to_shared(Bs);
    const int tid = threadIdx.x;
    const int m0 = blockIdx.y * BM, r0 = blockIdx.x * BN;
    const int w = tid >> 5, lane = tid & 31;
    const int wm = (w >> 1) * 32, wn = (w & 1) * 32;
    const int g = lane >> 2, tg = lane & 3;
    float accV[2][4][4] = {}, accT[2][4][4] = {};

    #pragma unroll
    for (int i = 0; i < BM * NB / 256; i++) {
        int e = tid + i * 256;
        int row = e >> 5, c = e & 31;
        trVs[row * WROW + c] = trV[(size_t)(m0 + row) * NB + c];
    }

    const int br = tid >> 2, bc = tid & 3;
    const uint32_t xA0 = xsb + (uint32_t)(((wm + (lane & 15)) * XRH + (lane >> 4) * 8) * 2);
    const uint32_t xA1 = xA0 + (uint32_t)(16 * XRH * 2);
    const uint32_t bInv = (uint32_t)(((wn + (lane & 7) + 8 * (lane >> 4)) * BRH
                                      + ((lane >> 3) & 1) * 8) * 2);

    for (int kp = 0; kp < Dm / KP; kp++) {
        __syncthreads();
        {
            const __half* Xg = Xh + (size_t)m0 * Dm + kp * KP;
            #pragma unroll
            for (int i = 0; i < 8; i++) {
                int rr = (tid >> 4) + i * 16, cc = tid & 15;
                CP_ASYNC16(xsb + (uint32_t)(rr * XRH + cc * 8) * 2,
                           Xg + (size_t)rr * Dm + cc * 8);
            }
        }
        auto stageB = [&](int s2) {
            const int j = s2 % NSTG, n = s2 >> 2, ks = s2 & 3;
            CP_ASYNC16(bsb + (uint32_t)((j * 64 + br) * BRH + bc * 8) * 2,
                       Bt + ((size_t)n * RK + r0 + br) * Dm + kp * KP + ks * 32 + bc * 8);
        };
        stageB(0); CP_COMMIT;
        stageB(1); CP_COMMIT;
        stageB(2); CP_COMMIT;
        stageB(3); CP_COMMIT;
        for (int s = 0; s < 128; s += 2) {
            if (s + 2 < 128) { asm volatile("cp.async.wait_group 2;"); }
            else             { asm volatile("cp.async.wait_group 0;"); }
            __syncthreads();
            if (s + 4 < 128) {
                stageB(s + 4); CP_COMMIT;
                stageB(s + 5); CP_COMMIT;
            }
            #pragma unroll
            for (int sub = 0; sub < 2; sub++) {
                const int ss = s + sub;
                const uint32_t bB = bsb + (uint32_t)((ss % NSTG) * (64 * BRH) * 2);
                const int kb = (ss & 3) * 32;
                #pragma unroll
                for (int seg = 0; seg < 32; seg += 16) {
                    unsigned aa[2][4], bb[4][2];
                    const int kc0 = kb + seg;
                    LDSM_X4(aa[0][0], aa[0][1], aa[0][2], aa[0][3], xA0 + kc0 * 2);
                    LDSM_X4(aa[1][0], aa[1][1], aa[1][2], aa[1][3], xA1 + kc0 * 2);
                    LDSM_X4(bb[0][0], bb[0][1], bb[1][0], bb[1][1], bB + bInv + seg * 2);
                    LDSM_X4(bb[2][0], bb[2][1], bb[3][0], bb[3][1],
                            bB + bInv + (uint32_t)(16 * BRH * 2) + seg * 2);
                    #pragma unroll
                    for (int mf = 0; mf < 2; mf++)
                        #pragma unroll
                        for (int j = 0; j < 4; j++) mma_f16(accT[mf][j], aa[mf], bb[j]);
                }
            }
            if (((s + 1) & 3) == 3) {
                const int n = (s + 1) >> 2;
                #pragma unroll
                for (int mf = 0; mf < 2; mf++) {
                    const int rL = wm + mf * 16 + g;
                    float w0 = trVs[rL * WROW + n];
                    float w8 = trVs[(rL + 8) * WROW + n];
                    #pragma unroll
                    for (int j = 0; j < 4; j++) {
                        accV[mf][j][0] += w0 * accT[mf][j][0];
                        accV[mf][j][1] += w0 * accT[mf][j][1];
                        accV[mf][j][2] += w8 * accT[mf][j][2];
                        accV[mf][j][3] += w8 * accT[mf][j][3];
                        accT[mf][j][0] = 0.f; accT[mf][j][1] = 0.f;
                        accT[mf][j][2] = 0.f; accT[mf][j][3] = 0.f;
                    }
                }
            }
        }
    }
    #pragma unroll
    for (int mf = 0; mf < 2; mf++)
        #pragma unroll
        for (int j = 0; j < 4; j++) {
            const int row = m0 + wm + mf * 16 + g;
            const int col = r0 + wn + j * 8 + tg * 2;
            *(float2*)(Vo + (size_t)row * RK + col)       = make_float2(accV[mf][j][0], accV[mf][j][1]);
            *(float2*)(Vo + (size_t)(row + 8) * RK + col) = make_float2(accV[mf][j][2], accV[mf][j][3]);
        }
}

// ---------------- causal attention (lane=key layout) ------------------------
__global__ void attn_kernel(const float* __restrict__ Q, const float* __restrict__ Km,
                            const float* __restrict__ V, float* __restrict__ ctx) {
    __shared__ float Ks[64][33];
    __shared__ float Vs[64][33];
    const int bh = blockIdx.x;
    const int b = bh >> 4, h = bh & 15;
    const int warp = threadIdx.x >> 5, lane = threadIdx.x & 31;
    const int q = blockIdx.y * 8 + warp;
    const size_t tq = (size_t)b * Ssz + q;
    const float scale = 0.17677669529663688f;
    const float qd = Q[tq * RK + h * DH + lane] * scale;
    float qr[32];
    #pragma unroll
    for (int d = 0; d < 32; d++) qr[d] = __shfl_sync(0xffffffffu, qd, d);
    float m = -1e30f, l = 0.f, acc = 0.f;
    const int qmax = blockIdx.y * 8 + 7;
    for (int k0 = 0; k0 <= qmax; k0 += 64) {
        __syncthreads();
        #pragma unroll
        for (int p = 0; p < 8; p++) {
            int e = threadIdx.x + p * 256;
            int r = e >> 5, c = e & 31;
            size_t tk = ((size_t)b * Ssz + k0 + r) * RK + h * DH + c;
            Ks[r][c] = Km[tk];
            Vs[r][c] = V[tk];
        }
        __syncthreads();
        #pragma unroll
        for (int j0 = 0; j0 < 64; j0 += 32) {
            if (k0 + j0 > q) break;
            const int kidx = k0 + j0 + lane;
            float sv = 0.f;
            #pragma unroll
            for (int d = 0; d < 32; d++) sv += qr[d] * Ks[j0 + lane][d];
            if (kidx > q) sv = -1e30f;
            float mx = sv;
            #pragma unroll
            for (int off = 16; off > 0; off >>= 1)
                mx = fmaxf(mx, __shfl_xor_sync(0xffffffffu, mx, off));
            const float mn = fmaxf(m, mx);
            const float p = __expf(sv - mn);
            float sum = p;
            #pragma unroll
            for (int off = 16; off > 0; off >>= 1)
                sum += __shfl_xor_sync(0xffffffffu, sum, off);
            const float cr = __expf(m - mn);
            l = l * cr + sum;
            float a2 = 0.f;
            #pragma unroll
            for (int j = 0; j < 32; j++)
                a2 += __shfl_sync(0xffffffffu, p, j) * Vs[j0 + j][lane];
            acc = acc * cr + a2;
            m = mn;
        }
    }
    ctx[tq * RK + h * DH + lane] = acc / l;
}

// ---------------- O projection, fp16 mma + ldmatrix (stage pairs) ------------
__global__ __launch_bounds__(256) void o_mma(
        const float* __restrict__ Cx, const __half* __restrict__ BvN,
        const float* __restrict__ trO, float* __restrict__ Out) {
    extern __shared__ __half smh[];
    float*  trOs = (float*)smh;                                  // [128][WROW]
    float*  ctxs = trOs + BM * WROW;                             // [128][CTXW]
    __half* Ah   = (__half*)(ctxs + BM * CTXW);                  // [NSTG][128][BRH]
    __half* Bh   = Ah + NSTG * BM * BRH;                         // [NSTG][64][BRH]
    const uint32_t ctxb = (uint32_t)__cvta_generic_to_shared(ctxs);
    const uint32_t asb  = (uint32_t)__cvta_generic_to_shared(Ah);
    const uint32_t bsb  = (uint32_t)__cvta_generic_to_shared(Bh);
    const int tid = threadIdx.x;
    const int m0 = blockIdx.y * BM, d0 = blockIdx.x * BN;
    const int w = tid >> 5, lane = tid & 31;
    const int wm = (w >> 1) * 32, wn = (w & 1) * 32;
    const int g = lane >> 2, tg = lane & 3;
    float accO[2][4][4] = {};
    const int br = tid >> 2, bc = tid & 3;
    const uint32_t aInv = (uint32_t)(((wm + (lane & 15)) * BRH + (lane >> 4) * 8) * 2);
    const uint32_t bInv = (uint32_t)(((wn + (lane & 7) + 8 * (lane >> 4)) * BRH
                                      + ((lane >> 3) & 1) * 8) * 2);

    #pragma unroll
    for (int i = 0; i < BM * NB / 256; i++) {
        int e = tid + i * 256;
        int row = e >> 5, c = e & 31;
        trOs[row * WROW + c] = trO[(size_t)(m0 + row) * NB + c];
    }

    for (int kp = 0; kp < RK / KP; kp++) {   // 4 panels over r
        __syncthreads();
        {   // ctx panel fp32 [128][128]
            #pragma unroll
            for (int i = 0; i < 16; i++) {
                int idx = tid + i * 256;
                int rr = idx >> 5, cc = idx & 31;
                CP_ASYNC16(ctxb + (uint32_t)(rr * CTXW + cc * 4) * 4,
                           Cx + (size_t)(m0 + rr) * RK + kp * KP + cc * 4);
            }
            CP_COMMIT;
            asm volatile("cp.async.wait_group 0;");
            __syncthreads();
        }
        auto stageA = [&](int s2) {
            const int j = s2 % NSTG, n = s2 >> 2, ks = s2 & 3;
            const int row = tid >> 1, off = (tid & 1) * 16;
            const float wv = trOs[row * WROW + n];
            const float* cr = ctxs + row * CTXW + ks * 32 + off;
            __half* dst = Ah + (j * BM + row) * BRH + off;
            #pragma unroll
            for (int q2 = 0; q2 < 2; q2++) {
                float4 v0 = *(const float4*)(cr + q2 * 8);
                float4 v1 = *(const float4*)(cr + q2 * 8 + 4);
                __half2 h0 = __floats2half2_rn(wv * v0.x, wv * v0.y);
                __half2 h1 = __floats2half2_rn(wv * v0.z, wv * v0.w);
                __half2 h2 = __floats2half2_rn(wv * v1.x, wv * v1.y);
                __half2 h3 = __floats2half2_rn(wv * v1.z, wv * v1.w);
                uint32_t da = (uint32_t)__cvta_generic_to_shared(dst + q2 * 8);
                STS128(da, h2u(h0), h2u(h1), h2u(h2), h2u(h3));
            }
        };
        auto stageB = [&](int s2) {
            const int j = s2 % NSTG, n = s2 >> 2, ks = s2 & 3;
            CP_ASYNC16(bsb + (uint32_t)((j * 64 + br) * BRH + bc * 8) * 2,
                       BvN + ((size_t)n * Dm + d0 + br) * RK + kp * KP + ks * 32 + bc * 8);
        };
        stageA(0); stageB(0); CP_COMMIT;
        stageA(1); stageB(1); CP_COMMIT;
        stageA(2); stageB(2); CP_COMMIT;
        stageA(3); stageB(3); CP_COMMIT;
        for (int s = 0; s < 128; s += 2) {
            if (s + 2 < 128) { asm volatile("cp.async.wait_group 2;"); }
            else             { asm volatile("cp.async.wait_group 0;"); }
            __syncthreads();
            if (s + 4 < 128) {
                stageA(s + 4); stageB(s + 4); CP_COMMIT;
                stageA(s + 5); stageB(s + 5); CP_COMMIT;
            }
            #pragma unroll
            for (int sub = 0; sub < 2; sub++) {
                const int ss = s + sub;
                const uint32_t aB = asb + (uint32_t)((ss % NSTG) * (BM * BRH) * 2);
                const uint32_t bB = bsb + (uint32_t)((ss % NSTG) * (64 * BRH) * 2);
                #pragma unroll
                for (int seg = 0; seg < 32; seg += 16) {
                    unsigned aa[2][4], bb[4][2];
                    LDSM_X4(aa[0][0], aa[0][1], aa[0][2], aa[0][3], aB + aInv + seg * 2);
                    LDSM_X4(aa[1][0], aa[1][1], aa[1][2], aa[1][3],
                            aB + aInv + (uint32_t)(16 * BRH * 2) + seg * 2);
                    LDSM_X4(bb[0][0], bb[0][1], bb[1][0], bb[1][1], bB + bInv + seg * 2);
                    LDSM_X4(bb[2][0], bb[2][1], bb[3][0], bb[3][1],
                            bB + bInv + (uint32_t)(16 * BRH * 2) + seg * 2);
                    #pragma unroll
                    for (int mf = 0; mf < 2; mf++)
                        #pragma unroll
                        for (int j = 0; j < 4; j++) mma_f16(accO[mf][j], aa[mf], bb[j]);
                }
            }
        }
    }
    #pragma unroll
    for (int mf = 0; mf < 2; mf++)
        #pragma unroll
        for (int j = 0; j < 4; j++) {
            const int row = m0 + wm + mf * 16 + g;
            const int col = d0 + wn + j * 8 + tg * 2;
            *(float2*)(Out + (size_t)row * Dm + col)       = make_float2(accO[mf][j][0], accO[mf][j][1]);
            *(float2*)(Out + (size_t)(row + 8) * Dm + col) = make_float2(accO[mf][j][2], accO[mf][j][3]);
        }
}

// ---------------- launch ----------------------------------------------------
extern "C" void kernel_launch(void* const* d_in, const int* in_sizes, int n_in,
                              void* d_out, int out_size) {
    const float* x        = (const float*)d_in[0];
    const float* W_router = (const float*)d_in[1];
    const float* recipe_Q = (const float*)d_in[2];
    const float* recipe_K = (const float*)d_in[3];
    const float* recipe_V = (const float*)d_in[4];
    const float* recipe_O = (const float*)d_in[5];
    const float* basis_qk = (const float*)d_in[6];
    const float* basis_vo = (const float*)d_in[7];
    float* out = (float*)d_out;

    float *scores, *tQ, *tK, *tV, *tO, *Qp, *Kp, *Vp, *ctx;
    __half *xh, *bqkT, *bvoT, *bvoN;
    cudaGetSymbolAddress((void**)&scores, g_scores);
    cudaGetSymbolAddress((void**)&tQ, g_trQ);
    cudaGetSymbolAddress((void**)&tK, g_trK);
    cudaGetSymbolAddress((void**)&tV, g_trV);
    cudaGetSymbolAddress((void**)&tO, g_trO);
    cudaGetSymbolAddress((void**)&Qp, g_Q);
    cudaGetSymbolAddress((void**)&Kp, g_Km);
    cudaGetSymbolAddress((void**)&Vp, g_V);
    cudaGetSymbolAddress((void**)&ctx, g_ctx);
    cudaGetSymbolAddress((void**)&xh, g_xh);
    cudaGetSymbolAddress((void**)&bqkT, g_bqkT);
    cudaGetSymbolAddress((void**)&bvoT, g_bvoT);
    cudaGetSymbolAddress((void**)&bvoN, g_bvoN);

    const int QK_SMEM = (BM * XRH + NSTG * 64 * BRH) * 2 + 2 * BM * WROW * 4;   // 99328
    const int V_SMEM  = (BM * XRH + NSTG * 64 * BRH) * 2 + BM * WROW * 4;       // 82432
    const int O_SMEM  = BM * WROW * 4 + BM * CTXW * 4
                      + (NSTG * BM * BRH + NSTG * 64 * BRH) * 2;                // 176640
    cudaFuncSetAttribute(qk_mma, cudaFuncAttributeMaxDynamicSharedMemorySize, QK_SMEM);
    cudaFuncSetAttribute(v_mma,  cudaFuncAttributeMaxDynamicSharedMemorySize, V_SMEM);
    cudaFuncSetAttribute(o_mma,  cudaFuncAttributeMaxDynamicSharedMemorySize, O_SMEM);

    cvt_half_kernel<<<1024, 256>>>((const float4*)x, (uint2*)xh, NT * Dm / 4);
    trans_cvt_h<<<dim3(RK / 32, Dm / 32, NB), dim3(32, 8)>>>(basis_qk, bqkT);
    router_gemm<<<dim3(NN / 64, NT / 64), 256>>>(x, W_router, scores);
    route_kernel<<<NT, 32>>>(scores, recipe_Q, recipe_K, recipe_V, recipe_O,
                             tQ, tK, tV, tO);
    trans_cvt_dual<<<dim3(RK / 32, Dm / 32, NB), dim3(32, 8)>>>(basis_vo, bvoT, bvoN);
    qk_mma<<<dim3(RK / BN, NT / BM), 256, QK_SMEM>>>(xh, bqkT, tQ, tK, Qp, Kp);
    v_mma<<<dim3(RK / BN, NT / BM), 256, V_SMEM>>>(xh, bvoT, tV, Vp);
    attn_kernel<<<dim3(Bsz * NH, Ssz / 8), 256>>>(Qp, Kp, Vp, ctx);
    o_mma<<<dim3(Dm / BN, NT / BM), 256, O_SMEM>>>(ctx, bvoN, tO, out);
}

// round 13
// speedup vs baseline: 8.0905x; 1.0304x over previous
#include <cuda_runtime.h>
#include <cuda_fp16.h>
#include <cfloat>
#include <cstdint>

#define Bsz 4
#define Ssz 1024
#define Dm  1024
#define NT  4096
#define NN  256
#define NB  32
#define RK  512
#define NH  16
#define DH  32
#define TOPK 8

// fp16 mma tiling
#define BM 128
#define BN 64
#define KP 128            // X panel width (halfs)
#define XRH 136           // X panel row stride in halfs
#define BRH 40            // B/A tile row stride in halfs
#define NSTG 6            // cp.async ring depth
#define WROW 33           // SMEM weight-tile row stride (floats)
#define OKW  16384        // o GEMM virtual K (NB*RK)

// ---------------- scratch ---------------------------------------------------
__device__ float  g_scores[NT * NN];
__device__ float  g_trQ[NT * NB];
__device__ float  g_trK[NT * NB];
__device__ float  g_trV[NT * NB];
__device__ float  g_trO[NT * NB];
__device__ float  g_Q[NT * RK];
__device__ float  g_Km[NT * RK];
__device__ float  g_V[NT * RK];
__device__ float  g_ctx[NT * RK];
__device__ __half g_xh[NT * Dm];             // fp16 x
__device__ __half g_bqkT[NB * RK * Dm];      // fp16 basis_qk^T [n][r][d]
__device__ __half g_bvoT[NB * RK * Dm];      // fp16 basis_vo^T [n][r][d]
__device__ __half g_bvoN[NB * Dm * RK];      // fp16 basis_vo native [n][d][r]
__device__ __half g_Afold[NT * OKW];         // fp16 trO-scaled ctx (128 MB)

// ---------------- helpers ---------------------------------------------------
__device__ __forceinline__ void mma_f16(float* c, const unsigned* a, const unsigned* b) {
    asm volatile("mma.sync.aligned.m16n8k16.row.col.f32.f16.f16.f32 "
        "{%0,%1,%2,%3}, {%4,%5,%6,%7}, {%8,%9}, {%0,%1,%2,%3};"
        : "+f"(c[0]), "+f"(c[1]), "+f"(c[2]), "+f"(c[3])
        : "r"(a[0]), "r"(a[1]), "r"(a[2]), "r"(a[3]), "r"(b[0]), "r"(b[1]));
}
#define CP_ASYNC16(dst, src) \
    asm volatile("cp.async.cg.shared.global [%0], [%1], 16;" :: "r"(dst), "l"(src))
#define CP_COMMIT asm volatile("cp.async.commit_group;")
#define LDSM_X4(r0, r1, r2, r3, a) \
    asm volatile("ldmatrix.sync.aligned.m8n8.x4.shared.b16 {%0, %1, %2, %3}, [%4];" \
        : "=r"(r0), "=r"(r1), "=r"(r2), "=r"(r3) : "r"(a))
__device__ __forceinline__ unsigned h2u(__half2 h) { return *reinterpret_cast<unsigned*>(&h); }

// ---------------- preprocessing ---------------------------------------------
__global__ void cvt_half_kernel(const float4* __restrict__ s, uint2* __restrict__ d, int n4) {
    for (int i = blockIdx.x * blockDim.x + threadIdx.x; i < n4; i += gridDim.x * blockDim.x) {
        float4 v = s[i];
        __half2 h0 = __floats2half2_rn(v.x, v.y);
        __half2 h1 = __floats2half2_rn(v.z, v.w);
        d[i] = make_uint2(h2u(h0), h2u(h1));
    }
}
// [n][1024 d][512 r] fp32 -> [n][512 r][1024 d] fp16
__global__ void trans_cvt_h(const float* __restrict__ in, __half* __restrict__ out) {
    __shared__ float tile[32][33];
    const int n = blockIdx.z;
    const int d0 = blockIdx.y * 32, r0 = blockIdx.x * 32;
    const float* src = in + (size_t)n * Dm * RK;
    __half* dst = out + (size_t)n * RK * Dm;
    const int tx = threadIdx.x, ty = threadIdx.y;
    #pragma unroll
    for (int i = 0; i < 4; i++)
        tile[ty + i * 8][tx] = src[(size_t)(d0 + ty + i * 8) * RK + r0 + tx];
    __syncthreads();
    #pragma unroll
    for (int i = 0; i < 4; i++)
        dst[(size_t)(r0 + ty + i * 8) * Dm + d0 + tx] = __float2half(tile[tx][ty + i * 8]);
}
// basis_vo: produce BOTH bvoT (transposed) and bvoN (native) fp16 in one pass
__global__ void trans_cvt_dual(const float* __restrict__ in, __half* __restrict__ outT,
                               __half* __restrict__ outN) {
    __shared__ float tile[32][33];
    const int n = blockIdx.z;
    const int d0 = blockIdx.y * 32, r0 = blockIdx.x * 32;
    const float* src = in + (size_t)n * Dm * RK;
    __half* dstT = outT + (size_t)n * RK * Dm;
    __half* dstN = outN + (size_t)n * Dm * RK;
    const int tx = threadIdx.x, ty = threadIdx.y;
    #pragma unroll
    for (int i = 0; i < 4; i++) {
        float v = src[(size_t)(d0 + ty + i * 8) * RK + r0 + tx];
        tile[ty + i * 8][tx] = v;
        dstN[(size_t)(d0 + ty + i * 8) * RK + r0 + tx] = __float2half(v);
    }
    __syncthreads();
    #pragma unroll
    for (int i = 0; i < 4; i++)
        dstT[(size_t)(r0 + ty + i * 8) * Dm + d0 + tx] = __float2half(tile[tx][ty + i * 8]);
}

// ---------------- router GEMM (fp32 SIMT, cp.async double-buffered) ---------
__global__ __launch_bounds__(256) void router_gemm(const float* __restrict__ A,
                                                   const float* __restrict__ Bw,
                                                   float* __restrict__ C) {
    __shared__ float As[2][64][20];
    __shared__ float Bs[2][16][68];
    const int tid = threadIdx.x;
    const int tx = tid & 15, ty = tid >> 4;
    const int m0 = blockIdx.y * 64, n0 = blockIdx.x * 64;
    const uint32_t asb = (uint32_t)__cvta_generic_to_shared(&As[0][0][0]);
    const uint32_t bsb = (uint32_t)__cvta_generic_to_shared(&Bs[0][0][0]);
    const int ar = tid >> 2, ac = (tid & 3) * 4;
    const int brr = tid >> 4, bcc = (tid & 15) * 4;
    float acc[4][4] = {};
    auto load = [&](int kt, int buf) {
        CP_ASYNC16(asb + (uint32_t)((buf * 64 * 20 + ar * 20 + ac) * 4),
                   A + (size_t)(m0 + ar) * Dm + kt * 16 + ac);
        CP_ASYNC16(bsb + (uint32_t)((buf * 16 * 68 + brr * 68 + bcc) * 4),
                   Bw + (size_t)(kt * 16 + brr) * NN + n0 + bcc);
    };
    load(0, 0); CP_COMMIT;
    for (int kt = 0; kt < Dm / 16; kt++) {
        const int buf = kt & 1;
        if (kt + 1 < Dm / 16) {
            load(kt + 1, buf ^ 1); CP_COMMIT;
            asm volatile("cp.async.wait_group 1;");
        } else {
            asm volatile("cp.async.wait_group 0;");
        }
        __syncthreads();
        #pragma unroll
        for (int kk = 0; kk < 16; kk++) {
            float4 bv = *(const float4*)&Bs[buf][kk][tx * 4];
            float a0 = As[buf][ty * 4 + 0][kk];
            float a1 = As[buf][ty * 4 + 1][kk];
            float a2 = As[buf][ty * 4 + 2][kk];
            float a3 = As[buf][ty * 4 + 3][kk];
            acc[0][0] += a0 * bv.x; acc[0][1] += a0 * bv.y; acc[0][2] += a0 * bv.z; acc[0][3] += a0 * bv.w;
            acc[1][0] += a1 * bv.x; acc[1][1] += a1 * bv.y; acc[1][2] += a1 * bv.z; acc[1][3] += a1 * bv.w;
            acc[2][0] += a2 * bv.x; acc[2][1] += a2 * bv.y; acc[2][2] += a2 * bv.z; acc[2][3] += a2 * bv.w;
            acc[3][0] += a3 * bv.x; acc[3][1] += a3 * bv.y; acc[3][2] += a3 * bv.z; acc[3][3] += a3 * bv.w;
        }
        __syncthreads();
    }
    #pragma unroll
    for (int i = 0; i < 4; i++)
        *(float4*)&C[(size_t)(m0 + ty * 4 + i) * NN + n0 + tx * 4] =
            make_float4(acc[i][0], acc[i][1], acc[i][2], acc[i][3]);
}

// ---------------- routing ----------------------------------------------------
__global__ void route_kernel(const float* __restrict__ scores,
                             const float* __restrict__ rQ, const float* __restrict__ rK,
                             const float* __restrict__ rV, const float* __restrict__ rO,
                             float* __restrict__ tQ, float* __restrict__ tK,
                             float* __restrict__ tV, float* __restrict__ tO) {
    const int t = blockIdx.x;
    const int lane = threadIdx.x;
    const float* s = scores + (size_t)t * NN;
    float v[8];
    #pragma unroll
    for (int i = 0; i < 8; i++) v[i] = s[i * 32 + lane];
    float top_v[TOPK];
    int   top_i[TOPK];
    for (int it = 0; it < TOPK; it++) {
        float lm = -FLT_MAX; int li = 0;
        #pragma unroll
        for (int i = 0; i < 8; i++) if (v[i] > lm) { lm = v[i]; li = i; }
        int gi = li * 32 + lane;
        #pragma unroll
        for (int off = 16; off > 0; off >>= 1) {
            float ov = __shfl_xor_sync(0xffffffffu, lm, off);
            int   oi = __shfl_xor_sync(0xffffffffu, gi, off);
            if (ov > lm || (ov == lm && oi < gi)) { lm = ov; gi = oi; }
        }
        top_v[it] = lm; top_i[it] = gi;
        if (lane == (gi & 31)) v[gi >> 5] = -FLT_MAX;
    }
    float w[TOPK], ssum = 0.f;
    #pragma unroll
    for (int k = 0; k < TOPK; k++) { w[k] = expf(top_v[k] - top_v[0]); ssum += w[k]; }
    float inv = 1.f / ssum;
    #pragma unroll
    for (int k = 0; k < TOPK; k++) w[k] *= inv;
    const float* recs[4] = { rQ, rK, rV, rO };
    float* outs[4] = { tQ, tK, tV, tO };
    for (int rr = 0; rr < 4; rr++) {
        const float* R = recs[rr];
        float a = 0.f;
        #pragma unroll
        for (int k = 0; k < TOPK; k++) a += w[k] * R[top_i[k] * NB + lane];
        float mx = a;
        #pragma unroll
        for (int off = 16; off > 0; off >>= 1) mx = fmaxf(mx, __shfl_xor_sync(0xffffffffu, mx, off));
        float e = expf(a - mx);
        float sm = e;
        #pragma unroll
        for (int off = 16; off > 0; off >>= 1) sm += __shfl_xor_sync(0xffffffffu, sm, off);
        outs[rr][(size_t)t * NB + lane] = e / sm;
    }
}

// ---------------- QK fused projection, fp16 mma + ldmatrix (occ 2) ----------
__global__ __launch_bounds__(256, 2) void qk_mma(
        const __half* __restrict__ Xh, const __half* __restrict__ Bt,
        const float* __restrict__ trQ, const float* __restrict__ trK,
        float* __restrict__ Qo, float* __restrict__ Ko) {
    extern __shared__ __half smh[];
    __half* Xs = smh;                        // [128][XRH]
    __half* Bs = smh + BM * XRH;             // [NSTG][64][BRH]
    float* trQs = (float*)(smh + BM * XRH + NSTG * 64 * BRH);   // [128][WROW]
    float* trKs = trQs + BM * WROW;
    const uint32_t xsb = (uint32_t)__cvta_generic_to_shared(Xs);
    const uint32_t bsb = (uint32_t)__cvta_generic_to_shared(Bs);
    const int tid = threadIdx.x;
    const int m0 = blockIdx.y * BM, r0 = blockIdx.x * BN;
    const int w = tid >> 5, lane = tid & 31;
    const int wm = (w >> 1) * 32, wn = (w & 1) * 32;
    const int g = lane >> 2, tg = lane & 3;
    float accQ[2][4][4] = {}, accK[2][4][4] = {}, accT[2][4][4] = {};

    #pragma unroll
    for (int i = 0; i < BM * NB / 256; i++) {
        int e = tid + i * 256;
        int row = e >> 5, c = e & 31;
        trQs[row * WROW + c] = trQ[(size_t)(m0 + row) * NB + c];
        trKs[row * WROW + c] = trK[(size_t)(m0 + row) * NB + c];
    }

    const int br = tid >> 2, bc = tid & 3;
    const uint32_t xA0 = xsb + (uint32_t)(((wm + (lane & 15)) * XRH + (lane >> 4) * 8) * 2);
    const uint32_t xA1 = xA0 + (uint32_t)(16 * XRH * 2);
    const uint32_t bInv = (uint32_t)(((wn + (lane & 7) + 8 * (lane >> 4)) * BRH
                                      + ((lane >> 3) & 1) * 8) * 2);

    for (int kp = 0; kp < Dm / KP; kp++) {
        __syncthreads();
        {
            const __half* Xg = Xh + (size_t)m0 * Dm + kp * KP;
            #pragma unroll
            for (int i = 0; i < 8; i++) {
                int rr = (tid >> 4) + i * 16, cc = tid & 15;
                CP_ASYNC16(xsb + (uint32_t)(rr * XRH + cc * 8) * 2,
                           Xg + (size_t)rr * Dm + cc * 8);
            }
        }
        auto stageB = [&](int s2) {
            const int j = s2 % NSTG, n = s2 >> 2, ks = s2 & 3;
            CP_ASYNC16(bsb + (uint32_t)((j * 64 + br) * BRH + bc * 8) * 2,
                       Bt + ((size_t)n * RK + r0 + br) * Dm + kp * KP + ks * 32 + bc * 8);
        };
        stageB(0); CP_COMMIT;
        stageB(1); CP_COMMIT;
        stageB(2); CP_COMMIT;
        stageB(3); CP_COMMIT;
        for (int s = 0; s < 128; s += 2) {
            if (s + 2 < 128) { asm volatile("cp.async.wait_group 2;"); }
            else             { asm volatile("cp.async.wait_group 0;"); }
            __syncthreads();
            if (s + 4 < 128) {
                stageB(s + 4); CP_COMMIT;
                stageB(s + 5); CP_COMMIT;
            }
            #pragma unroll
            for (int sub = 0; sub < 2; sub++) {
                const int ss = s + sub;
                const uint32_t bB = bsb + (uint32_t)((ss % NSTG) * (64 * BRH) * 2);
                const int kb = (ss & 3) * 32;
                #pragma unroll
                for (int seg = 0; seg < 32; seg += 16) {
                    unsigned aa[2][4], bb[4][2];
                    const int kc0 = kb + seg;
                    LDSM_X4(aa[0][0], aa[0][1], aa[0][2], aa[0][3], xA0 + kc0 * 2);
                    LDSM_X4(aa[1][0], aa[1][1], aa[1][2], aa[1][3], xA1 + kc0 * 2);
                    LDSM_X4(bb[0][0], bb[0][1], bb[1][0], bb[1][1], bB + bInv + seg * 2);
                    LDSM_X4(bb[2][0], bb[2][1], bb[3][0], bb[3][1],
                            bB + bInv + (uint32_t)(16 * BRH * 2) + seg * 2);
                    #pragma unroll
                    for (int mf = 0; mf < 2; mf++)
                        #pragma unroll
                        for (int j = 0; j < 4; j++) mma_f16(accT[mf][j], aa[mf], bb[j]);
                }
            }
            if (((s + 1) & 3) == 3) {
                const int n = (s + 1) >> 2;
                #pragma unroll
                for (int mf = 0; mf < 2; mf++) {
                    const int rL = wm + mf * 16 + g;
                    float wq0 = trQs[rL * WROW + n];
                    float wq8 = trQs[(rL + 8) * WROW + n];
                    float wk0 = trKs[rL * WROW + n];
                    float wk8 = trKs[(rL + 8) * WROW + n];
                    #pragma unroll
                    for (int j = 0; j < 4; j++) {
                        accQ[mf][j][0] += wq0 * accT[mf][j][0];
                        accQ[mf][j][1] += wq0 * accT[mf][j][1];
                        accQ[mf][j][2] += wq8 * accT[mf][j][2];
                        accQ[mf][j][3] += wq8 * accT[mf][j][3];
                        accK[mf][j][0] += wk0 * accT[mf][j][0];
                        accK[mf][j][1] += wk0 * accT[mf][j][1];
                        accK[mf][j][2] += wk8 * accT[mf][j][2];
                        accK[mf][j][3] += wk8 * accT[mf][j][3];
                        accT[mf][j][0] = 0.f; accT[mf][j][1] = 0.f;
                        accT[mf][j][2] = 0.f; accT[mf][j][3] = 0.f;
                    }
                }
            }
        }
    }
    #pragma unroll
    for (int mf = 0; mf < 2; mf++)
        #pragma unroll
        for (int j = 0; j < 4; j++) {
            const int row = m0 + wm + mf * 16 + g;
            const int col = r0 + wn + j * 8 + tg * 2;
            *(float2*)(Qo + (size_t)row * RK + col)       = make_float2(accQ[mf][j][0], accQ[mf][j][1]);
            *(float2*)(Qo + (size_t)(row + 8) * RK + col) = make_float2(accQ[mf][j][2], accQ[mf][j][3]);
            *(float2*)(Ko + (size_t)row * RK + col)       = make_float2(accK[mf][j][0], accK[mf][j][1]);
            *(float2*)(Ko + (size_t)(row + 8) * RK + col) = make_float2(accK[mf][j][2], accK[mf][j][3]);
        }
}

// ---------------- V projection, fp16 mma + ldmatrix (occ 2) ------------------
__global__ __launch_bounds__(256, 2) void v_mma(
        const __half* __restrict__ Xh, const __half* __restrict__ Bt,
        const float* __restrict__ trV, float* __restrict__ Vo) {
    extern __shared__ __half smh[];
    __half* Xs = smh;
    __half* Bs = smh + BM * XRH;
    float* trVs = (float*)(smh + BM * XRH + NSTG * 64 * BRH);   // [128][WROW]
    const uint32_t xsb = (uint32_t)__cvta_generic_to_shared(Xs);
    const uint32_t bsb = (uint32_t)__cvta_generic_to_shared(Bs);
    const int tid = threadIdx.x;
    const int m0 = blockIdx.y * BM, r0 = blockIdx.x * BN;
    const int w = tid >> 5, lane = tid & 31;
    const int wm = (w >> 1) * 32, wn = (w & 1) * 32;
    const int g = lane >> 2, tg = lane & 3;
    float accV[2][4][4] = {}, accT[2][4][4] = {};

    #pragma unroll
    for (int i = 0; i < BM * NB / 256; i++) {
        int e = tid + i * 256;
        int row = e >> 5, c = e & 31;
        trVs[row * WROW + c] = trV[(size_t)(m0 + row) * NB + c];
    }

    const int br = tid >> 2, bc = tid & 3;
    const uint32_t xA0 = xsb + (uint32_t)(((wm + (lane & 15)) * XRH + (lane >> 4) * 8) * 2);
    const uint32_t xA1 = xA0 + (uint32_t)(16 * XRH * 2);
    const uint32_t bInv = (uint32_t)(((wn + (lane & 7) + 8 * (lane >> 4)) * BRH
                                      + ((lane >> 3) & 1) * 8) * 2);

    for (int kp = 0; kp < Dm / KP; kp++) {
        __syncthreads();
        {
            const __half* Xg = Xh + (size_t)m0 * Dm + kp * KP;
            #pragma unroll
            for (int i = 0; i < 8; i++) {
                int rr = (tid >> 4) + i * 16, cc = tid & 15;
                CP_ASYNC16(xsb + (uint32_t)(rr * XRH + cc * 8) * 2,
                           Xg + (size_t)rr * Dm + cc * 8);
            }
        }
        auto stageB = [&](int s2) {
            const int j = s2 % NSTG, n = s2 >> 2, ks = s2 & 3;
            CP_ASYNC16(bsb + (uint32_t)((j * 64 + br) * BRH + bc * 8) * 2,
                       Bt + ((size_t)n * RK + r0 + br) * Dm + kp * KP + ks * 32 + bc * 8);
        };
        stageB(0); CP_COMMIT;
        stageB(1); CP_COMMIT;
        stageB(2); CP_COMMIT;
        stageB(3); CP_COMMIT;
        for (int s = 0; s < 128; s += 2) {
            if (s + 2 < 128) { asm volatile("cp.async.wait_group 2;"); }
            else             { asm volatile("cp.async.wait_group 0;"); }
            __syncthreads();
            if (s + 4 < 128) {
                stageB(s + 4); CP_COMMIT;
                stageB(s + 5); CP_COMMIT;
            }
            #pragma unroll
            for (int sub = 0; sub < 2; sub++) {
                const int ss = s + sub;
                const uint32_t bB = bsb + (uint32_t)((ss % NSTG) * (64 * BRH) * 2);
                const int kb = (ss & 3) * 32;
                #pragma unroll
                for (int seg = 0; seg < 32; seg += 16) {
                    unsigned aa[2][4], bb[4][2];
                    const int kc0 = kb + seg;
                    LDSM_X4(aa[0][0], aa[0][1], aa[0][2], aa[0][3], xA0 + kc0 * 2);
                    LDSM_X4(aa[1][0], aa[1][1], aa[1][2], aa[1][3], xA1 + kc0 * 2);
                    LDSM_X4(bb[0][0], bb[0][1], bb[1][0], bb[1][1], bB + bInv + seg * 2);
                    LDSM_X4(bb[2][0], bb[2][1], bb[3][0], bb[3][1],
                            bB + bInv + (uint32_t)(16 * BRH * 2) + seg * 2);
                    #pragma unroll
                    for (int mf = 0; mf < 2; mf++)
                        #pragma unroll
                        for (int j = 0; j < 4; j++) mma_f16(accT[mf][j], aa[mf], bb[j]);
                }
            }
            if (((s + 1) & 3) == 3) {
                const int n = (s + 1) >> 2;
                #pragma unroll
                for (int mf = 0; mf < 2; mf++) {
                    const int rL = wm + mf * 16 + g;
                    float w0 = trVs[rL * WROW + n];
                    float w8 = trVs[(rL + 8) * WROW + n];
                    #pragma unroll
                    for (int j = 0; j < 4; j++) {
                        accV[mf][j][0] += w0 * accT[mf][j][0];
                        accV[mf][j][1] += w0 * accT[mf][j][1];
                        accV[mf][j][2] += w8 * accT[mf][j][2];
                        accV[mf][j][3] += w8 * accT[mf][j][3];
                        accT[mf][j][0] = 0.f; accT[mf][j][1] = 0.f;
                        accT[mf][j][2] = 0.f; accT[mf][j][3] = 0.f;
                    }
                }
            }
        }
    }
    #pragma unroll
    for (int mf = 0; mf < 2; mf++)
        #pragma unroll
        for (int j = 0; j < 4; j++) {
            const int row = m0 + wm + mf * 16 + g;
            const int col = r0 + wn + j * 8 + tg * 2;
            *(float2*)(Vo + (size_t)row * RK + col)       = make_float2(accV[mf][j][0], accV[mf][j][1]);
            *(float2*)(Vo + (size_t)(row + 8) * RK + col) = make_float2(accV[mf][j][2], accV[mf][j][3]);
        }
}

// ---------------- causal attention (lane=key layout) ------------------------
__global__ void attn_kernel(const float* __restrict__ Q, const float* __restrict__ Km,
                            const float* __restrict__ V, float* __restrict__ ctx) {
    __shared__ float Ks[64][33];
    __shared__ float Vs[64][33];
    const int bh = blockIdx.x;
    const int b = bh >> 4, h = bh & 15;
    const int warp = threadIdx.x >> 5, lane = threadIdx.x & 31;
    const int q = blockIdx.y * 8 + warp;
    const size_t tq = (size_t)b * Ssz + q;
    const float scale = 0.17677669529663688f;
    const float qd = Q[tq * RK + h * DH + lane] * scale;
    float qr[32];
    #pragma unroll
    for (int d = 0; d < 32; d++) qr[d] = __shfl_sync(0xffffffffu, qd, d);
    float m = -1e30f, l = 0.f, acc = 0.f;
    const int qmax = blockIdx.y * 8 + 7;
    for (int k0 = 0; k0 <= qmax; k0 += 64) {
        __syncthreads();
        #pragma unroll
        for (int p = 0; p < 8; p++) {
            int e = threadIdx.x + p * 256;
            int r = e >> 5, c = e & 31;
            size_t tk = ((size_t)b * Ssz + k0 + r) * RK + h * DH + c;
            Ks[r][c] = Km[tk];
            Vs[r][c] = V[tk];
        }
        __syncthreads();
        #pragma unroll
        for (int j0 = 0; j0 < 64; j0 += 32) {
            if (k0 + j0 > q) break;
            const int kidx = k0 + j0 + lane;
            float sv = 0.f;
            #pragma unroll
            for (int d = 0; d < 32; d++) sv += qr[d] * Ks[j0 + lane][d];
            if (kidx > q) sv = -1e30f;
            float mx = sv;
            #pragma unroll
            for (int off = 16; off > 0; off >>= 1)
                mx = fmaxf(mx, __shfl_xor_sync(0xffffffffu, mx, off));
            const float mn = fmaxf(m, mx);
            const float p = __expf(sv - mn);
            float sum = p;
            #pragma unroll
            for (int off = 16; off > 0; off >>= 1)
                sum += __shfl_xor_sync(0xffffffffu, sum, off);
            const float cr = __expf(m - mn);
            l = l * cr + sum;
            float a2 = 0.f;
            #pragma unroll
            for (int j = 0; j < 32; j++)
                a2 += __shfl_sync(0xffffffffu, p, j) * Vs[j0 + j][lane];
            acc = acc * cr + a2;
            m = mn;
        }
    }
    ctx[tq * RK + h * DH + lane] = acc / l;
}

// ---------------- oa_fold: Afold[t][n*512+r] = fp16(trO[t,n]*ctx[t,r]) ------
__global__ __launch_bounds__(128) void oa_fold(const float* __restrict__ Cx,
                                               const float* __restrict__ trO,
                                               __half* __restrict__ Afold) {
    const int t = blockIdx.x;
    const int r4 = threadIdx.x * 4;
    const float4 cv = *(const float4*)(Cx + (size_t)t * RK + r4);
    __half* dst = Afold + (size_t)t * OKW + r4;
    #pragma unroll 8
    for (int n = 0; n < NB; n++) {
        const float wv = __ldg(trO + (size_t)t * NB + n);
        __half2 h0 = __floats2half2_rn(wv * cv.x, wv * cv.y);
        __half2 h1 = __floats2half2_rn(wv * cv.z, wv * cv.w);
        *(uint2*)(dst + (size_t)n * RK) = make_uint2(h2u(h0), h2u(h1));
    }
}

// ---------------- O projection: pure GEMM on Afold (occ 2) -------------------
// out[t,d] = sum_k Afold[t,k] * B'[k,d], k=(n,r), B' = bvoN
__global__ __launch_bounds__(256, 2) void o_mma(
        const __half* __restrict__ Af, const __half* __restrict__ BvN,
        float* __restrict__ Out) {
    extern __shared__ __half smh[];
    __half* Ah = smh;                          // [NSTG][128][BRH]
    __half* Bh = smh + NSTG * BM * BRH;        // [NSTG][64][BRH]
    const uint32_t asb = (uint32_t)__cvta_generic_to_shared(Ah);
    const uint32_t bsb = (uint32_t)__cvta_generic_to_shared(Bh);
    const int tid = threadIdx.x;
    const int m0 = blockIdx.y * BM, d0 = blockIdx.x * BN;
    const int w = tid >> 5, lane = tid & 31;
    const int wm = (w >> 1) * 32, wn = (w & 1) * 32;
    const int g = lane >> 2, tg = lane & 3;
    float accO[2][4][4] = {};
    const int ar = tid >> 1, ac = (tid & 1) * 16;  // A stage: 2 chunks... 1 per thread x2? 128*64B/16B=512 chunks, 256 thr -> 2 each
    const int br = tid >> 2, bc = tid & 3;
    const uint32_t aInv = (uint32_t)(((wm + (lane & 15)) * BRH + (lane >> 4) * 8) * 2);
    const uint32_t bInv = (uint32_t)(((wn + (lane & 7) + 8 * (lane >> 4)) * BRH
                                      + ((lane >> 3) & 1) * 8) * 2);

    const int S = OKW / 32;   // 512 stages of 32 k
    auto stageAB = [&](int s2) {
        const int j = s2 % NSTG;
        const size_t kb = (size_t)s2 * 32;
        // A: 128 rows x 32 halfs
        CP_ASYNC16(asb + (uint32_t)((j * BM + ar) * BRH + ac) * 2,
                   Af + (size_t)(m0 + ar) * OKW + kb + ac);
        CP_ASYNC16(asb + (uint32_t)((j * BM + ar) * BRH + ac + 8) * 2,
                   Af + (size_t)(m0 + ar) * OKW + kb + ac + 8);
        // B: 64 rows x 32 halfs ; B row d: bvoN[n][d][r] with k=(n,r): n=s2>>4, r=kb%512
        const int n = s2 >> 4, rb = (s2 & 15) * 32;
        CP_ASYNC16(bsb + (uint32_t)((j * 64 + br) * BRH + bc * 8) * 2,
                   BvN + ((size_t)n * Dm + d0 + br) * RK + rb + bc * 8);
    };
    stageAB(0); CP_COMMIT;
    stageAB(1); CP_COMMIT;
    stageAB(2); CP_COMMIT;
    stageAB(3); CP_COMMIT;
    for (int s = 0; s < S; s += 2) {
        if (s + 2 < S) { asm volatile("cp.async.wait_group 2;"); }
        else           { asm volatile("cp.async.wait_group 0;"); }
        __syncthreads();
        if (s + 4 < S) {
            stageAB(s + 4); CP_COMMIT;
            stageAB(s + 5); CP_COMMIT;
        }
        #pragma unroll
        for (int sub = 0; sub < 2; sub++) {
            const int ss = s + sub;
            const uint32_t aB = asb + (uint32_t)((ss % NSTG) * (BM * BRH) * 2);
            const uint32_t bB = bsb + (uint32_t)((ss % NSTG) * (64 * BRH) * 2);
            #pragma unroll
            for (int seg = 0; seg < 32; seg += 16) {
                unsigned aa[2][4], bb[4][2];
                LDSM_X4(aa[0][0], aa[0][1], aa[0][2], aa[0][3], aB + aInv + seg * 2);
                LDSM_X4(aa[1][0], aa[1][1], aa[1][2], aa[1][3],
                        aB + aInv + (uint32_t)(16 * BRH * 2) + seg * 2);
                LDSM_X4(bb[0][0], bb[0][1], bb[1][0], bb[1][1], bB + bInv + seg * 2);
                LDSM_X4(bb[2][0], bb[2][1], bb[3][0], bb[3][1],
                        bB + bInv + (uint32_t)(16 * BRH * 2) + seg * 2);
                #pragma unroll
                for (int mf = 0; mf < 2; mf++)
                    #pragma unroll
                    for (int j = 0; j < 4; j++) mma_f16(accO[mf][j], aa[mf], bb[j]);
            }
        }
    }
    #pragma unroll
    for (int mf = 0; mf < 2; mf++)
        #pragma unroll
        for (int j = 0; j < 4; j++) {
            const int row = m0 + wm + mf * 16 + g;
            const int col = d0 + wn + j * 8 + tg * 2;
            *(float2*)(Out + (size_t)row * Dm + col)       = make_float2(accO[mf][j][0], accO[mf][j][1]);
            *(float2*)(Out + (size_t)(row + 8) * Dm + col) = make_float2(accO[mf][j][2], accO[mf][j][3]);
        }
}

// ---------------- launch ----------------------------------------------------
extern "C" void kernel_launch(void* const* d_in, const int* in_sizes, int n_in,
                              void* d_out, int out_size) {
    const float* x        = (const float*)d_in[0];
    const float* W_router = (const float*)d_in[1];
    const float* recipe_Q = (const float*)d_in[2];
    const float* recipe_K = (const float*)d_in[3];
    const float* recipe_V = (const float*)d_in[4];
    const float* recipe_O = (const float*)d_in[5];
    const float* basis_qk = (const float*)d_in[6];
    const float* basis_vo = (const float*)d_in[7];
    float* out = (float*)d_out;

    float *scores, *tQ, *tK, *tV, *tO, *Qp, *Kp, *Vp, *ctx;
    __half *xh, *bqkT, *bvoT, *bvoN, *Af;
    cudaGetSymbolAddress((void**)&scores, g_scores);
    cudaGetSymbolAddress((void**)&tQ, g_trQ);
    cudaGetSymbolAddress((void**)&tK, g_trK);
    cudaGetSymbolAddress((void**)&tV, g_trV);
    cudaGetSymbolAddress((void**)&tO, g_trO);
    cudaGetSymbolAddress((void**)&Qp, g_Q);
    cudaGetSymbolAddress((void**)&Kp, g_Km);
    cudaGetSymbolAddress((void**)&Vp, g_V);
    cudaGetSymbolAddress((void**)&ctx, g_ctx);
    cudaGetSymbolAddress((void**)&xh, g_xh);
    cudaGetSymbolAddress((void**)&bqkT, g_bqkT);
    cudaGetSymbolAddress((void**)&bvoT, g_bvoT);
    cudaGetSymbolAddress((void**)&bvoN, g_bvoN);
    cudaGetSymbolAddress((void**)&Af, g_Afold);

    const int QK_SMEM = (BM * XRH + NSTG * 64 * BRH) * 2 + 2 * BM * WROW * 4;   // 99328
    const int V_SMEM  = (BM * XRH + NSTG * 64 * BRH) * 2 + BM * WROW * 4;       // 82432
    const int O_SMEM  = (NSTG * BM * BRH + NSTG * 64 * BRH) * 2;                // 92160
    cudaFuncSetAttribute(qk_mma, cudaFuncAttributeMaxDynamicSharedMemorySize, QK_SMEM);
    cudaFuncSetAttribute(v_mma,  cudaFuncAttributeMaxDynamicSharedMemorySize, V_SMEM);
    cudaFuncSetAttribute(o_mma,  cudaFuncAttributeMaxDynamicSharedMemorySize, O_SMEM);

    cvt_half_kernel<<<1024, 256>>>((const float4*)x, (uint2*)xh, NT * Dm / 4);
    trans_cvt_h<<<dim3(RK / 32, Dm / 32, NB), dim3(32, 8)>>>(basis_qk, bqkT);
    router_gemm<<<dim3(NN / 64, NT / 64), 256>>>(x, W_router, scores);
    route_kernel<<<NT, 32>>>(scores, recipe_Q, recipe_K, recipe_V, recipe_O,
                             tQ, tK, tV, tO);
    trans_cvt_dual<<<dim3(RK / 32, Dm / 32, NB), dim3(32, 8)>>>(basis_vo, bvoT, bvoN);
    qk_mma<<<dim3(RK / BN, NT / BM), 256, QK_SMEM>>>(xh, bqkT, tQ, tK, Qp, Kp);
    v_mma<<<dim3(RK / BN, NT / BM), 256, V_SMEM>>>(xh, bvoT, tV, Vp);
    attn_kernel<<<dim3(Bsz * NH, Ssz / 8), 256>>>(Qp, Kp, Vp, ctx);
    oa_fold<<<NT, 128>>>(ctx, tO, Af);
    o_mma<<<dim3(Dm / BN, NT / BM), 256, O_SMEM>>>(Af, bvoN, out);
}

// round 14
// speedup vs baseline: 8.3148x; 1.0277x over previous
#include <cuda_runtime.h>
#include <cuda_fp16.h>
#include <cfloat>
#include <cstdint>

#define Bsz 4
#define Ssz 1024
#define Dm  1024
#define NT  4096
#define NN  256
#define NB  32
#define RK  512
#define NH  16
#define DH  32
#define TOPK 8

// fp16 mma tiling
#define BM 128
#define BN 64
#define KP 128            // X panel width (halfs)
#define XRH 136           // X panel row stride in halfs
#define BRH 40            // o_mma A/B tile row stride in halfs
#define BRT 72            // qk/v B tile row stride in halfs (k-major rows)
#define NSTG 6            // cp.async ring depth
#define WROW 33           // SMEM weight-tile row stride (floats)
#define OKW  16384        // o GEMM virtual K (NB*RK)

// ---------------- scratch ---------------------------------------------------
__device__ float  g_scores[NT * NN];
__device__ float  g_trQ[NT * NB];
__device__ float  g_trK[NT * NB];
__device__ float  g_trV[NT * NB];
__device__ float  g_trO[NT * NB];
__device__ float  g_Q[NT * RK];
__device__ float  g_Km[NT * RK];
__device__ float  g_V[NT * RK];
__device__ float  g_ctx[NT * RK];
__device__ __half g_xh[NT * Dm];             // fp16 x
__device__ __half g_bqkN[NB * Dm * RK];      // fp16 basis_qk native [n][d][r]
__device__ __half g_bvoN[NB * Dm * RK];      // fp16 basis_vo native [n][d][r]
__device__ __half g_Afold[NT * OKW];         // fp16 trO-scaled ctx (128 MB)

// ---------------- helpers ---------------------------------------------------
__device__ __forceinline__ void mma_f16(float* c, const unsigned* a, const unsigned* b) {
    asm volatile("mma.sync.aligned.m16n8k16.row.col.f32.f16.f16.f32 "
        "{%0,%1,%2,%3}, {%4,%5,%6,%7}, {%8,%9}, {%0,%1,%2,%3};"
        : "+f"(c[0]), "+f"(c[1]), "+f"(c[2]), "+f"(c[3])
        : "r"(a[0]), "r"(a[1]), "r"(a[2]), "r"(a[3]), "r"(b[0]), "r"(b[1]));
}
#define CP_ASYNC16(dst, src) \
    asm volatile("cp.async.cg.shared.global [%0], [%1], 16;" :: "r"(dst), "l"(src))
#define CP_COMMIT asm volatile("cp.async.commit_group;")
#define LDSM_X4(r0, r1, r2, r3, a) \
    asm volatile("ldmatrix.sync.aligned.m8n8.x4.shared.b16 {%0, %1, %2, %3}, [%4];" \
        : "=r"(r0), "=r"(r1), "=r"(r2), "=r"(r3) : "r"(a))
#define LDSM_X4T(r0, r1, r2, r3, a) \
    asm volatile("ldmatrix.sync.aligned.m8n8.x4.trans.shared.b16 {%0, %1, %2, %3}, [%4];" \
        : "=r"(r0), "=r"(r1), "=r"(r2), "=r"(r3) : "r"(a))
__device__ __forceinline__ unsigned h2u(__half2 h) { return *reinterpret_cast<unsigned*>(&h); }

// ---------------- preprocessing ---------------------------------------------
__global__ void cvt_half_kernel(const float4* __restrict__ s, uint2* __restrict__ d, int n4) {
    for (int i = blockIdx.x * blockDim.x + threadIdx.x; i < n4; i += gridDim.x * blockDim.x) {
        float4 v = s[i];
        __half2 h0 = __floats2half2_rn(v.x, v.y);
        __half2 h1 = __floats2half2_rn(v.z, v.w);
        d[i] = make_uint2(h2u(h0), h2u(h1));
    }
}

// ---------------- router GEMM (fp32 SIMT, cp.async double-buffered) ---------
__global__ __launch_bounds__(256) void router_gemm(const float* __restrict__ A,
                                                   const float* __restrict__ Bw,
                                                   float* __restrict__ C) {
    __shared__ float As[2][64][20];
    __shared__ float Bs[2][16][68];
    const int tid = threadIdx.x;
    const int tx = tid & 15, ty = tid >> 4;
    const int m0 = blockIdx.y * 64, n0 = blockIdx.x * 64;
    const uint32_t asb = (uint32_t)__cvta_generic_to_shared(&As[0][0][0]);
    const uint32_t bsb = (uint32_t)__cvta_generic_to_shared(&Bs[0][0][0]);
    const int ar = tid >> 2, ac = (tid & 3) * 4;
    const int brr = tid >> 4, bcc = (tid & 15) * 4;
    float acc[4][4] = {};
    auto load = [&](int kt, int buf) {
        CP_ASYNC16(asb + (uint32_t)((buf * 64 * 20 + ar * 20 + ac) * 4),
                   A + (size_t)(m0 + ar) * Dm + kt * 16 + ac);
        CP_ASYNC16(bsb + (uint32_t)((buf * 16 * 68 + brr * 68 + bcc) * 4),
                   Bw + (size_t)(kt * 16 + brr) * NN + n0 + bcc);
    };
    load(0, 0); CP_COMMIT;
    for (int kt = 0; kt < Dm / 16; kt++) {
        const int buf = kt & 1;
        if (kt + 1 < Dm / 16) {
            load(kt + 1, buf ^ 1); CP_COMMIT;
            asm volatile("cp.async.wait_group 1;");
        } else {
            asm volatile("cp.async.wait_group 0;");
        }
        __syncthreads();
        #pragma unroll
        for (int kk = 0; kk < 16; kk++) {
            float4 bv = *(const float4*)&Bs[buf][kk][tx * 4];
            float a0 = As[buf][ty * 4 + 0][kk];
            float a1 = As[buf][ty * 4 + 1][kk];
            float a2 = As[buf][ty * 4 + 2][kk];
            float a3 = As[buf][ty * 4 + 3][kk];
            acc[0][0] += a0 * bv.x; acc[0][1] += a0 * bv.y; acc[0][2] += a0 * bv.z; acc[0][3] += a0 * bv.w;
            acc[1][0] += a1 * bv.x; acc[1][1] += a1 * bv.y; acc[1][2] += a1 * bv.z; acc[1][3] += a1 * bv.w;
            acc[2][0] += a2 * bv.x; acc[2][1] += a2 * bv.y; acc[2][2] += a2 * bv.z; acc[2][3] += a2 * bv.w;
            acc[3][0] += a3 * bv.x; acc[3][1] += a3 * bv.y; acc[3][2] += a3 * bv.z; acc[3][3] += a3 * bv.w;
        }
        __syncthreads();
    }
    #pragma unroll
    for (int i = 0; i < 4; i++)
        *(float4*)&C[(size_t)(m0 + ty * 4 + i) * NN + n0 + tx * 4] =
            make_float4(acc[i][0], acc[i][1], acc[i][2], acc[i][3]);
}

// ---------------- routing ----------------------------------------------------
__global__ void route_kernel(const float* __restrict__ scores,
                             const float* __restrict__ rQ, const float* __restrict__ rK,
                             const float* __restrict__ rV, const float* __restrict__ rO,
                             float* __restrict__ tQ, float* __restrict__ tK,
                             float* __restrict__ tV, float* __restrict__ tO) {
    const int t = blockIdx.x;
    const int lane = threadIdx.x;
    const float* s = scores + (size_t)t * NN;
    float v[8];
    #pragma unroll
    for (int i = 0; i < 8; i++) v[i] = s[i * 32 + lane];
    float top_v[TOPK];
    int   top_i[TOPK];
    for (int it = 0; it < TOPK; it++) {
        float lm = -FLT_MAX; int li = 0;
        #pragma unroll
        for (int i = 0; i < 8; i++) if (v[i] > lm) { lm = v[i]; li = i; }
        int gi = li * 32 + lane;
        #pragma unroll
        for (int off = 16; off > 0; off >>= 1) {
            float ov = __shfl_xor_sync(0xffffffffu, lm, off);
            int   oi = __shfl_xor_sync(0xffffffffu, gi, off);
            if (ov > lm || (ov == lm && oi < gi)) { lm = ov; gi = oi; }
        }
        top_v[it] = lm; top_i[it] = gi;
        if (lane == (gi & 31)) v[gi >> 5] = -FLT_MAX;
    }
    float w[TOPK], ssum = 0.f;
    #pragma unroll
    for (int k = 0; k < TOPK; k++) { w[k] = expf(top_v[k] - top_v[0]); ssum += w[k]; }
    float inv = 1.f / ssum;
    #pragma unroll
    for (int k = 0; k < TOPK; k++) w[k] *= inv;
    const float* recs[4] = { rQ, rK, rV, rO };
    float* outs[4] = { tQ, tK, tV, tO };
    for (int rr = 0; rr < 4; rr++) {
        const float* R = recs[rr];
        float a = 0.f;
        #pragma unroll
        for (int k = 0; k < TOPK; k++) a += w[k] * R[top_i[k] * NB + lane];
        float mx = a;
        #pragma unroll
        for (int off = 16; off > 0; off >>= 1) mx = fmaxf(mx, __shfl_xor_sync(0xffffffffu, mx, off));
        float e = expf(a - mx);
        float sm = e;
        #pragma unroll
        for (int off = 16; off > 0; off >>= 1) sm += __shfl_xor_sync(0xffffffffu, sm, off);
        outs[rr][(size_t)t * NB + lane] = e / sm;
    }
}

// ---------------- QK fused projection (native B via ldmatrix.trans, occ 2) --
__global__ __launch_bounds__(256, 2) void qk_mma(
        const __half* __restrict__ Xh, const __half* __restrict__ Bn,
        const float* __restrict__ trQ, const float* __restrict__ trK,
        float* __restrict__ Qo, float* __restrict__ Ko) {
    extern __shared__ __half smh[];
    __half* Xs = smh;                        // [128][XRH]
    __half* Bs = smh + BM * XRH;             // [NSTG][32 k][BRT]
    float* trQs = (float*)(smh + BM * XRH + NSTG * 32 * BRT);   // [128][WROW]
    float* trKs = trQs + BM * WROW;
    const uint32_t xsb = (uint32_t)__cvta_generic_to_shared(Xs);
    const uint32_t bsb = (uint32_t)__cvta_generic_to_shared(Bs);
    const int tid = threadIdx.x;
    const int m0 = blockIdx.y * BM, r0 = blockIdx.x * BN;
    const int w = tid >> 5, lane = tid & 31;
    const int wm = (w >> 1) * 32, wn = (w & 1) * 32;
    const int g = lane >> 2, tg = lane & 3;
    float accQ[2][4][4] = {}, accK[2][4][4] = {}, accT[2][4][4] = {};

    #pragma unroll
    for (int i = 0; i < BM * NB / 256; i++) {
        int e = tid + i * 256;
        int row = e >> 5, c = e & 31;
        trQs[row * WROW + c] = trQ[(size_t)(m0 + row) * NB + c];
        trKs[row * WROW + c] = trK[(size_t)(m0 + row) * NB + c];
    }

    const int bkr = tid >> 3, bcc = tid & 7;   // B stage: 32 k-rows x 8 chunks
    const uint32_t xA0 = xsb + (uint32_t)(((wm + (lane & 15)) * XRH + (lane >> 4) * 8) * 2);
    const uint32_t xA1 = xA0 + (uint32_t)(16 * XRH * 2);
    // trans B: lane -> (kappa=(l>>3)&1, rho=l>>4, row=l&7)
    const uint32_t bInvT = (uint32_t)(((((lane >> 3) & 1) * 8 + (lane & 7)) * BRT
                                       + wn + (lane >> 4) * 8) * 2);

    for (int kp = 0; kp < Dm / KP; kp++) {
        __syncthreads();
        {
            const __half* Xg = Xh + (size_t)m0 * Dm + kp * KP;
            #pragma unroll
            for (int i = 0; i < 8; i++) {
                int rr = (tid >> 4) + i * 16, cc = tid & 15;
                CP_ASYNC16(xsb + (uint32_t)(rr * XRH + cc * 8) * 2,
                           Xg + (size_t)rr * Dm + cc * 8);
            }
        }
        auto stageB = [&](int s2) {
            const int j = s2 % NSTG, n = s2 >> 2, ks = s2 & 3;
            CP_ASYNC16(bsb + (uint32_t)((j * 32 + bkr) * BRT + bcc * 8) * 2,
                       Bn + ((size_t)n * Dm + kp * KP + ks * 32 + bkr) * RK + r0 + bcc * 8);
        };
        stageB(0); CP_COMMIT;
        stageB(1); CP_COMMIT;
        stageB(2); CP_COMMIT;
        stageB(3); CP_COMMIT;
        for (int s = 0; s < 128; s += 2) {
            if (s + 2 < 128) { asm volatile("cp.async.wait_group 2;"); }
            else             { asm volatile("cp.async.wait_group 0;"); }
            __syncthreads();
            if (s + 4 < 128) {
                stageB(s + 4); CP_COMMIT;
                stageB(s + 5); CP_COMMIT;
            }
            #pragma unroll
            for (int sub = 0; sub < 2; sub++) {
                const int ss = s + sub;
                const uint32_t bB = bsb + (uint32_t)((ss % NSTG) * (32 * BRT) * 2);
                const int kb = (ss & 3) * 32;
                #pragma unroll
                for (int seg = 0; seg < 32; seg += 16) {
                    unsigned aa[2][4], bb[4][2];
                    const int kc0 = kb + seg;
                    LDSM_X4(aa[0][0], aa[0][1], aa[0][2], aa[0][3], xA0 + kc0 * 2);
                    LDSM_X4(aa[1][0], aa[1][1], aa[1][2], aa[1][3], xA1 + kc0 * 2);
                    // trans loads: jp=0 -> bb[0],bb[1]; jp=1 -> bb[2],bb[3]
                    LDSM_X4T(bb[0][0], bb[0][1], bb[1][0], bb[1][1],
                             bB + bInvT + (uint32_t)(seg * BRT) * 2);
                    LDSM_X4T(bb[2][0], bb[2][1], bb[3][0], bb[3][1],
                             bB + bInvT + (uint32_t)(seg * BRT + 16) * 2);
                    #pragma unroll
                    for (int mf = 0; mf < 2; mf++)
                        #pragma unroll
                        for (int j = 0; j < 4; j++) mma_f16(accT[mf][j], aa[mf], bb[j]);
                }
            }
            if (((s + 1) & 3) == 3) {
                const int n = (s + 1) >> 2;
                #pragma unroll
                for (int mf = 0; mf < 2; mf++) {
                    const int rL = wm + mf * 16 + g;
                    float wq0 = trQs[rL * WROW + n];
                    float wq8 = trQs[(rL + 8) * WROW + n];
                    float wk0 = trKs[rL * WROW + n];
                    float wk8 = trKs[(rL + 8) * WROW + n];
                    #pragma unroll
                    for (int j = 0; j < 4; j++) {
                        accQ[mf][j][0] += wq0 * accT[mf][j][0];
                        accQ[mf][j][1] += wq0 * accT[mf][j][1];
                        accQ[mf][j][2] += wq8 * accT[mf][j][2];
                        accQ[mf][j][3] += wq8 * accT[mf][j][3];
                        accK[mf][j][0] += wk0 * accT[mf][j][0];
                        accK[mf][j][1] += wk0 * accT[mf][j][1];
                        accK[mf][j][2] += wk8 * accT[mf][j][2];
                        accK[mf][j][3] += wk8 * accT[mf][j][3];
                        accT[mf][j][0] = 0.f; accT[mf][j][1] = 0.f;
                        accT[mf][j][2] = 0.f; accT[mf][j][3] = 0.f;
                    }
                }
            }
        }
    }
    #pragma unroll
    for (int mf = 0; mf < 2; mf++)
        #pragma unroll
        for (int j = 0; j < 4; j++) {
            const int row = m0 + wm + mf * 16 + g;
            const int col = r0 + wn + j * 8 + tg * 2;
            *(float2*)(Qo + (size_t)row * RK + col)       = make_float2(accQ[mf][j][0], accQ[mf][j][1]);
            *(float2*)(Qo + (size_t)(row + 8) * RK + col) = make_float2(accQ[mf][j][2], accQ[mf][j][3]);
            *(float2*)(Ko + (size_t)row * RK + col)       = make_float2(accK[mf][j][0], accK[mf][j][1]);
            *(float2*)(Ko + (size_t)(row + 8) * RK + col) = make_float2(accK[mf][j][2], accK[mf][j][3]);
        }
}

// ---------------- V projection (native B via ldmatrix.trans, occ 2) ----------
__global__ __launch_bounds__(256, 2) void v_mma(
        const __half* __restrict__ Xh, const __half* __restrict__ Bn,
        const float* __restrict__ trV, float* __restrict__ Vo) {
    extern __shared__ __half smh[];
    __half* Xs = smh;
    __half* Bs = smh + BM * XRH;
    float* trVs = (float*)(smh + BM * XRH + NSTG * 32 * BRT);   // [128][WROW]
    const uint32_t xsb = (uint32_t)__cvta_generic_to_shared(Xs);
    const uint32_t bsb = (uint32_t)__cvta_generic_to_shared(Bs);
    const int tid = threadIdx.x;
    const int m0 = blockIdx.y * BM, r0 = blockIdx.x * BN;
    const int w = tid >> 5, lane = tid & 31;
    const int wm = (w >> 1) * 32, wn = (w & 1) * 32;
    const int g = lane >> 2, tg = lane & 3;
    float accV[2][4][4] = {}, accT[2][4][4] = {};

    #pragma unroll
    for (int i = 0; i < BM * NB / 256; i++) {
        int e = tid + i * 256;
        int row = e >> 5, c = e & 31;
        trVs[row * WROW + c] = trV[(size_t)(m0 + row) * NB + c];
    }

    const int bkr = tid >> 3, bcc = tid & 7;
    const uint32_t xA0 = xsb + (uint32_t)(((wm + (lane & 15)) * XRH + (lane >> 4) * 8) * 2);
    const uint32_t xA1 = xA0 + (uint32_t)(16 * XRH * 2);
    const uint32_t bInvT = (uint32_t)(((((lane >> 3) & 1) * 8 + (lane & 7)) * BRT
                                       + wn + (lane >> 4) * 8) * 2);

    for (int kp = 0; kp < Dm / KP; kp++) {
        __syncthreads();
        {
            const __half* Xg = Xh + (size_t)m0 * Dm + kp * KP;
            #pragma unroll
            for (int i = 0; i < 8; i++) {
                int rr = (tid >> 4) + i * 16, cc = tid & 15;
                CP_ASYNC16(xsb + (uint32_t)(rr * XRH + cc * 8) * 2,
                           Xg + (size_t)rr * Dm + cc * 8);
            }
        }
        auto stageB = [&](int s2) {
            const int j = s2 % NSTG, n = s2 >> 2, ks = s2 & 3;
            CP_ASYNC16(bsb + (uint32_t)((j * 32 + bkr) * BRT + bcc * 8) * 2,
                       Bn + ((size_t)n * Dm + kp * KP + ks * 32 + bkr) * RK + r0 + bcc * 8);
        };
        stageB(0); CP_COMMIT;
        stageB(1); CP_COMMIT;
        stageB(2); CP_COMMIT;
        stageB(3); CP_COMMIT;
        for (int s = 0; s < 128; s += 2) {
            if (s + 2 < 128) { asm volatile("cp.async.wait_group 2;"); }
            else             { asm volatile("cp.async.wait_group 0;"); }
            __syncthreads();
            if (s + 4 < 128) {
                stageB(s + 4); CP_COMMIT;
                stageB(s + 5); CP_COMMIT;
            }
            #pragma unroll
            for (int sub = 0; sub < 2; sub++) {
                const int ss = s + sub;
                const uint32_t bB = bsb + (uint32_t)((ss % NSTG) * (32 * BRT) * 2);
                const int kb = (ss & 3) * 32;
                #pragma unroll
                for (int seg = 0; seg < 32; seg += 16) {
                    unsigned aa[2][4], bb[4][2];
                    const int kc0 = kb + seg;
                    LDSM_X4(aa[0][0], aa[0][1], aa[0][2], aa[0][3], xA0 + kc0 * 2);
                    LDSM_X4(aa[1][0], aa[1][1], aa[1][2], aa[1][3], xA1 + kc0 * 2);
                    LDSM_X4T(bb[0][0], bb[0][1], bb[1][0], bb[1][1],
                             bB + bInvT + (uint32_t)(seg * BRT) * 2);
                    LDSM_X4T(bb[2][0], bb[2][1], bb[3][0], bb[3][1],
                             bB + bInvT + (uint32_t)(seg * BRT + 16) * 2);
                    #pragma unroll
                    for (int mf = 0; mf < 2; mf++)
                        #pragma unroll
                        for (int j = 0; j < 4; j++) mma_f16(accT[mf][j], aa[mf], bb[j]);
                }
            }
            if (((s + 1) & 3) == 3) {
                const int n = (s + 1) >> 2;
                #pragma unroll
                for (int mf = 0; mf < 2; mf++) {
                    const int rL = wm + mf * 16 + g;
                    float w0 = trVs[rL * WROW + n];
                    float w8 = trVs[(rL + 8) * WROW + n];
                    #pragma unroll
                    for (int j = 0; j < 4; j++) {
                        accV[mf][j][0] += w0 * accT[mf][j][0];
                        accV[mf][j][1] += w0 * accT[mf][j][1];
                        accV[mf][j][2] += w8 * accT[mf][j][2];
                        accV[mf][j][3] += w8 * accT[mf][j][3];
                        accT[mf][j][0] = 0.f; accT[mf][j][1] = 0.f;
                        accT[mf][j][2] = 0.f; accT[mf][j][3] = 0.f;
                    }
                }
            }
        }
    }
    #pragma unroll
    for (int mf = 0; mf < 2; mf++)
        #pragma unroll
        for (int j = 0; j < 4; j++) {
            const int row = m0 + wm + mf * 16 + g;
            const int col = r0 + wn + j * 8 + tg * 2;
            *(float2*)(Vo + (size_t)row * RK + col)       = make_float2(accV[mf][j][0], accV[mf][j][1]);
            *(float2*)(Vo + (size_t)(row + 8) * RK + col) = make_float2(accV[mf][j][2], accV[mf][j][3]);
        }
}

// ---------------- causal attention (16 queries/block) ------------------------
__global__ __launch_bounds__(512) void attn_kernel(
        const float* __restrict__ Q, const float* __restrict__ Km,
        const float* __restrict__ V, float* __restrict__ ctx) {
    __shared__ float Ks[64][33];
    __shared__ float Vs[64][33];
    const int bh = blockIdx.x;
    const int b = bh >> 4, h = bh & 15;
    const int warp = threadIdx.x >> 5, lane = threadIdx.x & 31;
    const int q = blockIdx.y * 16 + warp;
    const size_t tq = (size_t)b * Ssz + q;
    const float scale = 0.17677669529663688f;
    const float qd = Q[tq * RK + h * DH + lane] * scale;
    float qr[32];
    #pragma unroll
    for (int d = 0; d < 32; d++) qr[d] = __shfl_sync(0xffffffffu, qd, d);
    float m = -1e30f, l = 0.f, acc = 0.f;
    const int qmax = blockIdx.y * 16 + 15;
    for (int k0 = 0; k0 <= qmax; k0 += 64) {
        __syncthreads();
        #pragma unroll
        for (int p = 0; p < 4; p++) {
            int e = threadIdx.x + p * 512;
            int r = e >> 5, c = e & 31;
            size_t tk = ((size_t)b * Ssz + k0 + r) * RK + h * DH + c;
            Ks[r][c] = Km[tk];
            Vs[r][c] = V[tk];
        }
        __syncthreads();
        #pragma unroll
        for (int j0 = 0; j0 < 64; j0 += 32) {
            if (k0 + j0 > q) break;
            const int kidx = k0 + j0 + lane;
            float sv = 0.f;
            #pragma unroll
            for (int d = 0; d < 32; d++) sv += qr[d] * Ks[j0 + lane][d];
            if (kidx > q) sv = -1e30f;
            float mx = sv;
            #pragma unroll
            for (int off = 16; off > 0; off >>= 1)
                mx = fmaxf(mx, __shfl_xor_sync(0xffffffffu, mx, off));
            const float mn = fmaxf(m, mx);
            const float p = __expf(sv - mn);
            float sum = p;
            #pragma unroll
            for (int off = 16; off > 0; off >>= 1)
                sum += __shfl_xor_sync(0xffffffffu, sum, off);
            const float cr = __expf(m - mn);
            l = l * cr + sum;
            float a2 = 0.f;
            #pragma unroll
            for (int j = 0; j < 32; j++)
                a2 += __shfl_sync(0xffffffffu, p, j) * Vs[j0 + j][lane];
            acc = acc * cr + a2;
            m = mn;
        }
    }
    ctx[tq * RK + h * DH + lane] = acc / l;
}

// ---------------- oa_fold: Afold[t][n*512+r] = fp16(trO[t,n]*ctx[t,r]) ------
__global__ __launch_bounds__(128) void oa_fold(const float* __restrict__ Cx,
                                               const float* __restrict__ trO,
                                               __half* __restrict__ Afold) {
    const int t = blockIdx.x;
    const int r4 = threadIdx.x * 4;
    const float4 cv = *(const float4*)(Cx + (size_t)t * RK + r4);
    __half* dst = Afold + (size_t)t * OKW + r4;
    #pragma unroll 8
    for (int n = 0; n < NB; n++) {
        const float wv = __ldg(trO + (size_t)t * NB + n);
        __half2 h0 = __floats2half2_rn(wv * cv.x, wv * cv.y);
        __half2 h1 = __floats2half2_rn(wv * cv.z, wv * cv.w);
        *(uint2*)(dst + (size_t)n * RK) = make_uint2(h2u(h0), h2u(h1));
    }
}

// ---------------- O projection: pure GEMM on Afold (occ 2) -------------------
__global__ __launch_bounds__(256, 2) void o_mma(
        const __half* __restrict__ Af, const __half* __restrict__ BvN,
        float* __restrict__ Out) {
    extern __shared__ __half smh[];
    __half* Ah = smh;                          // [NSTG][128][BRH]
    __half* Bh = smh + NSTG * BM * BRH;        // [NSTG][64][BRH]
    const uint32_t asb = (uint32_t)__cvta_generic_to_shared(Ah);
    const uint32_t bsb = (uint32_t)__cvta_generic_to_shared(Bh);
    const int tid = threadIdx.x;
    const int m0 = blockIdx.y * BM, d0 = blockIdx.x * BN;
    const int w = tid >> 5, lane = tid & 31;
    const int wm = (w >> 1) * 32, wn = (w & 1) * 32;
    const int g = lane >> 2, tg = lane & 3;
    float accO[2][4][4] = {};
    const int ar = tid >> 1, ac = (tid & 1) * 16;
    const int br = tid >> 2, bc = tid & 3;
    const uint32_t aInv = (uint32_t)(((wm + (lane & 15)) * BRH + (lane >> 4) * 8) * 2);
    const uint32_t bInv = (uint32_t)(((wn + (lane & 7) + 8 * (lane >> 4)) * BRH
                                      + ((lane >> 3) & 1) * 8) * 2);

    const int S = OKW / 32;   // 512 stages of 32 k
    auto stageAB = [&](int s2) {
        const int j = s2 % NSTG;
        const size_t kb = (size_t)s2 * 32;
        CP_ASYNC16(asb + (uint32_t)((j * BM + ar) * BRH + ac) * 2,
                   Af + (size_t)(m0 + ar) * OKW + kb + ac);
        CP_ASYNC16(asb + (uint32_t)((j * BM + ar) * BRH + ac + 8) * 2,
                   Af + (size_t)(m0 + ar) * OKW + kb + ac + 8);
        const int n = s2 >> 4, rb = (s2 & 15) * 32;
        CP_ASYNC16(bsb + (uint32_t)((j * 64 + br) * BRH + bc * 8) * 2,
                   BvN + ((size_t)n * Dm + d0 + br) * RK + rb + bc * 8);
    };
    stageAB(0); CP_COMMIT;
    stageAB(1); CP_COMMIT;
    stageAB(2); CP_COMMIT;
    stageAB(3); CP_COMMIT;
    for (int s = 0; s < S; s += 2) {
        if (s + 2 < S) { asm volatile("cp.async.wait_group 2;"); }
        else           { asm volatile("cp.async.wait_group 0;"); }
        __syncthreads();
        if (s + 4 < S) {
            stageAB(s + 4); CP_COMMIT;
            stageAB(s + 5); CP_COMMIT;
        }
        #pragma unroll
        for (int sub = 0; sub < 2; sub++) {
            const int ss = s + sub;
            const uint32_t aB = asb + (uint32_t)((ss % NSTG) * (BM * BRH) * 2);
            const uint32_t bB = bsb + (uint32_t)((ss % NSTG) * (64 * BRH) * 2);
            #pragma unroll
            for (int seg = 0; seg < 32; seg += 16) {
                unsigned aa[2][4], bb[4][2];
                LDSM_X4(aa[0][0], aa[0][1], aa[0][2], aa[0][3], aB + aInv + seg * 2);
                LDSM_X4(aa[1][0], aa[1][1], aa[1][2], aa[1][3],
                        aB + aInv + (uint32_t)(16 * BRH * 2) + seg * 2);
                LDSM_X4(bb[0][0], bb[0][1], bb[1][0], bb[1][1], bB + bInv + seg * 2);
                LDSM_X4(bb[2][0], bb[2][1], bb[3][0], bb[3][1],
                        bB + bInv + (uint32_t)(16 * BRH * 2) + seg * 2);
                #pragma unroll
                for (int mf = 0; mf < 2; mf++)
                    #pragma unroll
                    for (int j = 0; j < 4; j++) mma_f16(accO[mf][j], aa[mf], bb[j]);
            }
        }
    }
    #pragma unroll
    for (int mf = 0; mf < 2; mf++)
        #pragma unroll
        for (int j = 0; j < 4; j++) {
            const int row = m0 + wm + mf * 16 + g;
            const int col = d0 + wn + j * 8 + tg * 2;
            *(float2*)(Out + (size_t)row * Dm + col)       = make_float2(accO[mf][j][0], accO[mf][j][1]);
            *(float2*)(Out + (size_t)(row + 8) * Dm + col) = make_float2(accO[mf][j][2], accO[mf][j][3]);
        }
}

// ---------------- launch ----------------------------------------------------
extern "C" void kernel_launch(void* const* d_in, const int* in_sizes, int n_in,
                              void* d_out, int out_size) {
    const float* x        = (const float*)d_in[0];
    const float* W_router = (const float*)d_in[1];
    const float* recipe_Q = (const float*)d_in[2];
    const float* recipe_K = (const float*)d_in[3];
    const float* recipe_V = (const float*)d_in[4];
    const float* recipe_O = (const float*)d_in[5];
    const float* basis_qk = (const float*)d_in[6];
    const float* basis_vo = (const float*)d_in[7];
    float* out = (float*)d_out;

    float *scores, *tQ, *tK, *tV, *tO, *Qp, *Kp, *Vp, *ctx;
    __half *xh, *bqkN, *bvoN, *Af;
    cudaGetSymbolAddress((void**)&scores, g_scores);
    cudaGetSymbolAddress((void**)&tQ, g_trQ);
    cudaGetSymbolAddress((void**)&tK, g_trK);
    cudaGetSymbolAddress((void**)&tV, g_trV);
    cudaGetSymbolAddress((void**)&tO, g_trO);
    cudaGetSymbolAddress((void**)&Qp, g_Q);
    cudaGetSymbolAddress((void**)&Kp, g_Km);
    cudaGetSymbolAddress((void**)&Vp, g_V);
    cudaGetSymbolAddress((void**)&ctx, g_ctx);
    cudaGetSymbolAddress((void**)&xh, g_xh);
    cudaGetSymbolAddress((void**)&bqkN, g_bqkN);
    cudaGetSymbolAddress((void**)&bvoN, g_bvoN);
    cudaGetSymbolAddress((void**)&Af, g_Afold);

    const int QK_SMEM = (BM * XRH + NSTG * 32 * BRT) * 2 + 2 * BM * WROW * 4;   // 96256
    const int V_SMEM  = (BM * XRH + NSTG * 32 * BRT) * 2 + BM * WROW * 4;       // 79360
    const int O_SMEM  = (NSTG * BM * BRH + NSTG * 64 * BRH) * 2;                // 92160
    cudaFuncSetAttribute(qk_mma, cudaFuncAttributeMaxDynamicSharedMemorySize, QK_SMEM);
    cudaFuncSetAttribute(v_mma,  cudaFuncAttributeMaxDynamicSharedMemorySize, V_SMEM);
    cudaFuncSetAttribute(o_mma,  cudaFuncAttributeMaxDynamicSharedMemorySize, O_SMEM);

    cvt_half_kernel<<<1024, 256>>>((const float4*)x, (uint2*)xh, NT * Dm / 4);
    cvt_half_kernel<<<2048, 256>>>((const float4*)basis_qk, (uint2*)bqkN, NB * Dm * RK / 4);
    cvt_half_kernel<<<2048, 256>>>((const float4*)basis_vo, (uint2*)bvoN, NB * Dm * RK / 4);
    router_gemm<<<dim3(NN / 64, NT / 64), 256>>>(x, W_router, scores);
    route_kernel<<<NT, 32>>>(scores, recipe_Q, recipe_K, recipe_V, recipe_O,
                             tQ, tK, tV, tO);
    qk_mma<<<dim3(RK / BN, NT / BM), 256, QK_SMEM>>>(xh, bqkN, tQ, tK, Qp, Kp);
    v_mma<<<dim3(RK / BN, NT / BM), 256, V_SMEM>>>(xh, bvoN, tV, Vp);
    attn_kernel<<<dim3(Bsz * NH, Ssz / 16), 512>>>(Qp, Kp, Vp, ctx);
    oa_fold<<<NT, 128>>>(ctx, tO, Af);
    o_mma<<<dim3(Dm / BN, NT / BM), 256, O_SMEM>>>(Af, bvoN, out);
}